// round 4
// baseline (speedup 1.0000x reference)
#include <cuda_runtime.h>
#include <math.h>
#include <stdint.h>

#define D      512
#define T      256
#define TOPK   8
#define NPAIR  2048
#define NEXP   16
#define MAXH   2560
#define NSCORE 4096

// ---------------- scratch ----------------------------------------------------
__device__ float g_h1[T * D];
__device__ float g_h2[T * 256];
__device__ float g_scores[T * NSCORE];
__device__ float g_preu[NPAIR * D];
__device__ float g_xin[NPAIR * D];
__device__ float g_hmid[NPAIR * MAXH];
__device__ float g_y[NPAIR * D];
__device__ float g_z[NPAIR * D];
__device__ float g_w[NPAIR];
__device__ int   g_prei[NPAIR];
__device__ int   g_posti[NPAIR];
__device__ int   g_cnt[48];
__device__ int   g_rows[48 * NPAIR];

// ---------------- helpers ----------------------------------------------------
__device__ __forceinline__ float actf(int a, float v) {
    switch (a) {
        case 0: return 0.5f * v * (1.0f + erff(v * 0.7071067811865476f));
        case 1: return fmaxf(v, 0.0f);
        case 2: return tanhf(v);
        default: return v / (1.0f + expf(-v));
    }
}

__device__ __forceinline__ unsigned f2tf32(float f) {
    unsigned r;
    asm("cvt.rna.tf32.f32 %0, %1;" : "=r"(r) : "f"(f));
    return r;
}

__device__ __forceinline__ float wsum(float v) {
#pragma unroll
    for (int o = 16; o; o >>= 1) v += __shfl_xor_sync(0xffffffffu, v, o);
    return v;
}
__device__ __forceinline__ float wmax(float v) {
#pragma unroll
    for (int o = 16; o; o >>= 1) v = fmaxf(v, __shfl_xor_sync(0xffffffffu, v, o));
    return v;
}

#define MMA_TF32(c, a0, a1, a2, a3, b0, b1)                                      \
    asm volatile("mma.sync.aligned.m16n8k8.row.col.f32.tf32.tf32.f32 "           \
                 "{%0,%1,%2,%3}, {%4,%5,%6,%7}, {%8,%9}, {%0,%1,%2,%3};"         \
                 : "+f"((c)[0]), "+f"((c)[1]), "+f"((c)[2]), "+f"((c)[3])        \
                 : "r"(a0), "r"(a1), "r"(a2), "r"(a3), "r"(b0), "r"(b1))

struct GArgs {
    const float* A; int lda;
    const float* B; long bStride; int ldb;
    const float* bias; int biasStride;
    float* C; int ldc;
    int M, N, K;
    const int* rows; const int* cnt;
    int gshift;
    int varN, varK;
    int act;  // 0 none, 1..4 fixed (act-1), 5 per-expert e&3
};

// ---------------- tf32 grouped GEMM (experts) --------------------------------
// BM=64, BN=64, 128 threads = 4 warps (2x2), warp tile 32x32.
// Double-buffered smem, tf32 pre-converted at store, LDG prefetch, 1 sync/iter.
__global__ __launch_bounds__(128) void tgemm_k(GArgs g) {
    const int e  = blockIdx.z;
    const int Me = g.cnt[e];
    if (Me == 0) return;
    const int he = 512 * (2 + (e >> 2));
    const int Ne = g.varN ? he : g.N;
    const int Ke = g.varK ? he : g.K;
    const int n0 = blockIdx.x * 64;
    if (n0 >= Ne) return;

    const float* B  = g.B + (long)e * g.bStride;
    const int*   rl = g.rows + e * NPAIR;

    __shared__ unsigned As[2][64][20];
    __shared__ unsigned Bs[2][16][72];

    const int tid = threadIdx.x, warp = tid >> 5, lane = tid & 31;
    const int grp = lane >> 2, t4 = lane & 3;
    const int wm = warp >> 1, wn = warp & 1;
    const int a_row = tid >> 1;          // 0..63
    const int aq = (tid & 1) * 2;        // float4 index base {0,2}

    const int aAct = (g.act == 5) ? (e & 3) : (g.act - 1);
    const int KT = Ke >> 4;

    for (int m0 = blockIdx.y * 64; m0 < Me; m0 += gridDim.y * 64) {
        const bool mv = (m0 + a_row) < Me;
        long arow = 0;
        if (mv) arow = (long)(rl[m0 + a_row] >> g.gshift);
        const float* Ap = g.A + arow * (long)g.lda;

        int crow[4];
#pragma unroll
        for (int mi = 0; mi < 2; mi++)
#pragma unroll
            for (int h = 0; h < 2; h++) {
                int m = m0 + wm * 32 + mi * 16 + grp + h * 8;
                crow[mi * 2 + h] = (m < Me) ? rl[m] : -1;
            }

        float acc[2][4][4];
#pragma unroll
        for (int mi = 0; mi < 2; mi++)
#pragma unroll
            for (int ni = 0; ni < 4; ni++)
#pragma unroll
                for (int c = 0; c < 4; c++) acc[mi][ni][c] = 0.0f;

        // register staging loads
        float4 av[2], bv[2];
        auto ldreg = [&](int k0) {
#pragma unroll
            for (int i = 0; i < 2; i++)
                av[i] = mv ? *(const float4*)(Ap + k0 + (aq + i) * 4)
                           : make_float4(0.f, 0.f, 0.f, 0.f);
#pragma unroll
            for (int i = 0; i < 2; i++) {
                int c = tid + i * 128;
                int r = c >> 4, col = (c & 15) * 4;
                bv[i] = *(const float4*)(B + (long)(k0 + r) * g.ldb + n0 + col);
            }
        };

        ldreg(0);
        int buf = 0;
        for (int kt = 0; kt < KT; kt++) {
            // convert + store to smem
#pragma unroll
            for (int i = 0; i < 2; i++) {
                uint4 u;
                u.x = f2tf32(av[i].x); u.y = f2tf32(av[i].y);
                u.z = f2tf32(av[i].z); u.w = f2tf32(av[i].w);
                *(uint4*)&As[buf][a_row][(aq + i) * 4] = u;
            }
#pragma unroll
            for (int i = 0; i < 2; i++) {
                int c = tid + i * 128;
                int r = c >> 4, col = (c & 15) * 4;
                uint4 u;
                u.x = f2tf32(bv[i].x); u.y = f2tf32(bv[i].y);
                u.z = f2tf32(bv[i].z); u.w = f2tf32(bv[i].w);
                *(uint4*)&Bs[buf][r][col] = u;
            }
            __syncthreads();

            if (kt + 1 < KT) ldreg((kt + 1) << 4);   // prefetch, hidden by compute

#pragma unroll
            for (int ks = 0; ks < 2; ks++) {
                const int kk = ks * 8;
                unsigned a[2][4], b[4][2];
#pragma unroll
                for (int mi = 0; mi < 2; mi++) {
                    int mr = wm * 32 + mi * 16 + grp;
                    a[mi][0] = As[buf][mr][kk + t4];
                    a[mi][1] = As[buf][mr + 8][kk + t4];
                    a[mi][2] = As[buf][mr][kk + t4 + 4];
                    a[mi][3] = As[buf][mr + 8][kk + t4 + 4];
                }
#pragma unroll
                for (int ni = 0; ni < 4; ni++) {
                    int nc = wn * 32 + ni * 8 + grp;
                    b[ni][0] = Bs[buf][kk + t4][nc];
                    b[ni][1] = Bs[buf][kk + t4 + 4][nc];
                }
#pragma unroll
                for (int mi = 0; mi < 2; mi++)
#pragma unroll
                    for (int ni = 0; ni < 4; ni++)
                        MMA_TF32(acc[mi][ni], a[mi][0], a[mi][1], a[mi][2], a[mi][3],
                                 b[ni][0], b[ni][1]);
            }
            buf ^= 1;
        }

        const float* bias = g.bias + (long)e * g.biasStride;
#pragma unroll
        for (int ni = 0; ni < 4; ni++) {
            int c = n0 + wn * 32 + ni * 8 + t4 * 2;
            float b0 = bias[c], b1 = bias[c + 1];
#pragma unroll
            for (int mi = 0; mi < 2; mi++)
#pragma unroll
                for (int h = 0; h < 2; h++) {
                    int cr = crow[mi * 2 + h];
                    if (cr >= 0) {
                        float v0 = acc[mi][ni][h * 2 + 0] + b0;
                        float v1 = acc[mi][ni][h * 2 + 1] + b1;
                        if (aAct >= 0) { v0 = actf(aAct, v0); v1 = actf(aAct, v1); }
                        *(float2*)(g.C + (long)cr * g.ldc + c) = make_float2(v0, v1);
                    }
                }
        }
        __syncthreads();   // protect smem across m0 tiles
    }
}

// ---------------- router GEMM: split-tf32 (hi/lo), prefetch overlap ----------
__global__ __launch_bounds__(256) void rgemm_k(GArgs g) {
    const int n0 = blockIdx.x * 64;
    const int m0 = blockIdx.y * 128;
    if (n0 >= g.N) return;

    __shared__ unsigned AsH[128][20], AsL[128][20];
    __shared__ unsigned BsH[16][72], BsL[16][72];

    const int tid = threadIdx.x, warp = tid >> 5, lane = tid & 31;
    const int grp = lane >> 2, t4 = lane & 3;
    const int wm = warp >> 1, wn = warp & 1;
    const int a_row = tid >> 1;
    const int aq = (tid & 1) * 2;
    const int bk = tid >> 4, cb = (tid & 15) * 4;

    const bool mv = (m0 + a_row) < g.M;
    const float* Ap = g.A + (long)(m0 + a_row) * g.lda;

    float acc[2][4][4];
#pragma unroll
    for (int mi = 0; mi < 2; mi++)
#pragma unroll
        for (int ni = 0; ni < 4; ni++)
#pragma unroll
            for (int c = 0; c < 4; c++) acc[mi][ni][c] = 0.0f;

    float4 av[2], bv;
    auto ldreg = [&](int k0) {
#pragma unroll
        for (int i = 0; i < 2; i++)
            av[i] = mv ? *(const float4*)(Ap + k0 + (aq + i) * 4)
                       : make_float4(0.f, 0.f, 0.f, 0.f);
        bv = *(const float4*)(g.B + (long)(k0 + bk) * g.ldb + n0 + cb);
    };

    const int KT = g.K >> 4;
    ldreg(0);
    for (int kt = 0; kt < KT; kt++) {
        __syncthreads();   // everyone done reading smem from prev iter
#pragma unroll
        for (int i = 0; i < 2; i++) {
            float vv[4] = {av[i].x, av[i].y, av[i].z, av[i].w};
            uint4 uh, ul;
            unsigned* ph = &uh.x; unsigned* pl = &ul.x;
#pragma unroll
            for (int c = 0; c < 4; c++) {
                unsigned hb = f2tf32(vv[c]);
                ph[c] = hb;
                pl[c] = f2tf32(vv[c] - __uint_as_float(hb));
            }
            *(uint4*)&AsH[a_row][(aq + i) * 4] = uh;
            *(uint4*)&AsL[a_row][(aq + i) * 4] = ul;
        }
        {
            float vv[4] = {bv.x, bv.y, bv.z, bv.w};
            uint4 uh, ul;
            unsigned* ph = &uh.x; unsigned* pl = &ul.x;
#pragma unroll
            for (int c = 0; c < 4; c++) {
                unsigned hb = f2tf32(vv[c]);
                ph[c] = hb;
                pl[c] = f2tf32(vv[c] - __uint_as_float(hb));
            }
            *(uint4*)&BsH[bk][cb] = uh;
            *(uint4*)&BsL[bk][cb] = ul;
        }
        __syncthreads();

        if (kt + 1 < KT) ldreg((kt + 1) << 4);   // prefetch next, hidden by compute

#pragma unroll
        for (int ks = 0; ks < 2; ks++) {
            const int kk = ks * 8;
            unsigned ah[2][4], al[2][4], bh[4][2], bl[4][2];
#pragma unroll
            for (int mi = 0; mi < 2; mi++) {
                int mr = wm * 32 + mi * 16 + grp;
                ah[mi][0] = AsH[mr][kk + t4];     al[mi][0] = AsL[mr][kk + t4];
                ah[mi][1] = AsH[mr + 8][kk + t4]; al[mi][1] = AsL[mr + 8][kk + t4];
                ah[mi][2] = AsH[mr][kk + t4 + 4]; al[mi][2] = AsL[mr][kk + t4 + 4];
                ah[mi][3] = AsH[mr + 8][kk + t4 + 4]; al[mi][3] = AsL[mr + 8][kk + t4 + 4];
            }
#pragma unroll
            for (int ni = 0; ni < 4; ni++) {
                int nc = wn * 32 + ni * 8 + grp;
                bh[ni][0] = BsH[kk + t4][nc];     bl[ni][0] = BsL[kk + t4][nc];
                bh[ni][1] = BsH[kk + t4 + 4][nc]; bl[ni][1] = BsL[kk + t4 + 4][nc];
            }
#pragma unroll
            for (int mi = 0; mi < 2; mi++)
#pragma unroll
                for (int ni = 0; ni < 4; ni++) {
                    MMA_TF32(acc[mi][ni], ah[mi][0], ah[mi][1], ah[mi][2], ah[mi][3],
                             bh[ni][0], bh[ni][1]);
                    MMA_TF32(acc[mi][ni], ah[mi][0], ah[mi][1], ah[mi][2], ah[mi][3],
                             bl[ni][0], bl[ni][1]);
                    MMA_TF32(acc[mi][ni], al[mi][0], al[mi][1], al[mi][2], al[mi][3],
                             bh[ni][0], bh[ni][1]);
                }
        }
    }

    const int aAct = g.act - 1;
#pragma unroll
    for (int ni = 0; ni < 4; ni++) {
        int c = n0 + wn * 32 + ni * 8 + t4 * 2;
        float b0 = g.bias[c], b1 = g.bias[c + 1];
#pragma unroll
        for (int mi = 0; mi < 2; mi++)
#pragma unroll
            for (int h = 0; h < 2; h++) {
                int m = m0 + wm * 32 + mi * 16 + grp + h * 8;
                if (m < g.M) {
                    float v0 = acc[mi][ni][h * 2 + 0] + b0;
                    float v1 = acc[mi][ni][h * 2 + 1] + b1;
                    if (aAct >= 0) { v0 = actf(aAct, v0); v1 = actf(aAct, v1); }
                    *(float2*)(g.C + (long)m * g.ldc + c) = make_float2(v0, v1);
                }
            }
    }
}

// ---------------- zero counters ----------------------------------------------
__global__ void zero_k(int* cnt) {
    if (threadIdx.x < 48) cnt[threadIdx.x] = 0;
}

// ---------------- softmax + top-k + routing ----------------------------------
__global__ __launch_bounds__(256) void route_k(const float* scores, const float* temp,
                                               float* w, int* prei, int* posti,
                                               int* cnt, int* rows) {
    const int t = blockIdx.x, tid = threadIdx.x;
    const int wid = tid >> 5, lane = tid & 31;
    __shared__ float sm[NSCORE];
    __shared__ float ws1[8], ws2[8];
    __shared__ float wv[8];
    __shared__ int   wi[8];

    const float invT = 1.0f / temp[0];
    for (int j = tid; j < NSCORE; j += 256) sm[j] = scores[t * NSCORE + j] * invT;
    __syncthreads();

    float mx = -3.4e38f;
    for (int j = tid; j < NSCORE; j += 256) mx = fmaxf(mx, sm[j]);
    mx = wmax(mx);
    if (lane == 0) ws1[wid] = mx;
    __syncthreads();
    float gmax = ws1[0];
#pragma unroll
    for (int i = 1; i < 8; i++) gmax = fmaxf(gmax, ws1[i]);

    float sum = 0.0f;
    for (int j = tid; j < NSCORE; j += 256) sum += expf(sm[j] - gmax);
    sum = wsum(sum);
    if (lane == 0) ws2[wid] = sum;
    __syncthreads();
    float gsum = 0.0f;
#pragma unroll
    for (int i = 0; i < 8; i++) gsum += ws2[i];

    for (int k = 0; k < TOPK; k++) {
        float bv = -3.4e38f; int bi = NSCORE;
        for (int j = tid; j < NSCORE; j += 256) {
            float v = sm[j];
            if (v > bv || (v == bv && j < bi)) { bv = v; bi = j; }
        }
#pragma unroll
        for (int o = 16; o; o >>= 1) {
            float ov = __shfl_xor_sync(0xffffffffu, bv, o);
            int oi = __shfl_xor_sync(0xffffffffu, bi, o);
            if (ov > bv || (ov == bv && oi < bi)) { bv = ov; bi = oi; }
        }
        if (lane == 0) { wv[wid] = bv; wi[wid] = bi; }
        __syncthreads();
        if (tid == 0) {
            float fv = wv[0]; int fi = wi[0];
#pragma unroll
            for (int i = 1; i < 8; i++) {
                if (wv[i] > fv || (wv[i] == fv && wi[i] < fi)) { fv = wv[i]; fi = wi[i]; }
            }
            float prob = expf(fv - gmax) / gsum;
            float ww = (prob >= 1e-6f) ? prob : 0.0f;
            int pair = t * TOPK + k;
            int pe = fi >> 8, rem = fi & 255, me = rem >> 4, oe = rem & 15;
            prei[pair] = pe; posti[pair] = oe; w[pair] = ww;
            int s0 = atomicAdd(&cnt[pe], 1);       rows[pe * NPAIR + s0] = pair;
            int s1 = atomicAdd(&cnt[16 + me], 1);  rows[(16 + me) * NPAIR + s1] = pair;
            int s2 = atomicAdd(&cnt[32 + oe], 1);  rows[(32 + oe) * NPAIR + s2] = pair;
            sm[fi] = -3.4e38f;
        }
        __syncthreads();
    }
}

// ---------------- pre-expert LN + act (warp per pair) ------------------------
__global__ __launch_bounds__(256) void prelnact_k(const float* U, const int* prei,
                                                  const float* g, const float* b, float* X) {
    const int warp = threadIdx.x >> 5, lane = threadIdx.x & 31;
    const int p = blockIdx.x * 8 + warp;
    const int e = prei[p];
    float u[16];
#pragma unroll
    for (int j = 0; j < 16; j++) u[j] = U[p * D + lane + 32 * j];

    float s = 0.0f;
#pragma unroll
    for (int j = 0; j < 16; j++) s += u[j];
    const float mean = wsum(s) * (1.0f / D);

    float v = 0.0f;
#pragma unroll
    for (int j = 0; j < 16; j++) { float d = u[j] - mean; v += d * d; }
    const float rstd = rsqrtf(wsum(v) * (1.0f / D) + 1e-5f);

    const int a = e & 3;
#pragma unroll
    for (int j = 0; j < 16; j++) {
        int idx = lane + 32 * j;
        float val = (u[j] - mean) * rstd * g[e * D + idx] + b[e * D + idx];
        X[p * D + idx] = actf(a, val);
    }
}

// ---------------- post LN + weighted reduce (warp per pair) ------------------
__global__ __launch_bounds__(256) void final_k(const float* Z, const int* posti, const float* w,
                                               const float* g, const float* b, float* out) {
    const int t = blockIdx.x, tid = threadIdx.x;
    const int warp = tid >> 5, lane = tid & 31;
    __shared__ float sacc[8][D];

    const int pair = t * TOPK + warp;
    const int e = posti[pair];
    const float ww = w[pair];
    float z[16];
#pragma unroll
    for (int j = 0; j < 16; j++) z[j] = Z[(long)pair * D + lane + 32 * j];

    if ((e & 1) == 0) {
        float s = 0.0f;
#pragma unroll
        for (int j = 0; j < 16; j++) s += z[j];
        const float mean = wsum(s) * (1.0f / D);
        float v = 0.0f;
#pragma unroll
        for (int j = 0; j < 16; j++) { float d = z[j] - mean; v += d * d; }
        const float rstd = rsqrtf(wsum(v) * (1.0f / D) + 1e-5f);
#pragma unroll
        for (int j = 0; j < 16; j++) {
            int idx = lane + 32 * j;
            z[j] = (z[j] - mean) * rstd * g[e * D + idx] + b[e * D + idx];
        }
    }
#pragma unroll
    for (int j = 0; j < 16; j++) sacc[warp][lane + 32 * j] = ww * z[j];
    __syncthreads();

    for (int i = tid; i < D; i += 256) {
        float s = 0.0f;
#pragma unroll
        for (int k = 0; k < 8; k++) s += sacc[k][i];
        out[t * D + i] = s;
    }
}

// ---------------- launch -----------------------------------------------------
extern "C" void kernel_launch(void* const* d_in, const int* in_sizes, int n_in,
                              void* d_out, int out_size) {
    const float* x       = (const float*)d_in[0];
    const float* r_w1    = (const float*)d_in[1];
    const float* r_b1    = (const float*)d_in[2];
    const float* r_w2    = (const float*)d_in[3];
    const float* r_b2    = (const float*)d_in[4];
    const float* r_w3    = (const float*)d_in[5];
    const float* r_b3    = (const float*)d_in[6];
    const float* temp    = (const float*)d_in[7];
    const float* pre_w   = (const float*)d_in[8];
    const float* pre_b   = (const float*)d_in[9];
    const float* pre_g   = (const float*)d_in[10];
    const float* pre_be  = (const float*)d_in[11];
    const float* mlp_w1  = (const float*)d_in[12];
    const float* mlp_b1  = (const float*)d_in[13];
    const float* mlp_w2  = (const float*)d_in[14];
    const float* mlp_b2  = (const float*)d_in[15];
    const float* post_w  = (const float*)d_in[16];
    const float* post_b  = (const float*)d_in[17];
    const float* post_g  = (const float*)d_in[18];
    const float* post_be = (const float*)d_in[19];
    float* out = (float*)d_out;

    float *h1, *h2, *sc, *preu, *xin, *hmid, *y, *z, *w;
    int *prei, *posti, *cnt, *rows;
    cudaGetSymbolAddress((void**)&h1, g_h1);
    cudaGetSymbolAddress((void**)&h2, g_h2);
    cudaGetSymbolAddress((void**)&sc, g_scores);
    cudaGetSymbolAddress((void**)&preu, g_preu);
    cudaGetSymbolAddress((void**)&xin, g_xin);
    cudaGetSymbolAddress((void**)&hmid, g_hmid);
    cudaGetSymbolAddress((void**)&y, g_y);
    cudaGetSymbolAddress((void**)&z, g_z);
    cudaGetSymbolAddress((void**)&w, g_w);
    cudaGetSymbolAddress((void**)&prei, g_prei);
    cudaGetSymbolAddress((void**)&posti, g_posti);
    cudaGetSymbolAddress((void**)&cnt, g_cnt);
    cudaGetSymbolAddress((void**)&rows, g_rows);

    zero_k<<<1, 64>>>(cnt);

    // router: split-tf32 tensor core (near-fp32 accuracy, protects top-k)
    {
        GArgs a = {x, D, r_w1, 0, 512, r_b1, 0, h1, 512,
                   T, 512, 512, nullptr, nullptr, 0, 0, 0, 1};
        rgemm_k<<<dim3(8, 2, 1), 256>>>(a);
    }
    {
        GArgs a = {h1, 512, r_w2, 0, 256, r_b2, 0, h2, 256,
                   T, 256, 512, nullptr, nullptr, 0, 0, 0, 1};
        rgemm_k<<<dim3(4, 2, 1), 256>>>(a);
    }
    {
        GArgs a = {h2, 256, r_w3, 0, NSCORE, r_b3, 0, sc, NSCORE,
                   T, NSCORE, 256, nullptr, nullptr, 0, 0, 0, 0};
        rgemm_k<<<dim3(64, 2, 1), 256>>>(a);
    }

    route_k<<<T, 256>>>(sc, temp, w, prei, posti, cnt, rows);

    // experts: tf32 tensor cores, grouped + gathered
    {
        GArgs a = {x, D, pre_w, (long)D * D, D, pre_b, D, preu, D,
                   NPAIR, D, D, rows, cnt, 3, 0, 0, 0};
        tgemm_k<<<dim3(8, 2, NEXP), 128>>>(a);
    }
    prelnact_k<<<NPAIR / 8, 256>>>(preu, prei, pre_g, pre_be, xin);

    {
        GArgs a = {xin, D, mlp_w1, (long)D * MAXH, MAXH, mlp_b1, MAXH, hmid, MAXH,
                   NPAIR, MAXH, D, rows + 16 * NPAIR, cnt + 16, 0, 1, 0, 5};
        tgemm_k<<<dim3(40, 2, NEXP), 128>>>(a);
    }
    {
        GArgs a = {hmid, MAXH, mlp_w2, (long)MAXH * D, D, mlp_b2, D, y, D,
                   NPAIR, D, MAXH, rows + 16 * NPAIR, cnt + 16, 0, 0, 1, 0};
        tgemm_k<<<dim3(8, 2, NEXP), 128>>>(a);
    }
    {
        GArgs a = {y, D, post_w, (long)D * D, D, post_b, D, z, D,
                   NPAIR, D, D, rows + 32 * NPAIR, cnt + 32, 0, 0, 0, 0};
        tgemm_k<<<dim3(8, 2, NEXP), 128>>>(a);
    }

    final_k<<<T, 256>>>(z, posti, w, post_g, post_be, out);
}

// round 5
// speedup vs baseline: 1.1694x; 1.1694x over previous
#include <cuda_runtime.h>
#include <math.h>
#include <stdint.h>

#define D      512
#define T      256
#define TOPK   8
#define NPAIR  2048
#define NEXP   16
#define MAXH   2560
#define NSCORE 4096

// ---------------- scratch ----------------------------------------------------
__device__ float g_h1[T * D];
__device__ float g_h2[T * 256];
__device__ float g_scores[T * NSCORE];
__device__ float g_preu[NPAIR * D];
__device__ float g_xin[NPAIR * D];
__device__ float g_hmid[NPAIR * MAXH];
__device__ float g_y[NPAIR * D];
__device__ float g_z[NPAIR * D];
__device__ float g_w[NPAIR];
__device__ int   g_prei[NPAIR];
__device__ int   g_posti[NPAIR];
__device__ int   g_cnt[48];
__device__ int   g_rows[48 * NPAIR];

// ---------------- helpers ----------------------------------------------------
__device__ __forceinline__ float actf(int a, float v) {
    switch (a) {
        case 0: return 0.5f * v * (1.0f + erff(v * 0.7071067811865476f));
        case 1: return fmaxf(v, 0.0f);
        case 2: return tanhf(v);
        default: return v / (1.0f + expf(-v));
    }
}

__device__ __forceinline__ unsigned f2tf32(float f) {
    unsigned r;
    asm("cvt.rna.tf32.f32 %0, %1;" : "=r"(r) : "f"(f));
    return r;
}

__device__ __forceinline__ float wsum(float v) {
#pragma unroll
    for (int o = 16; o; o >>= 1) v += __shfl_xor_sync(0xffffffffu, v, o);
    return v;
}
__device__ __forceinline__ float wmax(float v) {
#pragma unroll
    for (int o = 16; o; o >>= 1) v = fmaxf(v, __shfl_xor_sync(0xffffffffu, v, o));
    return v;
}

#define MMA_TF32(c, a0, a1, a2, a3, b0, b1)                                      \
    asm volatile("mma.sync.aligned.m16n8k8.row.col.f32.tf32.tf32.f32 "           \
                 "{%0,%1,%2,%3}, {%4,%5,%6,%7}, {%8,%9}, {%0,%1,%2,%3};"         \
                 : "+f"((c)[0]), "+f"((c)[1]), "+f"((c)[2]), "+f"((c)[3])        \
                 : "r"(a0), "r"(a1), "r"(a2), "r"(a3), "r"(b0), "r"(b1))

struct GArgs {
    const float* A; int lda;
    const float* B; long bStride; int ldb;
    const float* bias; int biasStride;
    float* C; int ldc;
    int M, N, K;
    const int* rows; const int* cnt;
    int gshift;
    int varN, varK;
    int act;  // 0 none, 1..4 fixed (act-1), 5 per-expert e&3
};

// ---------------- tf32 grouped GEMM (experts) --------------------------------
// BM=64, BN in {32,64}; 128 threads = 4 warps (2x2); warp tile 32 x (BN/2).
// Simple 2-sync structure (R1-proven), tf32 converted once at smem store,
// conflict-free smem layouts. Parallelism comes from many blocks.
template<int BN>
__global__ __launch_bounds__(128) void tgemm_k(GArgs g) {
    constexpr int NI = BN / 16;          // n8 tiles per warp (2 or 4)
    constexpr int BNP = BN + 8;          // B row stride (words), keeps 16B align

    const int e  = blockIdx.z;
    const int Me = g.cnt[e];
    if (Me == 0) return;
    const int he = 512 * (2 + (e >> 2));
    const int Ne = g.varN ? he : g.N;
    const int Ke = g.varK ? he : g.K;
    const int n0 = blockIdx.x * BN;
    if (n0 >= Ne) return;

    const float* B  = g.B + (long)e * g.bStride;
    const int*   rl = g.rows + e * NPAIR;

    __shared__ unsigned As[64][20];      // [m][k], 80B rows: uint4-aligned
    __shared__ unsigned Bs[16][BNP];     // [k][n]

    const int tid = threadIdx.x, warp = tid >> 5, lane = tid & 31;
    const int grp = lane >> 2, t4 = lane & 3;
    const int wm = warp >> 1, wn = warp & 1;
    const int a_row = tid >> 1;          // 0..63
    const int aq = (tid & 1) * 2;        // float4 slot base {0,2}

    // B load mapping: 16*BN/4 float4s over 128 threads
    constexpr int BL = (16 * BN) / (4 * 128);   // 1 or 2 per thread
    constexpr int COLS4 = BN / 4;

    const int aAct = (g.act == 5) ? (e & 3) : (g.act - 1);

    for (int m0 = blockIdx.y * 64; m0 < Me; m0 += gridDim.y * 64) {
        const bool mv = (m0 + a_row) < Me;
        long arow = 0;
        if (mv) arow = (long)(rl[m0 + a_row] >> g.gshift);
        const float* Ap = g.A + arow * (long)g.lda;

        int crow[4];
#pragma unroll
        for (int mi = 0; mi < 2; mi++)
#pragma unroll
            for (int h = 0; h < 2; h++) {
                int m = m0 + wm * 32 + mi * 16 + grp + h * 8;
                crow[mi * 2 + h] = (m < Me) ? rl[m] : -1;
            }

        float acc[2][NI][4];
#pragma unroll
        for (int mi = 0; mi < 2; mi++)
#pragma unroll
            for (int ni = 0; ni < NI; ni++)
#pragma unroll
                for (int c = 0; c < 4; c++) acc[mi][ni][c] = 0.0f;

        for (int k0 = 0; k0 < Ke; k0 += 16) {
            // stage loads in registers
            float4 av[2];
#pragma unroll
            for (int i = 0; i < 2; i++)
                av[i] = mv ? *(const float4*)(Ap + k0 + (aq + i) * 4)
                           : make_float4(0.f, 0.f, 0.f, 0.f);
            float4 bv[BL];
#pragma unroll
            for (int i = 0; i < BL; i++) {
                int idx = tid + i * 128;
                int r = idx / COLS4, col = (idx % COLS4) * 4;
                bv[i] = *(const float4*)(B + (long)(k0 + r) * g.ldb + n0 + col);
            }
            __syncthreads();   // previous tile fully consumed
#pragma unroll
            for (int i = 0; i < 2; i++) {
                uint4 u;
                u.x = f2tf32(av[i].x); u.y = f2tf32(av[i].y);
                u.z = f2tf32(av[i].z); u.w = f2tf32(av[i].w);
                *(uint4*)&As[a_row][(aq + i) * 4] = u;
            }
#pragma unroll
            for (int i = 0; i < BL; i++) {
                int idx = tid + i * 128;
                int r = idx / COLS4, col = (idx % COLS4) * 4;
                uint4 u;
                u.x = f2tf32(bv[i].x); u.y = f2tf32(bv[i].y);
                u.z = f2tf32(bv[i].z); u.w = f2tf32(bv[i].w);
                *(uint4*)&Bs[r][col] = u;
            }
            __syncthreads();

#pragma unroll
            for (int ks = 0; ks < 2; ks++) {
                const int kk = ks * 8;
                unsigned a[2][4], b[NI][2];
#pragma unroll
                for (int mi = 0; mi < 2; mi++) {
                    int mr = wm * 32 + mi * 16 + grp;
                    a[mi][0] = As[mr][kk + t4];
                    a[mi][1] = As[mr + 8][kk + t4];
                    a[mi][2] = As[mr][kk + t4 + 4];
                    a[mi][3] = As[mr + 8][kk + t4 + 4];
                }
#pragma unroll
                for (int ni = 0; ni < NI; ni++) {
                    int nc = wn * (8 * NI) + ni * 8 + grp;
                    b[ni][0] = Bs[kk + t4][nc];
                    b[ni][1] = Bs[kk + t4 + 4][nc];
                }
#pragma unroll
                for (int mi = 0; mi < 2; mi++)
#pragma unroll
                    for (int ni = 0; ni < NI; ni++)
                        MMA_TF32(acc[mi][ni], a[mi][0], a[mi][1], a[mi][2], a[mi][3],
                                 b[ni][0], b[ni][1]);
            }
        }

        const float* bias = g.bias + (long)e * g.biasStride;
#pragma unroll
        for (int ni = 0; ni < NI; ni++) {
            int c = n0 + wn * (8 * NI) + ni * 8 + t4 * 2;
            float b0 = bias[c], b1 = bias[c + 1];
#pragma unroll
            for (int mi = 0; mi < 2; mi++)
#pragma unroll
                for (int h = 0; h < 2; h++) {
                    int cr = crow[mi * 2 + h];
                    if (cr >= 0) {
                        float v0 = acc[mi][ni][h * 2 + 0] + b0;
                        float v1 = acc[mi][ni][h * 2 + 1] + b1;
                        if (aAct >= 0) { v0 = actf(aAct, v0); v1 = actf(aAct, v1); }
                        *(float2*)(g.C + (long)cr * g.ldc + c) = make_float2(v0, v1);
                    }
                }
        }
        __syncthreads();  // smem reuse across m0 iterations
    }
}

// ---------------- router GEMM: split-tf32 (hi/lo) ----------------------------
__global__ __launch_bounds__(256) void rgemm_k(GArgs g) {
    const int n0 = blockIdx.x * 64;
    const int m0 = blockIdx.y * 128;
    if (n0 >= g.N) return;

    __shared__ unsigned AsH[128][20], AsL[128][20];
    __shared__ unsigned BsH[16][72], BsL[16][72];

    const int tid = threadIdx.x, warp = tid >> 5, lane = tid & 31;
    const int grp = lane >> 2, t4 = lane & 3;
    const int wm = warp >> 1, wn = warp & 1;
    const int a_row = tid >> 1;
    const int aq = (tid & 1) * 2;
    const int bk = tid >> 4, cb = (tid & 15) * 4;

    const bool mv = (m0 + a_row) < g.M;
    const float* Ap = g.A + (long)(m0 + a_row) * g.lda;

    float acc[2][4][4];
#pragma unroll
    for (int mi = 0; mi < 2; mi++)
#pragma unroll
        for (int ni = 0; ni < 4; ni++)
#pragma unroll
            for (int c = 0; c < 4; c++) acc[mi][ni][c] = 0.0f;

    float4 av[2], bv;
    auto ldreg = [&](int k0) {
#pragma unroll
        for (int i = 0; i < 2; i++)
            av[i] = mv ? *(const float4*)(Ap + k0 + (aq + i) * 4)
                       : make_float4(0.f, 0.f, 0.f, 0.f);
        bv = *(const float4*)(g.B + (long)(k0 + bk) * g.ldb + n0 + cb);
    };

    const int KT = g.K >> 4;
    ldreg(0);
    for (int kt = 0; kt < KT; kt++) {
        __syncthreads();
#pragma unroll
        for (int i = 0; i < 2; i++) {
            float vv[4] = {av[i].x, av[i].y, av[i].z, av[i].w};
            uint4 uh, ul;
            unsigned* ph = &uh.x; unsigned* pl = &ul.x;
#pragma unroll
            for (int c = 0; c < 4; c++) {
                unsigned hb = f2tf32(vv[c]);
                ph[c] = hb;
                pl[c] = f2tf32(vv[c] - __uint_as_float(hb));
            }
            *(uint4*)&AsH[a_row][(aq + i) * 4] = uh;
            *(uint4*)&AsL[a_row][(aq + i) * 4] = ul;
        }
        {
            float vv[4] = {bv.x, bv.y, bv.z, bv.w};
            uint4 uh, ul;
            unsigned* ph = &uh.x; unsigned* pl = &ul.x;
#pragma unroll
            for (int c = 0; c < 4; c++) {
                unsigned hb = f2tf32(vv[c]);
                ph[c] = hb;
                pl[c] = f2tf32(vv[c] - __uint_as_float(hb));
            }
            *(uint4*)&BsH[bk][cb] = uh;
            *(uint4*)&BsL[bk][cb] = ul;
        }
        __syncthreads();

        if (kt + 1 < KT) ldreg((kt + 1) << 4);

#pragma unroll
        for (int ks = 0; ks < 2; ks++) {
            const int kk = ks * 8;
            unsigned ah[2][4], al[2][4], bh[4][2], bl[4][2];
#pragma unroll
            for (int mi = 0; mi < 2; mi++) {
                int mr = wm * 32 + mi * 16 + grp;
                ah[mi][0] = AsH[mr][kk + t4];     al[mi][0] = AsL[mr][kk + t4];
                ah[mi][1] = AsH[mr + 8][kk + t4]; al[mi][1] = AsL[mr + 8][kk + t4];
                ah[mi][2] = AsH[mr][kk + t4 + 4]; al[mi][2] = AsL[mr][kk + t4 + 4];
                ah[mi][3] = AsH[mr + 8][kk + t4 + 4]; al[mi][3] = AsL[mr + 8][kk + t4 + 4];
            }
#pragma unroll
            for (int ni = 0; ni < 4; ni++) {
                int nc = wn * 32 + ni * 8 + grp;
                bh[ni][0] = BsH[kk + t4][nc];     bl[ni][0] = BsL[kk + t4][nc];
                bh[ni][1] = BsH[kk + t4 + 4][nc]; bl[ni][1] = BsL[kk + t4 + 4][nc];
            }
#pragma unroll
            for (int mi = 0; mi < 2; mi++)
#pragma unroll
                for (int ni = 0; ni < 4; ni++) {
                    MMA_TF32(acc[mi][ni], ah[mi][0], ah[mi][1], ah[mi][2], ah[mi][3],
                             bh[ni][0], bh[ni][1]);
                    MMA_TF32(acc[mi][ni], ah[mi][0], ah[mi][1], ah[mi][2], ah[mi][3],
                             bl[ni][0], bl[ni][1]);
                    MMA_TF32(acc[mi][ni], al[mi][0], al[mi][1], al[mi][2], al[mi][3],
                             bh[ni][0], bh[ni][1]);
                }
        }
    }

    const int aAct = g.act - 1;
#pragma unroll
    for (int ni = 0; ni < 4; ni++) {
        int c = n0 + wn * 32 + ni * 8 + t4 * 2;
        float b0 = g.bias[c], b1 = g.bias[c + 1];
#pragma unroll
        for (int mi = 0; mi < 2; mi++)
#pragma unroll
            for (int h = 0; h < 2; h++) {
                int m = m0 + wm * 32 + mi * 16 + grp + h * 8;
                if (m < g.M) {
                    float v0 = acc[mi][ni][h * 2 + 0] + b0;
                    float v1 = acc[mi][ni][h * 2 + 1] + b1;
                    if (aAct >= 0) { v0 = actf(aAct, v0); v1 = actf(aAct, v1); }
                    *(float2*)(g.C + (long)m * g.ldc + c) = make_float2(v0, v1);
                }
            }
    }
}

// ---------------- zero counters ----------------------------------------------
__global__ void zero_k(int* cnt) {
    if (threadIdx.x < 48) cnt[threadIdx.x] = 0;
}

// ---------------- softmax + top-k + routing ----------------------------------
__global__ __launch_bounds__(256) void route_k(const float* scores, const float* temp,
                                               float* w, int* prei, int* posti,
                                               int* cnt, int* rows) {
    const int t = blockIdx.x, tid = threadIdx.x;
    const int wid = tid >> 5, lane = tid & 31;
    __shared__ float sm[NSCORE];
    __shared__ float ws1[8], ws2[8];
    __shared__ float wv[8];
    __shared__ int   wi[8];

    const float invT = 1.0f / temp[0];
    for (int j = tid; j < NSCORE; j += 256) sm[j] = scores[t * NSCORE + j] * invT;
    __syncthreads();

    float mx = -3.4e38f;
    for (int j = tid; j < NSCORE; j += 256) mx = fmaxf(mx, sm[j]);
    mx = wmax(mx);
    if (lane == 0) ws1[wid] = mx;
    __syncthreads();
    float gmax = ws1[0];
#pragma unroll
    for (int i = 1; i < 8; i++) gmax = fmaxf(gmax, ws1[i]);

    float sum = 0.0f;
    for (int j = tid; j < NSCORE; j += 256) sum += expf(sm[j] - gmax);
    sum = wsum(sum);
    if (lane == 0) ws2[wid] = sum;
    __syncthreads();
    float gsum = 0.0f;
#pragma unroll
    for (int i = 0; i < 8; i++) gsum += ws2[i];

    for (int k = 0; k < TOPK; k++) {
        float bv = -3.4e38f; int bi = NSCORE;
        for (int j = tid; j < NSCORE; j += 256) {
            float v = sm[j];
            if (v > bv || (v == bv && j < bi)) { bv = v; bi = j; }
        }
#pragma unroll
        for (int o = 16; o; o >>= 1) {
            float ov = __shfl_xor_sync(0xffffffffu, bv, o);
            int oi = __shfl_xor_sync(0xffffffffu, bi, o);
            if (ov > bv || (ov == bv && oi < bi)) { bv = ov; bi = oi; }
        }
        if (lane == 0) { wv[wid] = bv; wi[wid] = bi; }
        __syncthreads();
        if (tid == 0) {
            float fv = wv[0]; int fi = wi[0];
#pragma unroll
            for (int i = 1; i < 8; i++) {
                if (wv[i] > fv || (wv[i] == fv && wi[i] < fi)) { fv = wv[i]; fi = wi[i]; }
            }
            float prob = expf(fv - gmax) / gsum;
            float ww = (prob >= 1e-6f) ? prob : 0.0f;
            int pair = t * TOPK + k;
            int pe = fi >> 8, rem = fi & 255, me = rem >> 4, oe = rem & 15;
            prei[pair] = pe; posti[pair] = oe; w[pair] = ww;
            int s0 = atomicAdd(&cnt[pe], 1);       rows[pe * NPAIR + s0] = pair;
            int s1 = atomicAdd(&cnt[16 + me], 1);  rows[(16 + me) * NPAIR + s1] = pair;
            int s2 = atomicAdd(&cnt[32 + oe], 1);  rows[(32 + oe) * NPAIR + s2] = pair;
            sm[fi] = -3.4e38f;
        }
        __syncthreads();
    }
}

// ---------------- pre-expert LN + act (warp per pair) ------------------------
__global__ __launch_bounds__(256) void prelnact_k(const float* U, const int* prei,
                                                  const float* g, const float* b, float* X) {
    const int warp = threadIdx.x >> 5, lane = threadIdx.x & 31;
    const int p = blockIdx.x * 8 + warp;
    const int e = prei[p];
    float u[16];
#pragma unroll
    for (int j = 0; j < 16; j++) u[j] = U[p * D + lane + 32 * j];

    float s = 0.0f;
#pragma unroll
    for (int j = 0; j < 16; j++) s += u[j];
    const float mean = wsum(s) * (1.0f / D);

    float v = 0.0f;
#pragma unroll
    for (int j = 0; j < 16; j++) { float d = u[j] - mean; v += d * d; }
    const float rstd = rsqrtf(wsum(v) * (1.0f / D) + 1e-5f);

    const int a = e & 3;
#pragma unroll
    for (int j = 0; j < 16; j++) {
        int idx = lane + 32 * j;
        float val = (u[j] - mean) * rstd * g[e * D + idx] + b[e * D + idx];
        X[p * D + idx] = actf(a, val);
    }
}

// ---------------- post LN + weighted reduce (warp per pair) ------------------
__global__ __launch_bounds__(256) void final_k(const float* Z, const int* posti, const float* w,
                                               const float* g, const float* b, float* out) {
    const int t = blockIdx.x, tid = threadIdx.x;
    const int warp = tid >> 5, lane = tid & 31;
    __shared__ float sacc[8][D];

    const int pair = t * TOPK + warp;
    const int e = posti[pair];
    const float ww = w[pair];
    float z[16];
#pragma unroll
    for (int j = 0; j < 16; j++) z[j] = Z[(long)pair * D + lane + 32 * j];

    if ((e & 1) == 0) {
        float s = 0.0f;
#pragma unroll
        for (int j = 0; j < 16; j++) s += z[j];
        const float mean = wsum(s) * (1.0f / D);
        float v = 0.0f;
#pragma unroll
        for (int j = 0; j < 16; j++) { float d = z[j] - mean; v += d * d; }
        const float rstd = rsqrtf(wsum(v) * (1.0f / D) + 1e-5f);
#pragma unroll
        for (int j = 0; j < 16; j++) {
            int idx = lane + 32 * j;
            z[j] = (z[j] - mean) * rstd * g[e * D + idx] + b[e * D + idx];
        }
    }
#pragma unroll
    for (int j = 0; j < 16; j++) sacc[warp][lane + 32 * j] = ww * z[j];
    __syncthreads();

    for (int i = tid; i < D; i += 256) {
        float s = 0.0f;
#pragma unroll
        for (int k = 0; k < 8; k++) s += sacc[k][i];
        out[t * D + i] = s;
    }
}

// ---------------- launch -----------------------------------------------------
extern "C" void kernel_launch(void* const* d_in, const int* in_sizes, int n_in,
                              void* d_out, int out_size) {
    const float* x       = (const float*)d_in[0];
    const float* r_w1    = (const float*)d_in[1];
    const float* r_b1    = (const float*)d_in[2];
    const float* r_w2    = (const float*)d_in[3];
    const float* r_b2    = (const float*)d_in[4];
    const float* r_w3    = (const float*)d_in[5];
    const float* r_b3    = (const float*)d_in[6];
    const float* temp    = (const float*)d_in[7];
    const float* pre_w   = (const float*)d_in[8];
    const float* pre_b   = (const float*)d_in[9];
    const float* pre_g   = (const float*)d_in[10];
    const float* pre_be  = (const float*)d_in[11];
    const float* mlp_w1  = (const float*)d_in[12];
    const float* mlp_b1  = (const float*)d_in[13];
    const float* mlp_w2  = (const float*)d_in[14];
    const float* mlp_b2  = (const float*)d_in[15];
    const float* post_w  = (const float*)d_in[16];
    const float* post_b  = (const float*)d_in[17];
    const float* post_g  = (const float*)d_in[18];
    const float* post_be = (const float*)d_in[19];
    float* out = (float*)d_out;

    float *h1, *h2, *sc, *preu, *xin, *hmid, *y, *z, *w;
    int *prei, *posti, *cnt, *rows;
    cudaGetSymbolAddress((void**)&h1, g_h1);
    cudaGetSymbolAddress((void**)&h2, g_h2);
    cudaGetSymbolAddress((void**)&sc, g_scores);
    cudaGetSymbolAddress((void**)&preu, g_preu);
    cudaGetSymbolAddress((void**)&xin, g_xin);
    cudaGetSymbolAddress((void**)&hmid, g_hmid);
    cudaGetSymbolAddress((void**)&y, g_y);
    cudaGetSymbolAddress((void**)&z, g_z);
    cudaGetSymbolAddress((void**)&w, g_w);
    cudaGetSymbolAddress((void**)&prei, g_prei);
    cudaGetSymbolAddress((void**)&posti, g_posti);
    cudaGetSymbolAddress((void**)&cnt, g_cnt);
    cudaGetSymbolAddress((void**)&rows, g_rows);

    zero_k<<<1, 64>>>(cnt);

    // router: split-tf32 tensor core (near-fp32 accuracy, protects top-k)
    {
        GArgs a = {x, D, r_w1, 0, 512, r_b1, 0, h1, 512,
                   T, 512, 512, nullptr, nullptr, 0, 0, 0, 1};
        rgemm_k<<<dim3(8, 2, 1), 256>>>(a);
    }
    {
        GArgs a = {h1, 512, r_w2, 0, 256, r_b2, 0, h2, 256,
                   T, 256, 512, nullptr, nullptr, 0, 0, 0, 1};
        rgemm_k<<<dim3(4, 2, 1), 256>>>(a);
    }
    {
        GArgs a = {h2, 256, r_w3, 0, NSCORE, r_b3, 0, sc, NSCORE,
                   T, NSCORE, 256, nullptr, nullptr, 0, 0, 0, 0};
        rgemm_k<<<dim3(64, 2, 1), 256>>>(a);
    }

    route_k<<<T, 256>>>(sc, temp, w, prei, posti, cnt, rows);

    // experts: tf32 tensor cores, grouped + gathered, many small blocks
    {
        GArgs a = {x, D, pre_w, (long)D * D, D, pre_b, D, preu, D,
                   NPAIR, D, D, rows, cnt, 3, 0, 0, 0};
        tgemm_k<32><<<dim3(16, 4, NEXP), 128>>>(a);
    }
    prelnact_k<<<NPAIR / 8, 256>>>(preu, prei, pre_g, pre_be, xin);

    {
        GArgs a = {xin, D, mlp_w1, (long)D * MAXH, MAXH, mlp_b1, MAXH, hmid, MAXH,
                   NPAIR, MAXH, D, rows + 16 * NPAIR, cnt + 16, 0, 1, 0, 5};
        tgemm_k<64><<<dim3(40, 3, NEXP), 128>>>(a);
    }
    {
        GArgs a = {hmid, MAXH, mlp_w2, (long)MAXH * D, D, mlp_b2, D, y, D,
                   NPAIR, D, MAXH, rows + 16 * NPAIR, cnt + 16, 0, 0, 1, 0};
        tgemm_k<32><<<dim3(16, 4, NEXP), 128>>>(a);
    }
    {
        GArgs a = {y, D, post_w, (long)D * D, D, post_b, D, z, D,
                   NPAIR, D, D, rows + 32 * NPAIR, cnt + 32, 0, 0, 0, 0};
        tgemm_k<32><<<dim3(16, 4, NEXP), 128>>>(a);
    }

    final_k<<<T, 256>>>(z, posti, w, post_g, post_be, out);
}

// round 6
// speedup vs baseline: 1.2768x; 1.0918x over previous
#include <cuda_runtime.h>
#include <math.h>
#include <stdint.h>

#define D      512
#define T      256
#define TOPK   8
#define NPAIR  2048
#define NEXP   16
#define MAXH   2560
#define NSCORE 4096

// ---------------- scratch ----------------------------------------------------
__device__ float g_h1[T * D];
__device__ float g_h2[T * 256];
__device__ float g_scores[T * NSCORE];
__device__ float g_preu[NPAIR * D];
__device__ float g_xin[NPAIR * D];
__device__ float g_hmid[NPAIR * MAXH];
__device__ float g_y[NPAIR * D];
__device__ float g_z[NPAIR * D];
__device__ float g_w[NPAIR];
__device__ int   g_prei[NPAIR];
__device__ int   g_posti[NPAIR];
__device__ int   g_cnt[48];
__device__ int   g_rows[48 * NPAIR];

// ---------------- helpers ----------------------------------------------------
__device__ __forceinline__ float actf(int a, float v) {
    switch (a) {
        case 0: return 0.5f * v * (1.0f + erff(v * 0.7071067811865476f));
        case 1: return fmaxf(v, 0.0f);
        case 2: return tanhf(v);
        default: return v / (1.0f + expf(-v));
    }
}

__device__ __forceinline__ unsigned f2tf32(float f) {
    unsigned r;
    asm("cvt.rna.tf32.f32 %0, %1;" : "=r"(r) : "f"(f));
    return r;
}

__device__ __forceinline__ float wsum(float v) {
#pragma unroll
    for (int o = 16; o; o >>= 1) v += __shfl_xor_sync(0xffffffffu, v, o);
    return v;
}
__device__ __forceinline__ float wmax(float v) {
#pragma unroll
    for (int o = 16; o; o >>= 1) v = fmaxf(v, __shfl_xor_sync(0xffffffffu, v, o));
    return v;
}

#define MMA_TF32(c, a0, a1, a2, a3, b0, b1)                                      \
    asm volatile("mma.sync.aligned.m16n8k8.row.col.f32.tf32.tf32.f32 "           \
                 "{%0,%1,%2,%3}, {%4,%5,%6,%7}, {%8,%9}, {%0,%1,%2,%3};"         \
                 : "+f"((c)[0]), "+f"((c)[1]), "+f"((c)[2]), "+f"((c)[3])        \
                 : "r"(a0), "r"(a1), "r"(a2), "r"(a3), "r"(b0), "r"(b1))

struct GArgs {
    const float* A; int lda;
    const float* B; long bStride; int ldb;
    const float* bias; int biasStride;
    float* C; int ldc;
    int M, N, K;
    const int* rows; const int* cnt;
    int gshift;
    int varN, varK;
    int act;  // 0 none, 1..4 fixed (act-1), 5 per-expert e&3
};

// ---------------- tf32 grouped GEMM (experts) --------------------------------
// BM in {32,64}, BN in {32,64}; 128 threads = 4 warps (2x2).
// Warp tile (BM/2) x (BN/2). Small tiles -> many blocks -> latency hiding.
template<int BM, int BN>
__global__ __launch_bounds__(128) void tgemm_k(GArgs g) {
    constexpr int MI = BM / 32;          // m16 tiles per warp (1 or 2)
    constexpr int NI = BN / 16;          // n8 tiles per warp (2 or 4)
    constexpr int BNP = BN + 8;
    constexpr int AL = BM / 32;          // A float4 loads per thread
    constexpr int BL = BN / 32;          // B float4 loads per thread
    constexpr int COLS4 = BN / 4;

    const int e  = blockIdx.z;
    const int Me = g.cnt[e];
    if (Me == 0) return;
    const int he = 512 * (2 + (e >> 2));
    const int Ne = g.varN ? he : g.N;
    const int Ke = g.varK ? he : g.K;
    const int n0 = blockIdx.x * BN;
    if (n0 >= Ne) return;

    const float* B  = g.B + (long)e * g.bStride;
    const int*   rl = g.rows + e * NPAIR;

    __shared__ unsigned As[BM][20];
    __shared__ unsigned Bs[16][BNP];

    const int tid = threadIdx.x, warp = tid >> 5, lane = tid & 31;
    const int grp = lane >> 2, t4 = lane & 3;
    const int wm = warp >> 1, wn = warp & 1;

    // A load map: BM*4 float4s over 128 threads
    const int a_row = (BM == 64) ? (tid >> 1) : (tid >> 2);
    const int aq    = (BM == 64) ? ((tid & 1) * 2) : (tid & 3);

    const int aAct = (g.act == 5) ? (e & 3) : (g.act - 1);

    for (int m0 = blockIdx.y * BM; m0 < Me; m0 += gridDim.y * BM) {
        const bool mv = (m0 + a_row) < Me;
        long arow = 0;
        if (mv) arow = (long)(rl[m0 + a_row] >> g.gshift);
        const float* Ap = g.A + arow * (long)g.lda;

        int crow[MI * 2];
#pragma unroll
        for (int mi = 0; mi < MI; mi++)
#pragma unroll
            for (int h = 0; h < 2; h++) {
                int m = m0 + wm * (BM / 2) + mi * 16 + grp + h * 8;
                crow[mi * 2 + h] = (m < Me) ? rl[m] : -1;
            }

        float acc[MI][NI][4];
#pragma unroll
        for (int mi = 0; mi < MI; mi++)
#pragma unroll
            for (int ni = 0; ni < NI; ni++)
#pragma unroll
                for (int c = 0; c < 4; c++) acc[mi][ni][c] = 0.0f;

        for (int k0 = 0; k0 < Ke; k0 += 16) {
            float4 av[AL];
#pragma unroll
            for (int i = 0; i < AL; i++)
                av[i] = mv ? *(const float4*)(Ap + k0 + (aq + i) * 4)
                           : make_float4(0.f, 0.f, 0.f, 0.f);
            float4 bv[BL];
#pragma unroll
            for (int i = 0; i < BL; i++) {
                int idx = tid + i * 128;
                int r = idx / COLS4, col = (idx % COLS4) * 4;
                bv[i] = *(const float4*)(B + (long)(k0 + r) * g.ldb + n0 + col);
            }
            __syncthreads();
#pragma unroll
            for (int i = 0; i < AL; i++) {
                uint4 u;
                u.x = f2tf32(av[i].x); u.y = f2tf32(av[i].y);
                u.z = f2tf32(av[i].z); u.w = f2tf32(av[i].w);
                *(uint4*)&As[a_row][(aq + i) * 4] = u;
            }
#pragma unroll
            for (int i = 0; i < BL; i++) {
                int idx = tid + i * 128;
                int r = idx / COLS4, col = (idx % COLS4) * 4;
                uint4 u;
                u.x = f2tf32(bv[i].x); u.y = f2tf32(bv[i].y);
                u.z = f2tf32(bv[i].z); u.w = f2tf32(bv[i].w);
                *(uint4*)&Bs[r][col] = u;
            }
            __syncthreads();

#pragma unroll
            for (int ks = 0; ks < 2; ks++) {
                const int kk = ks * 8;
                unsigned a[MI][4], b[NI][2];
#pragma unroll
                for (int mi = 0; mi < MI; mi++) {
                    int mr = wm * (BM / 2) + mi * 16 + grp;
                    a[mi][0] = As[mr][kk + t4];
                    a[mi][1] = As[mr + 8][kk + t4];
                    a[mi][2] = As[mr][kk + t4 + 4];
                    a[mi][3] = As[mr + 8][kk + t4 + 4];
                }
#pragma unroll
                for (int ni = 0; ni < NI; ni++) {
                    int nc = wn * (8 * NI) + ni * 8 + grp;
                    b[ni][0] = Bs[kk + t4][nc];
                    b[ni][1] = Bs[kk + t4 + 4][nc];
                }
#pragma unroll
                for (int mi = 0; mi < MI; mi++)
#pragma unroll
                    for (int ni = 0; ni < NI; ni++)
                        MMA_TF32(acc[mi][ni], a[mi][0], a[mi][1], a[mi][2], a[mi][3],
                                 b[ni][0], b[ni][1]);
            }
        }

        const float* bias = g.bias + (long)e * g.biasStride;
#pragma unroll
        for (int ni = 0; ni < NI; ni++) {
            int c = n0 + wn * (8 * NI) + ni * 8 + t4 * 2;
            float b0 = bias[c], b1 = bias[c + 1];
#pragma unroll
            for (int mi = 0; mi < MI; mi++)
#pragma unroll
                for (int h = 0; h < 2; h++) {
                    int cr = crow[mi * 2 + h];
                    if (cr >= 0) {
                        float v0 = acc[mi][ni][h * 2 + 0] + b0;
                        float v1 = acc[mi][ni][h * 2 + 1] + b1;
                        if (aAct >= 0) { v0 = actf(aAct, v0); v1 = actf(aAct, v1); }
                        *(float2*)(g.C + (long)cr * g.ldc + c) = make_float2(v0, v1);
                    }
                }
        }
        __syncthreads();
    }
}

// ---------------- router GEMM: split-tf32 (hi/lo) ----------------------------
__global__ __launch_bounds__(256) void rgemm_k(GArgs g) {
    const int n0 = blockIdx.x * 64;
    const int m0 = blockIdx.y * 128;
    if (n0 >= g.N) return;

    __shared__ unsigned AsH[128][20], AsL[128][20];
    __shared__ unsigned BsH[16][72], BsL[16][72];

    const int tid = threadIdx.x, warp = tid >> 5, lane = tid & 31;
    const int grp = lane >> 2, t4 = lane & 3;
    const int wm = warp >> 1, wn = warp & 1;
    const int a_row = tid >> 1;
    const int aq = (tid & 1) * 2;
    const int bk = tid >> 4, cb = (tid & 15) * 4;

    const bool mv = (m0 + a_row) < g.M;
    const float* Ap = g.A + (long)(m0 + a_row) * g.lda;

    float acc[2][4][4];
#pragma unroll
    for (int mi = 0; mi < 2; mi++)
#pragma unroll
        for (int ni = 0; ni < 4; ni++)
#pragma unroll
            for (int c = 0; c < 4; c++) acc[mi][ni][c] = 0.0f;

    float4 av[2], bv;
    auto ldreg = [&](int k0) {
#pragma unroll
        for (int i = 0; i < 2; i++)
            av[i] = mv ? *(const float4*)(Ap + k0 + (aq + i) * 4)
                       : make_float4(0.f, 0.f, 0.f, 0.f);
        bv = *(const float4*)(g.B + (long)(k0 + bk) * g.ldb + n0 + cb);
    };

    const int KT = g.K >> 4;
    ldreg(0);
    for (int kt = 0; kt < KT; kt++) {
        __syncthreads();
#pragma unroll
        for (int i = 0; i < 2; i++) {
            float vv[4] = {av[i].x, av[i].y, av[i].z, av[i].w};
            uint4 uh, ul;
            unsigned* ph = &uh.x; unsigned* pl = &ul.x;
#pragma unroll
            for (int c = 0; c < 4; c++) {
                unsigned hb = f2tf32(vv[c]);
                ph[c] = hb;
                pl[c] = f2tf32(vv[c] - __uint_as_float(hb));
            }
            *(uint4*)&AsH[a_row][(aq + i) * 4] = uh;
            *(uint4*)&AsL[a_row][(aq + i) * 4] = ul;
        }
        {
            float vv[4] = {bv.x, bv.y, bv.z, bv.w};
            uint4 uh, ul;
            unsigned* ph = &uh.x; unsigned* pl = &ul.x;
#pragma unroll
            for (int c = 0; c < 4; c++) {
                unsigned hb = f2tf32(vv[c]);
                ph[c] = hb;
                pl[c] = f2tf32(vv[c] - __uint_as_float(hb));
            }
            *(uint4*)&BsH[bk][cb] = uh;
            *(uint4*)&BsL[bk][cb] = ul;
        }
        __syncthreads();

        if (kt + 1 < KT) ldreg((kt + 1) << 4);

#pragma unroll
        for (int ks = 0; ks < 2; ks++) {
            const int kk = ks * 8;
            unsigned ah[2][4], al[2][4], bh[4][2], bl[4][2];
#pragma unroll
            for (int mi = 0; mi < 2; mi++) {
                int mr = wm * 32 + mi * 16 + grp;
                ah[mi][0] = AsH[mr][kk + t4];     al[mi][0] = AsL[mr][kk + t4];
                ah[mi][1] = AsH[mr + 8][kk + t4]; al[mi][1] = AsL[mr + 8][kk + t4];
                ah[mi][2] = AsH[mr][kk + t4 + 4]; al[mi][2] = AsL[mr][kk + t4 + 4];
                ah[mi][3] = AsH[mr + 8][kk + t4 + 4]; al[mi][3] = AsL[mr + 8][kk + t4 + 4];
            }
#pragma unroll
            for (int ni = 0; ni < 4; ni++) {
                int nc = wn * 32 + ni * 8 + grp;
                bh[ni][0] = BsH[kk + t4][nc];     bl[ni][0] = BsL[kk + t4][nc];
                bh[ni][1] = BsH[kk + t4 + 4][nc]; bl[ni][1] = BsL[kk + t4 + 4][nc];
            }
#pragma unroll
            for (int mi = 0; mi < 2; mi++)
#pragma unroll
                for (int ni = 0; ni < 4; ni++) {
                    MMA_TF32(acc[mi][ni], ah[mi][0], ah[mi][1], ah[mi][2], ah[mi][3],
                             bh[ni][0], bh[ni][1]);
                    MMA_TF32(acc[mi][ni], ah[mi][0], ah[mi][1], ah[mi][2], ah[mi][3],
                             bl[ni][0], bl[ni][1]);
                    MMA_TF32(acc[mi][ni], al[mi][0], al[mi][1], al[mi][2], al[mi][3],
                             bh[ni][0], bh[ni][1]);
                }
        }
    }

    const int aAct = g.act - 1;
#pragma unroll
    for (int ni = 0; ni < 4; ni++) {
        int c = n0 + wn * 32 + ni * 8 + t4 * 2;
        float b0 = g.bias[c], b1 = g.bias[c + 1];
#pragma unroll
        for (int mi = 0; mi < 2; mi++)
#pragma unroll
            for (int h = 0; h < 2; h++) {
                int m = m0 + wm * 32 + mi * 16 + grp + h * 8;
                if (m < g.M) {
                    float v0 = acc[mi][ni][h * 2 + 0] + b0;
                    float v1 = acc[mi][ni][h * 2 + 1] + b1;
                    if (aAct >= 0) { v0 = actf(aAct, v0); v1 = actf(aAct, v1); }
                    *(float2*)(g.C + (long)m * g.ldc + c) = make_float2(v0, v1);
                }
            }
    }
}

// ---------------- zero counters ----------------------------------------------
__global__ void zero_k(int* cnt) {
    if (threadIdx.x < 48) cnt[threadIdx.x] = 0;
}

// ---------------- softmax + top-k + routing ----------------------------------
__global__ __launch_bounds__(256) void route_k(const float* scores, const float* temp,
                                               float* w, int* prei, int* posti,
                                               int* cnt, int* rows) {
    const int t = blockIdx.x, tid = threadIdx.x;
    const int wid = tid >> 5, lane = tid & 31;
    __shared__ float sm[NSCORE];
    __shared__ float ws1[8], ws2[8];
    __shared__ float wv[8];
    __shared__ int   wi[8];

    const float invT = 1.0f / temp[0];
    for (int j = tid; j < NSCORE; j += 256) sm[j] = scores[t * NSCORE + j] * invT;
    __syncthreads();

    float mx = -3.4e38f;
    for (int j = tid; j < NSCORE; j += 256) mx = fmaxf(mx, sm[j]);
    mx = wmax(mx);
    if (lane == 0) ws1[wid] = mx;
    __syncthreads();
    float gmax = ws1[0];
#pragma unroll
    for (int i = 1; i < 8; i++) gmax = fmaxf(gmax, ws1[i]);

    float sum = 0.0f;
    for (int j = tid; j < NSCORE; j += 256) sum += expf(sm[j] - gmax);
    sum = wsum(sum);
    if (lane == 0) ws2[wid] = sum;
    __syncthreads();
    float gsum = 0.0f;
#pragma unroll
    for (int i = 0; i < 8; i++) gsum += ws2[i];

    for (int k = 0; k < TOPK; k++) {
        float bv = -3.4e38f; int bi = NSCORE;
        for (int j = tid; j < NSCORE; j += 256) {
            float v = sm[j];
            if (v > bv || (v == bv && j < bi)) { bv = v; bi = j; }
        }
#pragma unroll
        for (int o = 16; o; o >>= 1) {
            float ov = __shfl_xor_sync(0xffffffffu, bv, o);
            int oi = __shfl_xor_sync(0xffffffffu, bi, o);
            if (ov > bv || (ov == bv && oi < bi)) { bv = ov; bi = oi; }
        }
        if (lane == 0) { wv[wid] = bv; wi[wid] = bi; }
        __syncthreads();
        if (tid == 0) {
            float fv = wv[0]; int fi = wi[0];
#pragma unroll
            for (int i = 1; i < 8; i++) {
                if (wv[i] > fv || (wv[i] == fv && wi[i] < fi)) { fv = wv[i]; fi = wi[i]; }
            }
            float prob = expf(fv - gmax) / gsum;
            float ww = (prob >= 1e-6f) ? prob : 0.0f;
            int pair = t * TOPK + k;
            int pe = fi >> 8, rem = fi & 255, me = rem >> 4, oe = rem & 15;
            prei[pair] = pe; posti[pair] = oe; w[pair] = ww;
            int s0 = atomicAdd(&cnt[pe], 1);       rows[pe * NPAIR + s0] = pair;
            int s1 = atomicAdd(&cnt[16 + me], 1);  rows[(16 + me) * NPAIR + s1] = pair;
            int s2 = atomicAdd(&cnt[32 + oe], 1);  rows[(32 + oe) * NPAIR + s2] = pair;
            sm[fi] = -3.4e38f;
        }
        __syncthreads();
    }
}

// ---------------- pre-expert LN + act (warp per pair) ------------------------
__global__ __launch_bounds__(256) void prelnact_k(const float* U, const int* prei,
                                                  const float* g, const float* b, float* X) {
    const int warp = threadIdx.x >> 5, lane = threadIdx.x & 31;
    const int p = blockIdx.x * 8 + warp;
    const int e = prei[p];
    float u[16];
#pragma unroll
    for (int j = 0; j < 16; j++) u[j] = U[p * D + lane + 32 * j];

    float s = 0.0f;
#pragma unroll
    for (int j = 0; j < 16; j++) s += u[j];
    const float mean = wsum(s) * (1.0f / D);

    float v = 0.0f;
#pragma unroll
    for (int j = 0; j < 16; j++) { float d = u[j] - mean; v += d * d; }
    const float rstd = rsqrtf(wsum(v) * (1.0f / D) + 1e-5f);

    const int a = e & 3;
#pragma unroll
    for (int j = 0; j < 16; j++) {
        int idx = lane + 32 * j;
        float val = (u[j] - mean) * rstd * g[e * D + idx] + b[e * D + idx];
        X[p * D + idx] = actf(a, val);
    }
}

// ---------------- post LN + weighted reduce (warp per pair) ------------------
__global__ __launch_bounds__(256) void final_k(const float* Z, const int* posti, const float* w,
                                               const float* g, const float* b, float* out) {
    const int t = blockIdx.x, tid = threadIdx.x;
    const int warp = tid >> 5, lane = tid & 31;
    __shared__ float sacc[8][D];

    const int pair = t * TOPK + warp;
    const int e = posti[pair];
    const float ww = w[pair];
    float z[16];
#pragma unroll
    for (int j = 0; j < 16; j++) z[j] = Z[(long)pair * D + lane + 32 * j];

    if ((e & 1) == 0) {
        float s = 0.0f;
#pragma unroll
        for (int j = 0; j < 16; j++) s += z[j];
        const float mean = wsum(s) * (1.0f / D);
        float v = 0.0f;
#pragma unroll
        for (int j = 0; j < 16; j++) { float d = z[j] - mean; v += d * d; }
        const float rstd = rsqrtf(wsum(v) * (1.0f / D) + 1e-5f);
#pragma unroll
        for (int j = 0; j < 16; j++) {
            int idx = lane + 32 * j;
            z[j] = (z[j] - mean) * rstd * g[e * D + idx] + b[e * D + idx];
        }
    }
#pragma unroll
    for (int j = 0; j < 16; j++) sacc[warp][lane + 32 * j] = ww * z[j];
    __syncthreads();

    for (int i = tid; i < D; i += 256) {
        float s = 0.0f;
#pragma unroll
        for (int k = 0; k < 8; k++) s += sacc[k][i];
        out[t * D + i] = s;
    }
}

// ---------------- launch -----------------------------------------------------
extern "C" void kernel_launch(void* const* d_in, const int* in_sizes, int n_in,
                              void* d_out, int out_size) {
    const float* x       = (const float*)d_in[0];
    const float* r_w1    = (const float*)d_in[1];
    const float* r_b1    = (const float*)d_in[2];
    const float* r_w2    = (const float*)d_in[3];
    const float* r_b2    = (const float*)d_in[4];
    const float* r_w3    = (const float*)d_in[5];
    const float* r_b3    = (const float*)d_in[6];
    const float* temp    = (const float*)d_in[7];
    const float* pre_w   = (const float*)d_in[8];
    const float* pre_b   = (const float*)d_in[9];
    const float* pre_g   = (const float*)d_in[10];
    const float* pre_be  = (const float*)d_in[11];
    const float* mlp_w1  = (const float*)d_in[12];
    const float* mlp_b1  = (const float*)d_in[13];
    const float* mlp_w2  = (const float*)d_in[14];
    const float* mlp_b2  = (const float*)d_in[15];
    const float* post_w  = (const float*)d_in[16];
    const float* post_b  = (const float*)d_in[17];
    const float* post_g  = (const float*)d_in[18];
    const float* post_be = (const float*)d_in[19];
    float* out = (float*)d_out;

    float *h1, *h2, *sc, *preu, *xin, *hmid, *y, *z, *w;
    int *prei, *posti, *cnt, *rows;
    cudaGetSymbolAddress((void**)&h1, g_h1);
    cudaGetSymbolAddress((void**)&h2, g_h2);
    cudaGetSymbolAddress((void**)&sc, g_scores);
    cudaGetSymbolAddress((void**)&preu, g_preu);
    cudaGetSymbolAddress((void**)&xin, g_xin);
    cudaGetSymbolAddress((void**)&hmid, g_hmid);
    cudaGetSymbolAddress((void**)&y, g_y);
    cudaGetSymbolAddress((void**)&z, g_z);
    cudaGetSymbolAddress((void**)&w, g_w);
    cudaGetSymbolAddress((void**)&prei, g_prei);
    cudaGetSymbolAddress((void**)&posti, g_posti);
    cudaGetSymbolAddress((void**)&cnt, g_cnt);
    cudaGetSymbolAddress((void**)&rows, g_rows);

    zero_k<<<1, 64>>>(cnt);

    // router: split-tf32 tensor core (near-fp32 accuracy, protects top-k)
    {
        GArgs a = {x, D, r_w1, 0, 512, r_b1, 0, h1, 512,
                   T, 512, 512, nullptr, nullptr, 0, 0, 0, 1};
        rgemm_k<<<dim3(8, 2, 1), 256>>>(a);
    }
    {
        GArgs a = {h1, 512, r_w2, 0, 256, r_b2, 0, h2, 256,
                   T, 256, 512, nullptr, nullptr, 0, 0, 0, 1};
        rgemm_k<<<dim3(4, 2, 1), 256>>>(a);
    }
    {
        GArgs a = {h2, 256, r_w3, 0, NSCORE, r_b3, 0, sc, NSCORE,
                   T, NSCORE, 256, nullptr, nullptr, 0, 0, 0, 0};
        rgemm_k<<<dim3(64, 2, 1), 256>>>(a);
    }

    route_k<<<T, 256>>>(sc, temp, w, prei, posti, cnt, rows);

    // experts: tf32 tensor cores; tiny tiles -> chip-filling block counts
    {
        GArgs a = {x, D, pre_w, (long)D * D, D, pre_b, D, preu, D,
                   NPAIR, D, D, rows, cnt, 3, 0, 0, 0};
        tgemm_k<32, 32><<<dim3(16, 8, NEXP), 128>>>(a);
    }
    prelnact_k<<<NPAIR / 8, 256>>>(preu, prei, pre_g, pre_be, xin);

    {
        GArgs a = {xin, D, mlp_w1, (long)D * MAXH, MAXH, mlp_b1, MAXH, hmid, MAXH,
                   NPAIR, MAXH, D, rows + 16 * NPAIR, cnt + 16, 0, 1, 0, 5};
        tgemm_k<32, 64><<<dim3(40, 8, NEXP), 128>>>(a);
    }
    {
        GArgs a = {hmid, MAXH, mlp_w2, (long)MAXH * D, D, mlp_b2, D, y, D,
                   NPAIR, D, MAXH, rows + 16 * NPAIR, cnt + 16, 0, 0, 1, 0};
        tgemm_k<32, 32><<<dim3(16, 8, NEXP), 128>>>(a);
    }
    {
        GArgs a = {y, D, post_w, (long)D * D, D, post_b, D, z, D,
                   NPAIR, D, D, rows + 32 * NPAIR, cnt + 32, 0, 0, 0, 0};
        tgemm_k<32, 32><<<dim3(16, 8, NEXP), 128>>>(a);
    }

    final_k<<<T, 256>>>(z, posti, w, post_g, post_be, out);
}

// round 7
// speedup vs baseline: 1.4408x; 1.1284x over previous
#include <cuda_runtime.h>
#include <math.h>
#include <stdint.h>

#define D      512
#define T      256
#define TOPK   8
#define NPAIR  2048
#define NEXP   16
#define MAXH   2560
#define NSCORE 4096

// ---------------- scratch ----------------------------------------------------
__device__ float g_h1[T * D];
__device__ float g_h2[T * 256];
__device__ float g_scores[T * NSCORE];
__device__ float g_preu[NPAIR * D];
__device__ float g_xin[NPAIR * D];
__device__ float g_hmid[NPAIR * MAXH];
__device__ float g_y[NPAIR * D];
__device__ float g_z[NPAIR * D];
__device__ float g_w[NPAIR];
__device__ int   g_prei[NPAIR];
__device__ int   g_posti[NPAIR];
__device__ int   g_cnt[48];
__device__ int   g_rows[48 * NPAIR];

// ---------------- helpers ----------------------------------------------------
__device__ __forceinline__ float actf(int a, float v) {
    switch (a) {
        case 0: return 0.5f * v * (1.0f + erff(v * 0.7071067811865476f));
        case 1: return fmaxf(v, 0.0f);
        case 2: return tanhf(v);
        default: return v / (1.0f + expf(-v));
    }
}

__device__ __forceinline__ unsigned f2tf32(float f) {
    unsigned r;
    asm("cvt.rna.tf32.f32 %0, %1;" : "=r"(r) : "f"(f));
    return r;
}

__device__ __forceinline__ uint32_t sptr(const void* p) {
    return (uint32_t)__cvta_generic_to_shared(p);
}

__device__ __forceinline__ void cpa16(uint32_t d, const float* s, bool pred) {
    int sz = pred ? 16 : 0;
    asm volatile("cp.async.cg.shared.global [%0], [%1], 16, %2;"
                 :: "r"(d), "l"(s), "r"(sz));
}

__device__ __forceinline__ float wsum(float v) {
#pragma unroll
    for (int o = 16; o; o >>= 1) v += __shfl_xor_sync(0xffffffffu, v, o);
    return v;
}
__device__ __forceinline__ float wmax(float v) {
#pragma unroll
    for (int o = 16; o; o >>= 1) v = fmaxf(v, __shfl_xor_sync(0xffffffffu, v, o));
    return v;
}

#define MMA_TF32(c, a0, a1, a2, a3, b0, b1)                                      \
    asm volatile("mma.sync.aligned.m16n8k8.row.col.f32.tf32.tf32.f32 "           \
                 "{%0,%1,%2,%3}, {%4,%5,%6,%7}, {%8,%9}, {%0,%1,%2,%3};"         \
                 : "+f"((c)[0]), "+f"((c)[1]), "+f"((c)[2]), "+f"((c)[3])        \
                 : "r"(a0), "r"(a1), "r"(a2), "r"(a3), "r"(b0), "r"(b1))

struct GArgs {
    const float* A; int lda;
    const float* B; long bStride; int ldb;
    const float* bias; int biasStride;
    float* C; int ldc;
    int M, N, K;
    const int* rows; const int* cnt;
    int gshift;
    int varN, varK;
    int act;  // 0 none, 1..4 fixed (act-1), 5 per-expert e&3
};

// ---------------- tf32 grouped GEMM (experts), multi-stage cp.async ----------
// BM=32, BN in {32,64}; 128 threads = 4 warps (2x2); warp tile 16 x (BN/2).
// S-stage cp.async pipeline hides LDG latency; tf32 cvt at fragment load.
template<int BM, int BN>
__global__ __launch_bounds__(128) void tgemm_k(GArgs g) {
    constexpr int S   = (BN == 32) ? 4 : 3;
    constexpr int NI  = BN / 16;
    constexpr int BNP = BN + 8;
    constexpr int BL  = BN / 32;
    constexpr int COLS4 = BN / 4;

    const int e  = blockIdx.z;
    const int Me = g.cnt[e];
    if (Me == 0) return;
    const int he = 512 * (2 + (e >> 2));
    const int Ne = g.varN ? he : g.N;
    const int Ke = g.varK ? he : g.K;
    const int n0 = blockIdx.x * BN;
    if (n0 >= Ne) return;

    const float* Bp = g.B + (long)e * g.bStride;
    const int*   rl = g.rows + e * NPAIR;

    __shared__ float As[S][BM][20];
    __shared__ float Bs[S][16][BNP];

    const int tid = threadIdx.x, warp = tid >> 5, lane = tid & 31;
    const int grp = lane >> 2, t4 = lane & 3;
    const int wm = warp >> 1, wn = warp & 1;
    const int a_row = tid >> 2;          // 0..31
    const int acol  = (tid & 3) * 4;     // 0,4,8,12

    const int aAct = (g.act == 5) ? (e & 3) : (g.act - 1);
    const int KT = Ke >> 4;

    for (int m0 = blockIdx.y * BM; m0 < Me; m0 += gridDim.y * BM) {
        const bool mv = (m0 + a_row) < Me;
        long arow = 0;
        if (mv) arow = (long)(rl[m0 + a_row] >> g.gshift);
        const float* Ap = g.A + arow * (long)g.lda;

        int crow[2];
#pragma unroll
        for (int h = 0; h < 2; h++) {
            int m = m0 + wm * 16 + grp + h * 8;
            crow[h] = (m < Me) ? rl[m] : -1;
        }

        float acc[NI][4];
#pragma unroll
        for (int ni = 0; ni < NI; ni++)
#pragma unroll
            for (int c = 0; c < 4; c++) acc[ni][c] = 0.0f;

        auto loadStage = [&](int s, int kt) {
            int k0 = kt << 4;
            cpa16(sptr(&As[s][a_row][acol]), Ap + k0 + acol, mv);
#pragma unroll
            for (int i = 0; i < BL; i++) {
                int idx = tid + i * 128;
                int r = idx / COLS4, col = (idx % COLS4) * 4;
                cpa16(sptr(&Bs[s][r][col]),
                      Bp + (long)(k0 + r) * g.ldb + n0 + col, true);
            }
            asm volatile("cp.async.commit_group;");
        };

        // prologue: fill S-1 stages (uniform group accounting)
#pragma unroll
        for (int s = 0; s < S - 1; s++) {
            if (s < KT) loadStage(s, s);
            else        asm volatile("cp.async.commit_group;");
        }

        for (int kt = 0; kt < KT; kt++) {
            asm volatile("cp.async.wait_group %0;" :: "n"(S - 2));
            __syncthreads();
            const int buf = kt % S;

            if (kt + S - 1 < KT) loadStage((kt + S - 1) % S, kt + S - 1);
            else                 asm volatile("cp.async.commit_group;");

#pragma unroll
            for (int ks = 0; ks < 2; ks++) {
                const int kk = ks * 8;
                unsigned a[4], b[NI][2];
                {
                    int mr = wm * 16 + grp;
                    a[0] = f2tf32(As[buf][mr][kk + t4]);
                    a[1] = f2tf32(As[buf][mr + 8][kk + t4]);
                    a[2] = f2tf32(As[buf][mr][kk + t4 + 4]);
                    a[3] = f2tf32(As[buf][mr + 8][kk + t4 + 4]);
                }
#pragma unroll
                for (int ni = 0; ni < NI; ni++) {
                    int nc = wn * (8 * NI) + ni * 8 + grp;
                    b[ni][0] = f2tf32(Bs[buf][kk + t4][nc]);
                    b[ni][1] = f2tf32(Bs[buf][kk + t4 + 4][nc]);
                }
#pragma unroll
                for (int ni = 0; ni < NI; ni++)
                    MMA_TF32(acc[ni], a[0], a[1], a[2], a[3], b[ni][0], b[ni][1]);
            }
        }

        const float* bias = g.bias + (long)e * g.biasStride;
#pragma unroll
        for (int ni = 0; ni < NI; ni++) {
            int c = n0 + wn * (8 * NI) + ni * 8 + t4 * 2;
            float b0 = bias[c], b1 = bias[c + 1];
#pragma unroll
            for (int h = 0; h < 2; h++) {
                int cr = crow[h];
                if (cr >= 0) {
                    float v0 = acc[ni][h * 2 + 0] + b0;
                    float v1 = acc[ni][h * 2 + 1] + b1;
                    if (aAct >= 0) { v0 = actf(aAct, v0); v1 = actf(aAct, v1); }
                    *(float2*)(g.C + (long)cr * g.ldc + c) = make_float2(v0, v1);
                }
            }
        }
        asm volatile("cp.async.wait_group 0;");
        __syncthreads();   // smem safe for next m0 tile
    }
}

// ---------------- router GEMM: split-tf32 (hi/lo) ----------------------------
__global__ __launch_bounds__(256) void rgemm_k(GArgs g) {
    const int n0 = blockIdx.x * 64;
    const int m0 = blockIdx.y * 128;
    if (n0 >= g.N) return;

    __shared__ unsigned AsH[128][20], AsL[128][20];
    __shared__ unsigned BsH[16][72], BsL[16][72];

    const int tid = threadIdx.x, warp = tid >> 5, lane = tid & 31;
    const int grp = lane >> 2, t4 = lane & 3;
    const int wm = warp >> 1, wn = warp & 1;
    const int a_row = tid >> 1;
    const int aq = (tid & 1) * 2;
    const int bk = tid >> 4, cb = (tid & 15) * 4;

    const bool mv = (m0 + a_row) < g.M;
    const float* Ap = g.A + (long)(m0 + a_row) * g.lda;

    float acc[2][4][4];
#pragma unroll
    for (int mi = 0; mi < 2; mi++)
#pragma unroll
        for (int ni = 0; ni < 4; ni++)
#pragma unroll
            for (int c = 0; c < 4; c++) acc[mi][ni][c] = 0.0f;

    float4 av[2], bv;
    auto ldreg = [&](int k0) {
#pragma unroll
        for (int i = 0; i < 2; i++)
            av[i] = mv ? *(const float4*)(Ap + k0 + (aq + i) * 4)
                       : make_float4(0.f, 0.f, 0.f, 0.f);
        bv = *(const float4*)(g.B + (long)(k0 + bk) * g.ldb + n0 + cb);
    };

    const int KT = g.K >> 4;
    ldreg(0);
    for (int kt = 0; kt < KT; kt++) {
        __syncthreads();
#pragma unroll
        for (int i = 0; i < 2; i++) {
            float vv[4] = {av[i].x, av[i].y, av[i].z, av[i].w};
            uint4 uh, ul;
            unsigned* ph = &uh.x; unsigned* pl = &ul.x;
#pragma unroll
            for (int c = 0; c < 4; c++) {
                unsigned hb = f2tf32(vv[c]);
                ph[c] = hb;
                pl[c] = f2tf32(vv[c] - __uint_as_float(hb));
            }
            *(uint4*)&AsH[a_row][(aq + i) * 4] = uh;
            *(uint4*)&AsL[a_row][(aq + i) * 4] = ul;
        }
        {
            float vv[4] = {bv.x, bv.y, bv.z, bv.w};
            uint4 uh, ul;
            unsigned* ph = &uh.x; unsigned* pl = &ul.x;
#pragma unroll
            for (int c = 0; c < 4; c++) {
                unsigned hb = f2tf32(vv[c]);
                ph[c] = hb;
                pl[c] = f2tf32(vv[c] - __uint_as_float(hb));
            }
            *(uint4*)&BsH[bk][cb] = uh;
            *(uint4*)&BsL[bk][cb] = ul;
        }
        __syncthreads();

        if (kt + 1 < KT) ldreg((kt + 1) << 4);

#pragma unroll
        for (int ks = 0; ks < 2; ks++) {
            const int kk = ks * 8;
            unsigned ah[2][4], al[2][4], bh[4][2], bl[4][2];
#pragma unroll
            for (int mi = 0; mi < 2; mi++) {
                int mr = wm * 32 + mi * 16 + grp;
                ah[mi][0] = AsH[mr][kk + t4];     al[mi][0] = AsL[mr][kk + t4];
                ah[mi][1] = AsH[mr + 8][kk + t4]; al[mi][1] = AsL[mr + 8][kk + t4];
                ah[mi][2] = AsH[mr][kk + t4 + 4]; al[mi][2] = AsL[mr][kk + t4 + 4];
                ah[mi][3] = AsH[mr + 8][kk + t4 + 4]; al[mi][3] = AsL[mr + 8][kk + t4 + 4];
            }
#pragma unroll
            for (int ni = 0; ni < 4; ni++) {
                int nc = wn * 32 + ni * 8 + grp;
                bh[ni][0] = BsH[kk + t4][nc];     bl[ni][0] = BsL[kk + t4][nc];
                bh[ni][1] = BsH[kk + t4 + 4][nc]; bl[ni][1] = BsL[kk + t4 + 4][nc];
            }
#pragma unroll
            for (int mi = 0; mi < 2; mi++)
#pragma unroll
                for (int ni = 0; ni < 4; ni++) {
                    MMA_TF32(acc[mi][ni], ah[mi][0], ah[mi][1], ah[mi][2], ah[mi][3],
                             bh[ni][0], bh[ni][1]);
                    MMA_TF32(acc[mi][ni], ah[mi][0], ah[mi][1], ah[mi][2], ah[mi][3],
                             bl[ni][0], bl[ni][1]);
                    MMA_TF32(acc[mi][ni], al[mi][0], al[mi][1], al[mi][2], al[mi][3],
                             bh[ni][0], bh[ni][1]);
                }
        }
    }

    const int aAct = g.act - 1;
#pragma unroll
    for (int ni = 0; ni < 4; ni++) {
        int c = n0 + wn * 32 + ni * 8 + t4 * 2;
        float b0 = g.bias[c], b1 = g.bias[c + 1];
#pragma unroll
        for (int mi = 0; mi < 2; mi++)
#pragma unroll
            for (int h = 0; h < 2; h++) {
                int m = m0 + wm * 32 + mi * 16 + grp + h * 8;
                if (m < g.M) {
                    float v0 = acc[mi][ni][h * 2 + 0] + b0;
                    float v1 = acc[mi][ni][h * 2 + 1] + b1;
                    if (aAct >= 0) { v0 = actf(aAct, v0); v1 = actf(aAct, v1); }
                    *(float2*)(g.C + (long)m * g.ldc + c) = make_float2(v0, v1);
                }
            }
    }
}

// ---------------- zero counters ----------------------------------------------
__global__ void zero_k(int* cnt) {
    if (threadIdx.x < 48) cnt[threadIdx.x] = 0;
}

// ---------------- softmax + top-k + routing ----------------------------------
__global__ __launch_bounds__(256) void route_k(const float* scores, const float* temp,
                                               float* w, int* prei, int* posti,
                                               int* cnt, int* rows) {
    const int t = blockIdx.x, tid = threadIdx.x;
    const int wid = tid >> 5, lane = tid & 31;
    __shared__ float sm[NSCORE];
    __shared__ float ws1[8], ws2[8];
    __shared__ float wv[8];
    __shared__ int   wi[8];

    const float invT = 1.0f / temp[0];
    for (int j = tid; j < NSCORE; j += 256) sm[j] = scores[t * NSCORE + j] * invT;
    __syncthreads();

    float mx = -3.4e38f;
    for (int j = tid; j < NSCORE; j += 256) mx = fmaxf(mx, sm[j]);
    mx = wmax(mx);
    if (lane == 0) ws1[wid] = mx;
    __syncthreads();
    float gmax = ws1[0];
#pragma unroll
    for (int i = 1; i < 8; i++) gmax = fmaxf(gmax, ws1[i]);

    float sum = 0.0f;
    for (int j = tid; j < NSCORE; j += 256) sum += expf(sm[j] - gmax);
    sum = wsum(sum);
    if (lane == 0) ws2[wid] = sum;
    __syncthreads();
    float gsum = 0.0f;
#pragma unroll
    for (int i = 0; i < 8; i++) gsum += ws2[i];

    for (int k = 0; k < TOPK; k++) {
        float bv = -3.4e38f; int bi = NSCORE;
        for (int j = tid; j < NSCORE; j += 256) {
            float v = sm[j];
            if (v > bv || (v == bv && j < bi)) { bv = v; bi = j; }
        }
#pragma unroll
        for (int o = 16; o; o >>= 1) {
            float ov = __shfl_xor_sync(0xffffffffu, bv, o);
            int oi = __shfl_xor_sync(0xffffffffu, bi, o);
            if (ov > bv || (ov == bv && oi < bi)) { bv = ov; bi = oi; }
        }
        if (lane == 0) { wv[wid] = bv; wi[wid] = bi; }
        __syncthreads();
        if (tid == 0) {
            float fv = wv[0]; int fi = wi[0];
#pragma unroll
            for (int i = 1; i < 8; i++) {
                if (wv[i] > fv || (wv[i] == fv && wi[i] < fi)) { fv = wv[i]; fi = wi[i]; }
            }
            float prob = expf(fv - gmax) / gsum;
            float ww = (prob >= 1e-6f) ? prob : 0.0f;
            int pair = t * TOPK + k;
            int pe = fi >> 8, rem = fi & 255, me = rem >> 4, oe = rem & 15;
            prei[pair] = pe; posti[pair] = oe; w[pair] = ww;
            int s0 = atomicAdd(&cnt[pe], 1);       rows[pe * NPAIR + s0] = pair;
            int s1 = atomicAdd(&cnt[16 + me], 1);  rows[(16 + me) * NPAIR + s1] = pair;
            int s2 = atomicAdd(&cnt[32 + oe], 1);  rows[(32 + oe) * NPAIR + s2] = pair;
            sm[fi] = -3.4e38f;
        }
        __syncthreads();
    }
}

// ---------------- pre-expert LN + act (warp per pair) ------------------------
__global__ __launch_bounds__(256) void prelnact_k(const float* U, const int* prei,
                                                  const float* g, const float* b, float* X) {
    const int warp = threadIdx.x >> 5, lane = threadIdx.x & 31;
    const int p = blockIdx.x * 8 + warp;
    const int e = prei[p];
    float u[16];
#pragma unroll
    for (int j = 0; j < 16; j++) u[j] = U[p * D + lane + 32 * j];

    float s = 0.0f;
#pragma unroll
    for (int j = 0; j < 16; j++) s += u[j];
    const float mean = wsum(s) * (1.0f / D);

    float v = 0.0f;
#pragma unroll
    for (int j = 0; j < 16; j++) { float d = u[j] - mean; v += d * d; }
    const float rstd = rsqrtf(wsum(v) * (1.0f / D) + 1e-5f);

    const int a = e & 3;
#pragma unroll
    for (int j = 0; j < 16; j++) {
        int idx = lane + 32 * j;
        float val = (u[j] - mean) * rstd * g[e * D + idx] + b[e * D + idx];
        X[p * D + idx] = actf(a, val);
    }
}

// ---------------- post LN + weighted reduce (warp per pair) ------------------
__global__ __launch_bounds__(256) void final_k(const float* Z, const int* posti, const float* w,
                                               const float* g, const float* b, float* out) {
    const int t = blockIdx.x, tid = threadIdx.x;
    const int warp = tid >> 5, lane = tid & 31;
    __shared__ float sacc[8][D];

    const int pair = t * TOPK + warp;
    const int e = posti[pair];
    const float ww = w[pair];
    float z[16];
#pragma unroll
    for (int j = 0; j < 16; j++) z[j] = Z[(long)pair * D + lane + 32 * j];

    if ((e & 1) == 0) {
        float s = 0.0f;
#pragma unroll
        for (int j = 0; j < 16; j++) s += z[j];
        const float mean = wsum(s) * (1.0f / D);
        float v = 0.0f;
#pragma unroll
        for (int j = 0; j < 16; j++) { float d = z[j] - mean; v += d * d; }
        const float rstd = rsqrtf(wsum(v) * (1.0f / D) + 1e-5f);
#pragma unroll
        for (int j = 0; j < 16; j++) {
            int idx = lane + 32 * j;
            z[j] = (z[j] - mean) * rstd * g[e * D + idx] + b[e * D + idx];
        }
    }
#pragma unroll
    for (int j = 0; j < 16; j++) sacc[warp][lane + 32 * j] = ww * z[j];
    __syncthreads();

    for (int i = tid; i < D; i += 256) {
        float s = 0.0f;
#pragma unroll
        for (int k = 0; k < 8; k++) s += sacc[k][i];
        out[t * D + i] = s;
    }
}

// ---------------- launch -----------------------------------------------------
extern "C" void kernel_launch(void* const* d_in, const int* in_sizes, int n_in,
                              void* d_out, int out_size) {
    const float* x       = (const float*)d_in[0];
    const float* r_w1    = (const float*)d_in[1];
    const float* r_b1    = (const float*)d_in[2];
    const float* r_w2    = (const float*)d_in[3];
    const float* r_b2    = (const float*)d_in[4];
    const float* r_w3    = (const float*)d_in[5];
    const float* r_b3    = (const float*)d_in[6];
    const float* temp    = (const float*)d_in[7];
    const float* pre_w   = (const float*)d_in[8];
    const float* pre_b   = (const float*)d_in[9];
    const float* pre_g   = (const float*)d_in[10];
    const float* pre_be  = (const float*)d_in[11];
    const float* mlp_w1  = (const float*)d_in[12];
    const float* mlp_b1  = (const float*)d_in[13];
    const float* mlp_w2  = (const float*)d_in[14];
    const float* mlp_b2  = (const float*)d_in[15];
    const float* post_w  = (const float*)d_in[16];
    const float* post_b  = (const float*)d_in[17];
    const float* post_g  = (const float*)d_in[18];
    const float* post_be = (const float*)d_in[19];
    float* out = (float*)d_out;

    float *h1, *h2, *sc, *preu, *xin, *hmid, *y, *z, *w;
    int *prei, *posti, *cnt, *rows;
    cudaGetSymbolAddress((void**)&h1, g_h1);
    cudaGetSymbolAddress((void**)&h2, g_h2);
    cudaGetSymbolAddress((void**)&sc, g_scores);
    cudaGetSymbolAddress((void**)&preu, g_preu);
    cudaGetSymbolAddress((void**)&xin, g_xin);
    cudaGetSymbolAddress((void**)&hmid, g_hmid);
    cudaGetSymbolAddress((void**)&y, g_y);
    cudaGetSymbolAddress((void**)&z, g_z);
    cudaGetSymbolAddress((void**)&w, g_w);
    cudaGetSymbolAddress((void**)&prei, g_prei);
    cudaGetSymbolAddress((void**)&posti, g_posti);
    cudaGetSymbolAddress((void**)&cnt, g_cnt);
    cudaGetSymbolAddress((void**)&rows, g_rows);

    zero_k<<<1, 64>>>(cnt);

    // router: split-tf32 tensor core (near-fp32 accuracy, protects top-k)
    {
        GArgs a = {x, D, r_w1, 0, 512, r_b1, 0, h1, 512,
                   T, 512, 512, nullptr, nullptr, 0, 0, 0, 1};
        rgemm_k<<<dim3(8, 2, 1), 256>>>(a);
    }
    {
        GArgs a = {h1, 512, r_w2, 0, 256, r_b2, 0, h2, 256,
                   T, 256, 512, nullptr, nullptr, 0, 0, 0, 1};
        rgemm_k<<<dim3(4, 2, 1), 256>>>(a);
    }
    {
        GArgs a = {h2, 256, r_w3, 0, NSCORE, r_b3, 0, sc, NSCORE,
                   T, NSCORE, 256, nullptr, nullptr, 0, 0, 0, 0};
        rgemm_k<<<dim3(64, 2, 1), 256>>>(a);
    }

    route_k<<<T, 256>>>(sc, temp, w, prei, posti, cnt, rows);

    // experts: tf32 tensor cores; small tiles + cp.async multi-stage pipeline
    {
        GArgs a = {x, D, pre_w, (long)D * D, D, pre_b, D, preu, D,
                   NPAIR, D, D, rows, cnt, 3, 0, 0, 0};
        tgemm_k<32, 32><<<dim3(16, 8, NEXP), 128>>>(a);
    }
    prelnact_k<<<NPAIR / 8, 256>>>(preu, prei, pre_g, pre_be, xin);

    {
        GArgs a = {xin, D, mlp_w1, (long)D * MAXH, MAXH, mlp_b1, MAXH, hmid, MAXH,
                   NPAIR, MAXH, D, rows + 16 * NPAIR, cnt + 16, 0, 1, 0, 5};
        tgemm_k<32, 64><<<dim3(40, 8, NEXP), 128>>>(a);
    }
    {
        GArgs a = {hmid, MAXH, mlp_w2, (long)MAXH * D, D, mlp_b2, D, y, D,
                   NPAIR, D, MAXH, rows + 16 * NPAIR, cnt + 16, 0, 0, 1, 0};
        tgemm_k<32, 32><<<dim3(16, 8, NEXP), 128>>>(a);
    }
    {
        GArgs a = {y, D, post_w, (long)D * D, D, post_b, D, z, D,
                   NPAIR, D, D, rows + 32 * NPAIR, cnt + 32, 0, 0, 0, 0};
        tgemm_k<32, 32><<<dim3(16, 8, NEXP), 128>>>(a);
    }

    final_k<<<T, 256>>>(z, posti, w, post_g, post_be, out);
}

// round 8
// speedup vs baseline: 1.6310x; 1.1320x over previous
#include <cuda_runtime.h>
#include <math.h>
#include <stdint.h>

#define D      512
#define T      256
#define TOPK   8
#define NPAIR  2048
#define NEXP   16
#define MAXH   2560
#define NSCORE 4096

// ---------------- scratch ----------------------------------------------------
__device__ float g_h1[T * D];
__device__ float g_h2[T * 256];
__device__ float g_scores[T * NSCORE];
__device__ float g_preu[NPAIR * D];
__device__ float g_xin[NPAIR * D];
__device__ float g_hmid[NPAIR * MAXH];
__device__ float g_y[NPAIR * D];
__device__ float g_z[NPAIR * D];
__device__ float g_w[NPAIR];
__device__ int   g_prei[NPAIR];
__device__ int   g_posti[NPAIR];
__device__ int   g_cnt[48];
__device__ int   g_rows[48 * NPAIR];

// ---------------- helpers ----------------------------------------------------
__device__ __forceinline__ float actf(int a, float v) {
    switch (a) {
        case 0: return 0.5f * v * (1.0f + erff(v * 0.7071067811865476f));
        case 1: return fmaxf(v, 0.0f);
        case 2: return tanhf(v);
        default: return v / (1.0f + expf(-v));
    }
}

__device__ __forceinline__ unsigned f2tf32(float f) {
    unsigned r;
    asm("cvt.rna.tf32.f32 %0, %1;" : "=r"(r) : "f"(f));
    return r;
}

__device__ __forceinline__ uint32_t sptr(const void* p) {
    return (uint32_t)__cvta_generic_to_shared(p);
}

__device__ __forceinline__ void cpa16(uint32_t d, const float* s, bool pred) {
    int sz = pred ? 16 : 0;
    asm volatile("cp.async.cg.shared.global [%0], [%1], 16, %2;"
                 :: "r"(d), "l"(s), "r"(sz));
}

__device__ __forceinline__ float wsum(float v) {
#pragma unroll
    for (int o = 16; o; o >>= 1) v += __shfl_xor_sync(0xffffffffu, v, o);
    return v;
}
__device__ __forceinline__ float wmax(float v) {
#pragma unroll
    for (int o = 16; o; o >>= 1) v = fmaxf(v, __shfl_xor_sync(0xffffffffu, v, o));
    return v;
}

#define MMA_TF32(c, a0, a1, a2, a3, b0, b1)                                      \
    asm volatile("mma.sync.aligned.m16n8k8.row.col.f32.tf32.tf32.f32 "           \
                 "{%0,%1,%2,%3}, {%4,%5,%6,%7}, {%8,%9}, {%0,%1,%2,%3};"         \
                 : "+f"((c)[0]), "+f"((c)[1]), "+f"((c)[2]), "+f"((c)[3])        \
                 : "r"(a0), "r"(a1), "r"(a2), "r"(a3), "r"(b0), "r"(b1))

struct GArgs {
    const float* A; int lda;
    const float* B; long bStride; int ldb;
    const float* bias; int biasStride;
    float* C; int ldc;
    int M, N, K;
    const int* rows; const int* cnt;
    int gshift;
    int varN, varK;
    int act;  // 0 none, 1..4 fixed (act-1), 5 per-expert e&3
};

// ---------------- tf32 grouped GEMM (experts) --------------------------------
// BM=32, BN=64; 64 threads = 2 warps (1x2); warp tile 32x32 (MI=2, NI=4).
// S=4 stage cp.async pipeline; 4:1 non-tensor:tensor issue ratio.
__global__ __launch_bounds__(64) void tgemm_k(GArgs g) {
    constexpr int S   = 4;
    constexpr int BM  = 32;
    constexpr int BN  = 64;
    constexpr int MI  = 2;
    constexpr int NI  = 4;
    constexpr int BNP = BN + 8;

    const int e  = blockIdx.z;
    const int Me = g.cnt[e];
    if (Me == 0) return;
    const int he = 512 * (2 + (e >> 2));
    const int Ne = g.varN ? he : g.N;
    const int Ke = g.varK ? he : g.K;
    const int n0 = blockIdx.x * BN;
    if (n0 >= Ne) return;

    const float* Bp = g.B + (long)e * g.bStride;
    const int*   rl = g.rows + e * NPAIR;

    __shared__ float As[S][BM][20];
    __shared__ float Bs[S][16][BNP];

    const int tid = threadIdx.x, lane = tid & 31;
    const int wn = tid >> 5;            // 0..1
    const int grp = lane >> 2, t4 = lane & 3;
    const int a_row = tid >> 1;         // 0..31
    const int aq    = (tid & 1) * 2;    // float4 slot base {0,2}

    const int aAct = (g.act == 5) ? (e & 3) : (g.act - 1);
    const int KT = Ke >> 4;

    for (int m0 = blockIdx.y * BM; m0 < Me; m0 += gridDim.y * BM) {
        const bool mv = (m0 + a_row) < Me;
        long arow = 0;
        if (mv) arow = (long)(rl[m0 + a_row] >> g.gshift);
        const float* Ap = g.A + arow * (long)g.lda;

        int crow[MI * 2];
#pragma unroll
        for (int mi = 0; mi < MI; mi++)
#pragma unroll
            for (int h = 0; h < 2; h++) {
                int m = m0 + mi * 16 + grp + h * 8;
                crow[mi * 2 + h] = (m < Me) ? rl[m] : -1;
            }

        float acc[MI][NI][4];
#pragma unroll
        for (int mi = 0; mi < MI; mi++)
#pragma unroll
            for (int ni = 0; ni < NI; ni++)
#pragma unroll
                for (int c = 0; c < 4; c++) acc[mi][ni][c] = 0.0f;

        auto loadStage = [&](int s, int kt) {
            int k0 = kt << 4;
            // A: 32 rows x 16 floats = 128 float4, 2 per thread
#pragma unroll
            for (int i = 0; i < 2; i++)
                cpa16(sptr(&As[s][a_row][(aq + i) * 4]), Ap + k0 + (aq + i) * 4, mv);
            // B: 16 rows x 64 floats = 256 float4, 4 per thread
#pragma unroll
            for (int i = 0; i < 4; i++) {
                int idx = tid + i * 64;
                int r = idx >> 4, col = (idx & 15) * 4;
                cpa16(sptr(&Bs[s][r][col]),
                      Bp + (long)(k0 + r) * g.ldb + n0 + col, true);
            }
            asm volatile("cp.async.commit_group;");
        };

#pragma unroll
        for (int s = 0; s < S - 1; s++) {
            if (s < KT) loadStage(s, s);
            else        asm volatile("cp.async.commit_group;");
        }

        for (int kt = 0; kt < KT; kt++) {
            asm volatile("cp.async.wait_group %0;" :: "n"(S - 2));
            __syncthreads();
            const int buf = kt % S;

            if (kt + S - 1 < KT) loadStage((kt + S - 1) % S, kt + S - 1);
            else                 asm volatile("cp.async.commit_group;");

#pragma unroll
            for (int ks = 0; ks < 2; ks++) {
                const int kk = ks * 8;
                unsigned a[MI][4], b[NI][2];
#pragma unroll
                for (int mi = 0; mi < MI; mi++) {
                    int mr = mi * 16 + grp;
                    a[mi][0] = f2tf32(As[buf][mr][kk + t4]);
                    a[mi][1] = f2tf32(As[buf][mr + 8][kk + t4]);
                    a[mi][2] = f2tf32(As[buf][mr][kk + t4 + 4]);
                    a[mi][3] = f2tf32(As[buf][mr + 8][kk + t4 + 4]);
                }
#pragma unroll
                for (int ni = 0; ni < NI; ni++) {
                    int nc = wn * 32 + ni * 8 + grp;
                    b[ni][0] = f2tf32(Bs[buf][kk + t4][nc]);
                    b[ni][1] = f2tf32(Bs[buf][kk + t4 + 4][nc]);
                }
#pragma unroll
                for (int mi = 0; mi < MI; mi++)
#pragma unroll
                    for (int ni = 0; ni < NI; ni++)
                        MMA_TF32(acc[mi][ni], a[mi][0], a[mi][1], a[mi][2], a[mi][3],
                                 b[ni][0], b[ni][1]);
            }
        }

        const float* bias = g.bias + (long)e * g.biasStride;
#pragma unroll
        for (int ni = 0; ni < NI; ni++) {
            int c = n0 + wn * 32 + ni * 8 + t4 * 2;
            float b0 = bias[c], b1 = bias[c + 1];
#pragma unroll
            for (int mi = 0; mi < MI; mi++)
#pragma unroll
                for (int h = 0; h < 2; h++) {
                    int cr = crow[mi * 2 + h];
                    if (cr >= 0) {
                        float v0 = acc[mi][ni][h * 2 + 0] + b0;
                        float v1 = acc[mi][ni][h * 2 + 1] + b1;
                        if (aAct >= 0) { v0 = actf(aAct, v0); v1 = actf(aAct, v1); }
                        *(float2*)(g.C + (long)cr * g.ldc + c) = make_float2(v0, v1);
                    }
                }
        }
        asm volatile("cp.async.wait_group 0;");
        __syncthreads();
    }
}

// ---------------- router GEMM: split-tf32 (hi/lo) ----------------------------
__global__ __launch_bounds__(256) void rgemm_k(GArgs g) {
    const int n0 = blockIdx.x * 64;
    const int m0 = blockIdx.y * 128;
    if (n0 >= g.N) return;

    __shared__ unsigned AsH[128][20], AsL[128][20];
    __shared__ unsigned BsH[16][72], BsL[16][72];

    const int tid = threadIdx.x, warp = tid >> 5, lane = tid & 31;
    const int grp = lane >> 2, t4 = lane & 3;
    const int wm = warp >> 1, wn = warp & 1;
    const int a_row = tid >> 1;
    const int aq = (tid & 1) * 2;
    const int bk = tid >> 4, cb = (tid & 15) * 4;

    const bool mv = (m0 + a_row) < g.M;
    const float* Ap = g.A + (long)(m0 + a_row) * g.lda;

    float acc[2][4][4];
#pragma unroll
    for (int mi = 0; mi < 2; mi++)
#pragma unroll
        for (int ni = 0; ni < 4; ni++)
#pragma unroll
            for (int c = 0; c < 4; c++) acc[mi][ni][c] = 0.0f;

    float4 av[2], bv;
    auto ldreg = [&](int k0) {
#pragma unroll
        for (int i = 0; i < 2; i++)
            av[i] = mv ? *(const float4*)(Ap + k0 + (aq + i) * 4)
                       : make_float4(0.f, 0.f, 0.f, 0.f);
        bv = *(const float4*)(g.B + (long)(k0 + bk) * g.ldb + n0 + cb);
    };

    const int KT = g.K >> 4;
    ldreg(0);
    for (int kt = 0; kt < KT; kt++) {
        __syncthreads();
#pragma unroll
        for (int i = 0; i < 2; i++) {
            float vv[4] = {av[i].x, av[i].y, av[i].z, av[i].w};
            uint4 uh, ul;
            unsigned* ph = &uh.x; unsigned* pl = &ul.x;
#pragma unroll
            for (int c = 0; c < 4; c++) {
                unsigned hb = f2tf32(vv[c]);
                ph[c] = hb;
                pl[c] = f2tf32(vv[c] - __uint_as_float(hb));
            }
            *(uint4*)&AsH[a_row][(aq + i) * 4] = uh;
            *(uint4*)&AsL[a_row][(aq + i) * 4] = ul;
        }
        {
            float vv[4] = {bv.x, bv.y, bv.z, bv.w};
            uint4 uh, ul;
            unsigned* ph = &uh.x; unsigned* pl = &ul.x;
#pragma unroll
            for (int c = 0; c < 4; c++) {
                unsigned hb = f2tf32(vv[c]);
                ph[c] = hb;
                pl[c] = f2tf32(vv[c] - __uint_as_float(hb));
            }
            *(uint4*)&BsH[bk][cb] = uh;
            *(uint4*)&BsL[bk][cb] = ul;
        }
        __syncthreads();

        if (kt + 1 < KT) ldreg((kt + 1) << 4);

#pragma unroll
        for (int ks = 0; ks < 2; ks++) {
            const int kk = ks * 8;
            unsigned ah[2][4], al[2][4], bh[4][2], bl[4][2];
#pragma unroll
            for (int mi = 0; mi < 2; mi++) {
                int mr = wm * 32 + mi * 16 + grp;
                ah[mi][0] = AsH[mr][kk + t4];     al[mi][0] = AsL[mr][kk + t4];
                ah[mi][1] = AsH[mr + 8][kk + t4]; al[mi][1] = AsL[mr + 8][kk + t4];
                ah[mi][2] = AsH[mr][kk + t4 + 4]; al[mi][2] = AsL[mr][kk + t4 + 4];
                ah[mi][3] = AsH[mr + 8][kk + t4 + 4]; al[mi][3] = AsL[mr + 8][kk + t4 + 4];
            }
#pragma unroll
            for (int ni = 0; ni < 4; ni++) {
                int nc = wn * 32 + ni * 8 + grp;
                bh[ni][0] = BsH[kk + t4][nc];     bl[ni][0] = BsL[kk + t4][nc];
                bh[ni][1] = BsH[kk + t4 + 4][nc]; bl[ni][1] = BsL[kk + t4 + 4][nc];
            }
#pragma unroll
            for (int mi = 0; mi < 2; mi++)
#pragma unroll
                for (int ni = 0; ni < 4; ni++) {
                    MMA_TF32(acc[mi][ni], ah[mi][0], ah[mi][1], ah[mi][2], ah[mi][3],
                             bh[ni][0], bh[ni][1]);
                    MMA_TF32(acc[mi][ni], ah[mi][0], ah[mi][1], ah[mi][2], ah[mi][3],
                             bl[ni][0], bl[ni][1]);
                    MMA_TF32(acc[mi][ni], al[mi][0], al[mi][1], al[mi][2], al[mi][3],
                             bh[ni][0], bh[ni][1]);
                }
        }
    }

    const int aAct = g.act - 1;
#pragma unroll
    for (int ni = 0; ni < 4; ni++) {
        int c = n0 + wn * 32 + ni * 8 + t4 * 2;
        float b0 = g.bias[c], b1 = g.bias[c + 1];
#pragma unroll
        for (int mi = 0; mi < 2; mi++)
#pragma unroll
            for (int h = 0; h < 2; h++) {
                int m = m0 + wm * 32 + mi * 16 + grp + h * 8;
                if (m < g.M) {
                    float v0 = acc[mi][ni][h * 2 + 0] + b0;
                    float v1 = acc[mi][ni][h * 2 + 1] + b1;
                    if (aAct >= 0) { v0 = actf(aAct, v0); v1 = actf(aAct, v1); }
                    *(float2*)(g.C + (long)m * g.ldc + c) = make_float2(v0, v1);
                }
            }
    }
}

// ---------------- zero counters ----------------------------------------------
__global__ void zero_k(int* cnt) {
    if (threadIdx.x < 48) cnt[threadIdx.x] = 0;
}

// ---------------- softmax + top-k + routing ----------------------------------
__global__ __launch_bounds__(256) void route_k(const float* scores, const float* temp,
                                               float* w, int* prei, int* posti,
                                               int* cnt, int* rows) {
    const int t = blockIdx.x, tid = threadIdx.x;
    const int wid = tid >> 5, lane = tid & 31;
    __shared__ float sm[NSCORE];
    __shared__ float ws1[8], ws2[8];
    __shared__ float wv[8];
    __shared__ int   wi[8];

    const float invT = 1.0f / temp[0];
    for (int j = tid; j < NSCORE; j += 256) sm[j] = scores[t * NSCORE + j] * invT;
    __syncthreads();

    float mx = -3.4e38f;
    for (int j = tid; j < NSCORE; j += 256) mx = fmaxf(mx, sm[j]);
    mx = wmax(mx);
    if (lane == 0) ws1[wid] = mx;
    __syncthreads();
    float gmax = ws1[0];
#pragma unroll
    for (int i = 1; i < 8; i++) gmax = fmaxf(gmax, ws1[i]);

    float sum = 0.0f;
    for (int j = tid; j < NSCORE; j += 256) sum += expf(sm[j] - gmax);
    sum = wsum(sum);
    if (lane == 0) ws2[wid] = sum;
    __syncthreads();
    float gsum = 0.0f;
#pragma unroll
    for (int i = 0; i < 8; i++) gsum += ws2[i];

    for (int k = 0; k < TOPK; k++) {
        float bv = -3.4e38f; int bi = NSCORE;
        for (int j = tid; j < NSCORE; j += 256) {
            float v = sm[j];
            if (v > bv || (v == bv && j < bi)) { bv = v; bi = j; }
        }
#pragma unroll
        for (int o = 16; o; o >>= 1) {
            float ov = __shfl_xor_sync(0xffffffffu, bv, o);
            int oi = __shfl_xor_sync(0xffffffffu, bi, o);
            if (ov > bv || (ov == bv && oi < bi)) { bv = ov; bi = oi; }
        }
        if (lane == 0) { wv[wid] = bv; wi[wid] = bi; }
        __syncthreads();
        if (tid == 0) {
            float fv = wv[0]; int fi = wi[0];
#pragma unroll
            for (int i = 1; i < 8; i++) {
                if (wv[i] > fv || (wv[i] == fv && wi[i] < fi)) { fv = wv[i]; fi = wi[i]; }
            }
            float prob = expf(fv - gmax) / gsum;
            float ww = (prob >= 1e-6f) ? prob : 0.0f;
            int pair = t * TOPK + k;
            int pe = fi >> 8, rem = fi & 255, me = rem >> 4, oe = rem & 15;
            prei[pair] = pe; posti[pair] = oe; w[pair] = ww;
            int s0 = atomicAdd(&cnt[pe], 1);       rows[pe * NPAIR + s0] = pair;
            int s1 = atomicAdd(&cnt[16 + me], 1);  rows[(16 + me) * NPAIR + s1] = pair;
            int s2 = atomicAdd(&cnt[32 + oe], 1);  rows[(32 + oe) * NPAIR + s2] = pair;
            sm[fi] = -3.4e38f;
        }
        __syncthreads();
    }
}

// ---------------- pre-expert LN + act (warp per pair) ------------------------
__global__ __launch_bounds__(256) void prelnact_k(const float* U, const int* prei,
                                                  const float* g, const float* b, float* X) {
    const int warp = threadIdx.x >> 5, lane = threadIdx.x & 31;
    const int p = blockIdx.x * 8 + warp;
    const int e = prei[p];
    float u[16];
#pragma unroll
    for (int j = 0; j < 16; j++) u[j] = U[p * D + lane + 32 * j];

    float s = 0.0f;
#pragma unroll
    for (int j = 0; j < 16; j++) s += u[j];
    const float mean = wsum(s) * (1.0f / D);

    float v = 0.0f;
#pragma unroll
    for (int j = 0; j < 16; j++) { float d = u[j] - mean; v += d * d; }
    const float rstd = rsqrtf(wsum(v) * (1.0f / D) + 1e-5f);

    const int a = e & 3;
#pragma unroll
    for (int j = 0; j < 16; j++) {
        int idx = lane + 32 * j;
        float val = (u[j] - mean) * rstd * g[e * D + idx] + b[e * D + idx];
        X[p * D + idx] = actf(a, val);
    }
}

// ---------------- post LN + weighted reduce (warp per pair) ------------------
__global__ __launch_bounds__(256) void final_k(const float* Z, const int* posti, const float* w,
                                               const float* g, const float* b, float* out) {
    const int t = blockIdx.x, tid = threadIdx.x;
    const int warp = tid >> 5, lane = tid & 31;
    __shared__ float sacc[8][D];

    const int pair = t * TOPK + warp;
    const int e = posti[pair];
    const float ww = w[pair];
    float z[16];
#pragma unroll
    for (int j = 0; j < 16; j++) z[j] = Z[(long)pair * D + lane + 32 * j];

    if ((e & 1) == 0) {
        float s = 0.0f;
#pragma unroll
        for (int j = 0; j < 16; j++) s += z[j];
        const float mean = wsum(s) * (1.0f / D);
        float v = 0.0f;
#pragma unroll
        for (int j = 0; j < 16; j++) { float d = z[j] - mean; v += d * d; }
        const float rstd = rsqrtf(wsum(v) * (1.0f / D) + 1e-5f);
#pragma unroll
        for (int j = 0; j < 16; j++) {
            int idx = lane + 32 * j;
            z[j] = (z[j] - mean) * rstd * g[e * D + idx] + b[e * D + idx];
        }
    }
#pragma unroll
    for (int j = 0; j < 16; j++) sacc[warp][lane + 32 * j] = ww * z[j];
    __syncthreads();

    for (int i = tid; i < D; i += 256) {
        float s = 0.0f;
#pragma unroll
        for (int k = 0; k < 8; k++) s += sacc[k][i];
        out[t * D + i] = s;
    }
}

// ---------------- launch -----------------------------------------------------
extern "C" void kernel_launch(void* const* d_in, const int* in_sizes, int n_in,
                              void* d_out, int out_size) {
    const float* x       = (const float*)d_in[0];
    const float* r_w1    = (const float*)d_in[1];
    const float* r_b1    = (const float*)d_in[2];
    const float* r_w2    = (const float*)d_in[3];
    const float* r_b2    = (const float*)d_in[4];
    const float* r_w3    = (const float*)d_in[5];
    const float* r_b3    = (const float*)d_in[6];
    const float* temp    = (const float*)d_in[7];
    const float* pre_w   = (const float*)d_in[8];
    const float* pre_b   = (const float*)d_in[9];
    const float* pre_g   = (const float*)d_in[10];
    const float* pre_be  = (const float*)d_in[11];
    const float* mlp_w1  = (const float*)d_in[12];
    const float* mlp_b1  = (const float*)d_in[13];
    const float* mlp_w2  = (const float*)d_in[14];
    const float* mlp_b2  = (const float*)d_in[15];
    const float* post_w  = (const float*)d_in[16];
    const float* post_b  = (const float*)d_in[17];
    const float* post_g  = (const float*)d_in[18];
    const float* post_be = (const float*)d_in[19];
    float* out = (float*)d_out;

    float *h1, *h2, *sc, *preu, *xin, *hmid, *y, *z, *w;
    int *prei, *posti, *cnt, *rows;
    cudaGetSymbolAddress((void**)&h1, g_h1);
    cudaGetSymbolAddress((void**)&h2, g_h2);
    cudaGetSymbolAddress((void**)&sc, g_scores);
    cudaGetSymbolAddress((void**)&preu, g_preu);
    cudaGetSymbolAddress((void**)&xin, g_xin);
    cudaGetSymbolAddress((void**)&hmid, g_hmid);
    cudaGetSymbolAddress((void**)&y, g_y);
    cudaGetSymbolAddress((void**)&z, g_z);
    cudaGetSymbolAddress((void**)&w, g_w);
    cudaGetSymbolAddress((void**)&prei, g_prei);
    cudaGetSymbolAddress((void**)&posti, g_posti);
    cudaGetSymbolAddress((void**)&cnt, g_cnt);
    cudaGetSymbolAddress((void**)&rows, g_rows);

    zero_k<<<1, 64>>>(cnt);

    // router: split-tf32 tensor core (near-fp32 accuracy, protects top-k)
    {
        GArgs a = {x, D, r_w1, 0, 512, r_b1, 0, h1, 512,
                   T, 512, 512, nullptr, nullptr, 0, 0, 0, 1};
        rgemm_k<<<dim3(8, 2, 1), 256>>>(a);
    }
    {
        GArgs a = {h1, 512, r_w2, 0, 256, r_b2, 0, h2, 256,
                   T, 256, 512, nullptr, nullptr, 0, 0, 0, 1};
        rgemm_k<<<dim3(4, 2, 1), 256>>>(a);
    }
    {
        GArgs a = {h2, 256, r_w3, 0, NSCORE, r_b3, 0, sc, NSCORE,
                   T, NSCORE, 256, nullptr, nullptr, 0, 0, 0, 0};
        rgemm_k<<<dim3(64, 2, 1), 256>>>(a);
    }

    route_k<<<T, 256>>>(sc, temp, w, prei, posti, cnt, rows);

    // experts: tf32 tensor cores, 2-warp blocks, warp tile 32x32, cp.async S=4
    {
        GArgs a = {x, D, pre_w, (long)D * D, D, pre_b, D, preu, D,
                   NPAIR, D, D, rows, cnt, 3, 0, 0, 0};
        tgemm_k<<<dim3(8, 6, NEXP), 64>>>(a);
    }
    prelnact_k<<<NPAIR / 8, 256>>>(preu, prei, pre_g, pre_be, xin);

    {
        GArgs a = {xin, D, mlp_w1, (long)D * MAXH, MAXH, mlp_b1, MAXH, hmid, MAXH,
                   NPAIR, MAXH, D, rows + 16 * NPAIR, cnt + 16, 0, 1, 0, 5};
        tgemm_k<<<dim3(40, 4, NEXP), 64>>>(a);
    }
    {
        GArgs a = {hmid, MAXH, mlp_w2, (long)MAXH * D, D, mlp_b2, D, y, D,
                   NPAIR, D, MAXH, rows + 16 * NPAIR, cnt + 16, 0, 0, 1, 0};
        tgemm_k<<<dim3(8, 6, NEXP), 64>>>(a);
    }
    {
        GArgs a = {y, D, post_w, (long)D * D, D, post_b, D, z, D,
                   NPAIR, D, D, rows + 32 * NPAIR, cnt + 32, 0, 0, 0, 0};
        tgemm_k<<<dim3(8, 6, NEXP), 64>>>(a);
    }

    final_k<<<T, 256>>>(z, posti, w, post_g, post_be, out);
}

// round 9
// speedup vs baseline: 1.6849x; 1.0330x over previous
#include <cuda_runtime.h>
#include <math.h>
#include <stdint.h>

#define D      512
#define T      256
#define TOPK   8
#define NPAIR  2048
#define NEXP   16
#define MAXH   2560
#define NSCORE 4096

// ---------------- scratch ----------------------------------------------------
__device__ float g_h1[T * D];
__device__ float g_h2[T * 256];
__device__ float g_scores[T * NSCORE];
__device__ float g_preu[2 * NPAIR * D];      // 2 split-K partials
__device__ float g_xin[NPAIR * D];
__device__ float g_hmid[NPAIR * MAXH];
__device__ float g_y4[4 * NPAIR * D];        // 4 split-K partials (mlp2)
__device__ float g_y[NPAIR * D];
__device__ float g_z[2 * NPAIR * D];         // 2 split-K partials (post)
__device__ float g_w[NPAIR];
__device__ int   g_prei[NPAIR];
__device__ int   g_mlpi[NPAIR];
__device__ int   g_posti[NPAIR];
__device__ int   g_cnt[48];
__device__ int   g_rows[48 * NPAIR];

// ---------------- helpers ----------------------------------------------------
__device__ __forceinline__ float actf(int a, float v) {
    switch (a) {
        case 0: return 0.5f * v * (1.0f + erff(v * 0.7071067811865476f));
        case 1: return fmaxf(v, 0.0f);
        case 2: return tanhf(v);
        default: return v / (1.0f + expf(-v));
    }
}

__device__ __forceinline__ unsigned f2tf32(float f) {
    unsigned r;
    asm("cvt.rna.tf32.f32 %0, %1;" : "=r"(r) : "f"(f));
    return r;
}

__device__ __forceinline__ uint32_t sptr(const void* p) {
    return (uint32_t)__cvta_generic_to_shared(p);
}

__device__ __forceinline__ void cpa16(uint32_t d, const float* s, bool pred) {
    int sz = pred ? 16 : 0;
    asm volatile("cp.async.cg.shared.global [%0], [%1], 16, %2;"
                 :: "r"(d), "l"(s), "r"(sz));
}

__device__ __forceinline__ float wsum(float v) {
#pragma unroll
    for (int o = 16; o; o >>= 1) v += __shfl_xor_sync(0xffffffffu, v, o);
    return v;
}
__device__ __forceinline__ float wmax(float v) {
#pragma unroll
    for (int o = 16; o; o >>= 1) v = fmaxf(v, __shfl_xor_sync(0xffffffffu, v, o));
    return v;
}

#define MMA_TF32(c, a0, a1, a2, a3, b0, b1)                                      \
    asm volatile("mma.sync.aligned.m16n8k8.row.col.f32.tf32.tf32.f32 "           \
                 "{%0,%1,%2,%3}, {%4,%5,%6,%7}, {%8,%9}, {%0,%1,%2,%3};"         \
                 : "+f"((c)[0]), "+f"((c)[1]), "+f"((c)[2]), "+f"((c)[3])        \
                 : "r"(a0), "r"(a1), "r"(a2), "r"(a3), "r"(b0), "r"(b1))

struct GArgs {
    const float* A; int lda;
    const float* B; long bStride; int ldb;
    const float* bias; int biasStride;
    float* C; int ldc;
    int M, N, K;
    const int* rows; const int* cnt;
    int gshift;
    int varN, varK;
    int act;            // 0 none, 1..4 fixed (act-1), 5 per-expert e&3
    long cStride;       // split-K partial-buffer stride (elements)
};

// ---------------- tf32 grouped GEMM (experts), split-K capable ---------------
// BM=32, BN=64; 64 threads = 2 warps; warp tile 32x32; S=4 cp.async stages.
// SPLIT>1: each x-slice computes a K-range into C + slice*cStride (no bias/act).
template<int SPLIT>
__global__ __launch_bounds__(64) void tgemm_k(GArgs g) {
    constexpr int S   = 4;
    constexpr int BM  = 32;
    constexpr int BN  = 64;
    constexpr int MI  = 2;
    constexpr int NI  = 4;
    constexpr int BNP = BN + 8;

    const int e  = blockIdx.z;
    const int Me = g.cnt[e];
    if (Me == 0) return;
    const int he = 512 * (2 + (e >> 2));
    const int Ne = g.varN ? he : g.N;
    const int Ke = g.varK ? he : g.K;

    const int ntiles = gridDim.x / SPLIT;
    const int slice  = blockIdx.x / ntiles;
    const int n0     = (blockIdx.x % ntiles) * BN;
    if (n0 >= Ne) return;

    const int Ksl   = Ke / SPLIT;
    const int kbase = slice * Ksl;
    const int KT    = Ksl >> 4;

    float* Cp = g.C + (long)slice * g.cStride;

    const float* Bp = g.B + (long)e * g.bStride;
    const int*   rl = g.rows + e * NPAIR;

    __shared__ float As[S][BM][20];
    __shared__ float Bs[S][16][BNP];

    const int tid = threadIdx.x, lane = tid & 31;
    const int wn = tid >> 5;
    const int grp = lane >> 2, t4 = lane & 3;
    const int a_row = tid >> 1;
    const int aq    = (tid & 1) * 2;

    const int aAct = (g.act == 5) ? (e & 3) : (g.act - 1);

    for (int m0 = blockIdx.y * BM; m0 < Me; m0 += gridDim.y * BM) {
        const bool mv = (m0 + a_row) < Me;
        long arow = 0;
        if (mv) arow = (long)(rl[m0 + a_row] >> g.gshift);
        const float* Ap = g.A + arow * (long)g.lda + kbase;

        int crow[MI * 2];
#pragma unroll
        for (int mi = 0; mi < MI; mi++)
#pragma unroll
            for (int h = 0; h < 2; h++) {
                int m = m0 + mi * 16 + grp + h * 8;
                crow[mi * 2 + h] = (m < Me) ? rl[m] : -1;
            }

        float acc[MI][NI][4];
#pragma unroll
        for (int mi = 0; mi < MI; mi++)
#pragma unroll
            for (int ni = 0; ni < NI; ni++)
#pragma unroll
                for (int c = 0; c < 4; c++) acc[mi][ni][c] = 0.0f;

        auto loadStage = [&](int s, int kt) {
            int k0 = kt << 4;
#pragma unroll
            for (int i = 0; i < 2; i++)
                cpa16(sptr(&As[s][a_row][(aq + i) * 4]), Ap + k0 + (aq + i) * 4, mv);
#pragma unroll
            for (int i = 0; i < 4; i++) {
                int idx = tid + i * 64;
                int r = idx >> 4, col = (idx & 15) * 4;
                cpa16(sptr(&Bs[s][r][col]),
                      Bp + (long)(kbase + k0 + r) * g.ldb + n0 + col, true);
            }
            asm volatile("cp.async.commit_group;");
        };

#pragma unroll
        for (int s = 0; s < S - 1; s++) {
            if (s < KT) loadStage(s, s);
            else        asm volatile("cp.async.commit_group;");
        }

        for (int kt = 0; kt < KT; kt++) {
            asm volatile("cp.async.wait_group %0;" :: "n"(S - 2));
            __syncthreads();
            const int buf = kt % S;

            if (kt + S - 1 < KT) loadStage((kt + S - 1) % S, kt + S - 1);
            else                 asm volatile("cp.async.commit_group;");

#pragma unroll
            for (int ks = 0; ks < 2; ks++) {
                const int kk = ks * 8;
                unsigned a[MI][4], b[NI][2];
#pragma unroll
                for (int mi = 0; mi < MI; mi++) {
                    int mr = mi * 16 + grp;
                    a[mi][0] = f2tf32(As[buf][mr][kk + t4]);
                    a[mi][1] = f2tf32(As[buf][mr + 8][kk + t4]);
                    a[mi][2] = f2tf32(As[buf][mr][kk + t4 + 4]);
                    a[mi][3] = f2tf32(As[buf][mr + 8][kk + t4 + 4]);
                }
#pragma unroll
                for (int ni = 0; ni < NI; ni++) {
                    int nc = wn * 32 + ni * 8 + grp;
                    b[ni][0] = f2tf32(Bs[buf][kk + t4][nc]);
                    b[ni][1] = f2tf32(Bs[buf][kk + t4 + 4][nc]);
                }
#pragma unroll
                for (int mi = 0; mi < MI; mi++)
#pragma unroll
                    for (int ni = 0; ni < NI; ni++)
                        MMA_TF32(acc[mi][ni], a[mi][0], a[mi][1], a[mi][2], a[mi][3],
                                 b[ni][0], b[ni][1]);
            }
        }

#pragma unroll
        for (int ni = 0; ni < NI; ni++) {
            int c = n0 + wn * 32 + ni * 8 + t4 * 2;
            float b0 = 0.0f, b1 = 0.0f;
            if (SPLIT == 1) {
                const float* bias = g.bias + (long)e * g.biasStride;
                b0 = bias[c]; b1 = bias[c + 1];
            }
#pragma unroll
            for (int mi = 0; mi < MI; mi++)
#pragma unroll
                for (int h = 0; h < 2; h++) {
                    int cr = crow[mi * 2 + h];
                    if (cr >= 0) {
                        float v0 = acc[mi][ni][h * 2 + 0] + b0;
                        float v1 = acc[mi][ni][h * 2 + 1] + b1;
                        if (SPLIT == 1 && aAct >= 0) { v0 = actf(aAct, v0); v1 = actf(aAct, v1); }
                        *(float2*)(Cp + (long)cr * g.ldc + c) = make_float2(v0, v1);
                    }
                }
        }
        asm volatile("cp.async.wait_group 0;");
        __syncthreads();
    }
}

// ---------------- router GEMM: split-tf32 (hi/lo) ----------------------------
__global__ __launch_bounds__(256) void rgemm_k(GArgs g) {
    const int n0 = blockIdx.x * 64;
    const int m0 = blockIdx.y * 128;
    if (n0 >= g.N) return;

    __shared__ unsigned AsH[128][20], AsL[128][20];
    __shared__ unsigned BsH[16][72], BsL[16][72];

    const int tid = threadIdx.x, warp = tid >> 5, lane = tid & 31;
    const int grp = lane >> 2, t4 = lane & 3;
    const int wm = warp >> 1, wn = warp & 1;
    const int a_row = tid >> 1;
    const int aq = (tid & 1) * 2;
    const int bk = tid >> 4, cb = (tid & 15) * 4;

    const bool mv = (m0 + a_row) < g.M;
    const float* Ap = g.A + (long)(m0 + a_row) * g.lda;

    float acc[2][4][4];
#pragma unroll
    for (int mi = 0; mi < 2; mi++)
#pragma unroll
        for (int ni = 0; ni < 4; ni++)
#pragma unroll
            for (int c = 0; c < 4; c++) acc[mi][ni][c] = 0.0f;

    float4 av[2], bv;
    auto ldreg = [&](int k0) {
#pragma unroll
        for (int i = 0; i < 2; i++)
            av[i] = mv ? *(const float4*)(Ap + k0 + (aq + i) * 4)
                       : make_float4(0.f, 0.f, 0.f, 0.f);
        bv = *(const float4*)(g.B + (long)(k0 + bk) * g.ldb + n0 + cb);
    };

    const int KT = g.K >> 4;
    ldreg(0);
    for (int kt = 0; kt < KT; kt++) {
        __syncthreads();
#pragma unroll
        for (int i = 0; i < 2; i++) {
            float vv[4] = {av[i].x, av[i].y, av[i].z, av[i].w};
            uint4 uh, ul;
            unsigned* ph = &uh.x; unsigned* pl = &ul.x;
#pragma unroll
            for (int c = 0; c < 4; c++) {
                unsigned hb = f2tf32(vv[c]);
                ph[c] = hb;
                pl[c] = f2tf32(vv[c] - __uint_as_float(hb));
            }
            *(uint4*)&AsH[a_row][(aq + i) * 4] = uh;
            *(uint4*)&AsL[a_row][(aq + i) * 4] = ul;
        }
        {
            float vv[4] = {bv.x, bv.y, bv.z, bv.w};
            uint4 uh, ul;
            unsigned* ph = &uh.x; unsigned* pl = &ul.x;
#pragma unroll
            for (int c = 0; c < 4; c++) {
                unsigned hb = f2tf32(vv[c]);
                ph[c] = hb;
                pl[c] = f2tf32(vv[c] - __uint_as_float(hb));
            }
            *(uint4*)&BsH[bk][cb] = uh;
            *(uint4*)&BsL[bk][cb] = ul;
        }
        __syncthreads();

        if (kt + 1 < KT) ldreg((kt + 1) << 4);

#pragma unroll
        for (int ks = 0; ks < 2; ks++) {
            const int kk = ks * 8;
            unsigned ah[2][4], al[2][4], bh[4][2], bl[4][2];
#pragma unroll
            for (int mi = 0; mi < 2; mi++) {
                int mr = wm * 32 + mi * 16 + grp;
                ah[mi][0] = AsH[mr][kk + t4];     al[mi][0] = AsL[mr][kk + t4];
                ah[mi][1] = AsH[mr + 8][kk + t4]; al[mi][1] = AsL[mr + 8][kk + t4];
                ah[mi][2] = AsH[mr][kk + t4 + 4]; al[mi][2] = AsL[mr][kk + t4 + 4];
                ah[mi][3] = AsH[mr + 8][kk + t4 + 4]; al[mi][3] = AsL[mr + 8][kk + t4 + 4];
            }
#pragma unroll
            for (int ni = 0; ni < 4; ni++) {
                int nc = wn * 32 + ni * 8 + grp;
                bh[ni][0] = BsH[kk + t4][nc];     bl[ni][0] = BsL[kk + t4][nc];
                bh[ni][1] = BsH[kk + t4 + 4][nc]; bl[ni][1] = BsL[kk + t4 + 4][nc];
            }
#pragma unroll
            for (int mi = 0; mi < 2; mi++)
#pragma unroll
                for (int ni = 0; ni < 4; ni++) {
                    MMA_TF32(acc[mi][ni], ah[mi][0], ah[mi][1], ah[mi][2], ah[mi][3],
                             bh[ni][0], bh[ni][1]);
                    MMA_TF32(acc[mi][ni], ah[mi][0], ah[mi][1], ah[mi][2], ah[mi][3],
                             bl[ni][0], bl[ni][1]);
                    MMA_TF32(acc[mi][ni], al[mi][0], al[mi][1], al[mi][2], al[mi][3],
                             bh[ni][0], bh[ni][1]);
                }
        }
    }

    const int aAct = g.act - 1;
#pragma unroll
    for (int ni = 0; ni < 4; ni++) {
        int c = n0 + wn * 32 + ni * 8 + t4 * 2;
        float b0 = g.bias[c], b1 = g.bias[c + 1];
#pragma unroll
        for (int mi = 0; mi < 2; mi++)
#pragma unroll
            for (int h = 0; h < 2; h++) {
                int m = m0 + wm * 32 + mi * 16 + grp + h * 8;
                if (m < g.M) {
                    float v0 = acc[mi][ni][h * 2 + 0] + b0;
                    float v1 = acc[mi][ni][h * 2 + 1] + b1;
                    if (aAct >= 0) { v0 = actf(aAct, v0); v1 = actf(aAct, v1); }
                    *(float2*)(g.C + (long)m * g.ldc + c) = make_float2(v0, v1);
                }
            }
    }
}

// ---------------- zero counters ----------------------------------------------
__global__ void zero_k(int* cnt) {
    if (threadIdx.x < 48) cnt[threadIdx.x] = 0;
}

// ---------------- softmax + top-k + routing ----------------------------------
__global__ __launch_bounds__(256) void route_k(const float* scores, const float* temp,
                                               float* w, int* prei, int* mlpi, int* posti,
                                               int* cnt, int* rows) {
    const int t = blockIdx.x, tid = threadIdx.x;
    const int wid = tid >> 5, lane = tid & 31;
    __shared__ float sm[NSCORE];
    __shared__ float ws1[8], ws2[8];
    __shared__ float wv[8];
    __shared__ int   wi[8];

    const float invT = 1.0f / temp[0];
    for (int j = tid; j < NSCORE; j += 256) sm[j] = scores[t * NSCORE + j] * invT;
    __syncthreads();

    float mx = -3.4e38f;
    for (int j = tid; j < NSCORE; j += 256) mx = fmaxf(mx, sm[j]);
    mx = wmax(mx);
    if (lane == 0) ws1[wid] = mx;
    __syncthreads();
    float gmax = ws1[0];
#pragma unroll
    for (int i = 1; i < 8; i++) gmax = fmaxf(gmax, ws1[i]);

    float sum = 0.0f;
    for (int j = tid; j < NSCORE; j += 256) sum += expf(sm[j] - gmax);
    sum = wsum(sum);
    if (lane == 0) ws2[wid] = sum;
    __syncthreads();
    float gsum = 0.0f;
#pragma unroll
    for (int i = 0; i < 8; i++) gsum += ws2[i];

    for (int k = 0; k < TOPK; k++) {
        float bv = -3.4e38f; int bi = NSCORE;
        for (int j = tid; j < NSCORE; j += 256) {
            float v = sm[j];
            if (v > bv || (v == bv && j < bi)) { bv = v; bi = j; }
        }
#pragma unroll
        for (int o = 16; o; o >>= 1) {
            float ov = __shfl_xor_sync(0xffffffffu, bv, o);
            int oi = __shfl_xor_sync(0xffffffffu, bi, o);
            if (ov > bv || (ov == bv && oi < bi)) { bv = ov; bi = oi; }
        }
        if (lane == 0) { wv[wid] = bv; wi[wid] = bi; }
        __syncthreads();
        if (tid == 0) {
            float fv = wv[0]; int fi = wi[0];
#pragma unroll
            for (int i = 1; i < 8; i++) {
                if (wv[i] > fv || (wv[i] == fv && wi[i] < fi)) { fv = wv[i]; fi = wi[i]; }
            }
            float prob = expf(fv - gmax) / gsum;
            float ww = (prob >= 1e-6f) ? prob : 0.0f;
            int pair = t * TOPK + k;
            int pe = fi >> 8, rem = fi & 255, me = rem >> 4, oe = rem & 15;
            prei[pair] = pe; mlpi[pair] = me; posti[pair] = oe; w[pair] = ww;
            int s0 = atomicAdd(&cnt[pe], 1);       rows[pe * NPAIR + s0] = pair;
            int s1 = atomicAdd(&cnt[16 + me], 1);  rows[(16 + me) * NPAIR + s1] = pair;
            int s2 = atomicAdd(&cnt[32 + oe], 1);  rows[(32 + oe) * NPAIR + s2] = pair;
            sm[fi] = -3.4e38f;
        }
        __syncthreads();
    }
}

// ---------------- pre: sum 2 partials + bias + LN + act ----------------------
__global__ __launch_bounds__(256) void prelnact_k(const float* U, const int* prei,
                                                  const float* pbias,
                                                  const float* g, const float* b, float* X) {
    const int warp = threadIdx.x >> 5, lane = threadIdx.x & 31;
    const int p = blockIdx.x * 8 + warp;
    const int e = prei[p];
    float u[16];
#pragma unroll
    for (int j = 0; j < 16; j++) {
        int idx = lane + 32 * j;
        u[j] = U[p * D + idx] + U[(long)NPAIR * D + p * D + idx] + pbias[e * D + idx];
    }

    float s = 0.0f;
#pragma unroll
    for (int j = 0; j < 16; j++) s += u[j];
    const float mean = wsum(s) * (1.0f / D);

    float v = 0.0f;
#pragma unroll
    for (int j = 0; j < 16; j++) { float d = u[j] - mean; v += d * d; }
    const float rstd = rsqrtf(wsum(v) * (1.0f / D) + 1e-5f);

    const int a = e & 3;
#pragma unroll
    for (int j = 0; j < 16; j++) {
        int idx = lane + 32 * j;
        float val = (u[j] - mean) * rstd * g[e * D + idx] + b[e * D + idx];
        X[p * D + idx] = actf(a, val);
    }
}

// ---------------- mlp2: sum 4 partials + bias --------------------------------
__global__ __launch_bounds__(256) void addy_k(const float* Y4, const int* mlpi,
                                              const float* b2, float* y) {
    const int warp = threadIdx.x >> 5, lane = threadIdx.x & 31;
    const int p = blockIdx.x * 8 + warp;
    const int e = mlpi[p];
#pragma unroll
    for (int j = 0; j < 16; j++) {
        int idx = lane + 32 * j;
        long off = (long)p * D + idx;
        float s = Y4[off] + Y4[(long)NPAIR * D + off]
                + Y4[2L * NPAIR * D + off] + Y4[3L * NPAIR * D + off]
                + b2[e * D + idx];
        y[off] = s;
    }
}

// ---------------- post: sum 2 partials + bias + LN + weighted reduce ---------
__global__ __launch_bounds__(256) void final_k(const float* Z, const int* posti, const float* w,
                                               const float* pbias,
                                               const float* g, const float* b, float* out) {
    const int t = blockIdx.x, tid = threadIdx.x;
    const int warp = tid >> 5, lane = tid & 31;
    __shared__ float sacc[8][D];

    const int pair = t * TOPK + warp;
    const int e = posti[pair];
    const float ww = w[pair];
    float z[16];
#pragma unroll
    for (int j = 0; j < 16; j++) {
        int idx = lane + 32 * j;
        z[j] = Z[(long)pair * D + idx] + Z[(long)NPAIR * D + (long)pair * D + idx]
             + pbias[e * D + idx];
    }

    if ((e & 1) == 0) {
        float s = 0.0f;
#pragma unroll
        for (int j = 0; j < 16; j++) s += z[j];
        const float mean = wsum(s) * (1.0f / D);
        float v = 0.0f;
#pragma unroll
        for (int j = 0; j < 16; j++) { float d = z[j] - mean; v += d * d; }
        const float rstd = rsqrtf(wsum(v) * (1.0f / D) + 1e-5f);
#pragma unroll
        for (int j = 0; j < 16; j++) {
            int idx = lane + 32 * j;
            z[j] = (z[j] - mean) * rstd * g[e * D + idx] + b[e * D + idx];
        }
    }
#pragma unroll
    for (int j = 0; j < 16; j++) sacc[warp][lane + 32 * j] = ww * z[j];
    __syncthreads();

    for (int i = tid; i < D; i += 256) {
        float s = 0.0f;
#pragma unroll
        for (int k = 0; k < 8; k++) s += sacc[k][i];
        out[t * D + i] = s;
    }
}

// ---------------- launch -----------------------------------------------------
extern "C" void kernel_launch(void* const* d_in, const int* in_sizes, int n_in,
                              void* d_out, int out_size) {
    const float* x       = (const float*)d_in[0];
    const float* r_w1    = (const float*)d_in[1];
    const float* r_b1    = (const float*)d_in[2];
    const float* r_w2    = (const float*)d_in[3];
    const float* r_b2    = (const float*)d_in[4];
    const float* r_w3    = (const float*)d_in[5];
    const float* r_b3    = (const float*)d_in[6];
    const float* temp    = (const float*)d_in[7];
    const float* pre_w   = (const float*)d_in[8];
    const float* pre_b   = (const float*)d_in[9];
    const float* pre_g   = (const float*)d_in[10];
    const float* pre_be  = (const float*)d_in[11];
    const float* mlp_w1  = (const float*)d_in[12];
    const float* mlp_b1  = (const float*)d_in[13];
    const float* mlp_w2  = (const float*)d_in[14];
    const float* mlp_b2  = (const float*)d_in[15];
    const float* post_w  = (const float*)d_in[16];
    const float* post_b  = (const float*)d_in[17];
    const float* post_g  = (const float*)d_in[18];
    const float* post_be = (const float*)d_in[19];
    float* out = (float*)d_out;

    float *h1, *h2, *sc, *preu, *xin, *hmid, *y4, *y, *z, *w;
    int *prei, *mlpi, *posti, *cnt, *rows;
    cudaGetSymbolAddress((void**)&h1, g_h1);
    cudaGetSymbolAddress((void**)&h2, g_h2);
    cudaGetSymbolAddress((void**)&sc, g_scores);
    cudaGetSymbolAddress((void**)&preu, g_preu);
    cudaGetSymbolAddress((void**)&xin, g_xin);
    cudaGetSymbolAddress((void**)&hmid, g_hmid);
    cudaGetSymbolAddress((void**)&y4, g_y4);
    cudaGetSymbolAddress((void**)&y, g_y);
    cudaGetSymbolAddress((void**)&z, g_z);
    cudaGetSymbolAddress((void**)&w, g_w);
    cudaGetSymbolAddress((void**)&prei, g_prei);
    cudaGetSymbolAddress((void**)&mlpi, g_mlpi);
    cudaGetSymbolAddress((void**)&posti, g_posti);
    cudaGetSymbolAddress((void**)&cnt, g_cnt);
    cudaGetSymbolAddress((void**)&rows, g_rows);

    zero_k<<<1, 64>>>(cnt);

    // router: split-tf32 tensor core (near-fp32 accuracy, protects top-k)
    {
        GArgs a = {x, D, r_w1, 0, 512, r_b1, 0, h1, 512,
                   T, 512, 512, nullptr, nullptr, 0, 0, 0, 1};
        rgemm_k<<<dim3(8, 2, 1), 256>>>(a);
    }
    {
        GArgs a = {h1, 512, r_w2, 0, 256, r_b2, 0, h2, 256,
                   T, 256, 512, nullptr, nullptr, 0, 0, 0, 1};
        rgemm_k<<<dim3(4, 2, 1), 256>>>(a);
    }
    {
        GArgs a = {h2, 256, r_w3, 0, NSCORE, r_b3, 0, sc, NSCORE,
                   T, NSCORE, 256, nullptr, nullptr, 0, 0, 0, 0};
        rgemm_k<<<dim3(64, 2, 1), 256>>>(a);
    }

    route_k<<<T, 256>>>(sc, temp, w, prei, mlpi, posti, cnt, rows);

    // pre: split-K=2, partials -> preu[2], consumer sums + bias + LN + act
    {
        GArgs a = {x, D, pre_w, (long)D * D, D, pre_b, D, preu, D,
                   NPAIR, D, D, rows, cnt, 3, 0, 0, 0, (long)NPAIR * D};
        tgemm_k<2><<<dim3(16, 6, NEXP), 64>>>(a);
    }
    prelnact_k<<<NPAIR / 8, 256>>>(preu, prei, pre_b, pre_g, pre_be, xin);

    // mlp1: fused bias+act, enough parallelism already
    {
        GArgs a = {xin, D, mlp_w1, (long)D * MAXH, MAXH, mlp_b1, MAXH, hmid, MAXH,
                   NPAIR, MAXH, D, rows + 16 * NPAIR, cnt + 16, 0, 1, 0, 5, 0};
        tgemm_k<1><<<dim3(40, 4, NEXP), 64>>>(a);
    }
    // mlp2: split-K=4, partials -> y4, consumer sums + bias
    {
        GArgs a = {hmid, MAXH, mlp_w2, (long)MAXH * D, D, mlp_b2, D, y4, D,
                   NPAIR, D, MAXH, rows + 16 * NPAIR, cnt + 16, 0, 0, 1, 0, (long)NPAIR * D};
        tgemm_k<4><<<dim3(32, 6, NEXP), 64>>>(a);
    }
    addy_k<<<NPAIR / 8, 256>>>(y4, mlpi, mlp_b2, y);

    // post: split-K=2, partials -> z[2], consumer sums + bias + LN + reduce
    {
        GArgs a = {y, D, post_w, (long)D * D, D, post_b, D, z, D,
                   NPAIR, D, D, rows + 32 * NPAIR, cnt + 32, 0, 0, 0, 0, (long)NPAIR * D};
        tgemm_k<2><<<dim3(16, 6, NEXP), 64>>>(a);
    }

    final_k<<<T, 256>>>(z, posti, w, post_b, post_g, post_be, out);
}

// round 10
// speedup vs baseline: 1.7114x; 1.0157x over previous
#include <cuda_runtime.h>
#include <math.h>
#include <stdint.h>

#define D      512
#define T      256
#define TOPK   8
#define NPAIR  2048
#define NEXP   16
#define MAXH   2560
#define NSCORE 4096

// ---------------- scratch ----------------------------------------------------
__device__ float g_h1[T * D];
__device__ float g_h2[T * 256];
__device__ float g_scores[2 * T * NSCORE];   // 2 split-K partials (fc3)
__device__ float g_preu[2 * NPAIR * D];      // 2 split-K partials
__device__ float g_xin[NPAIR * D];
__device__ float g_hmid[NPAIR * MAXH];
__device__ float g_y4[4 * NPAIR * D];        // 4 split-K partials (mlp2)
__device__ float g_y[NPAIR * D];
__device__ float g_z[2 * NPAIR * D];         // 2 split-K partials (post)
__device__ float g_w[NPAIR];
__device__ int   g_prei[NPAIR];
__device__ int   g_mlpi[NPAIR];
__device__ int   g_posti[NPAIR];
__device__ int   g_cnt[48];
__device__ int   g_rows[48 * NPAIR];

// ---------------- helpers ----------------------------------------------------
__device__ __forceinline__ float actf(int a, float v) {
    switch (a) {
        case 0: return 0.5f * v * (1.0f + erff(v * 0.7071067811865476f));
        case 1: return fmaxf(v, 0.0f);
        case 2: return tanhf(v);
        default: return v / (1.0f + expf(-v));
    }
}

__device__ __forceinline__ unsigned f2tf32(float f) {
    unsigned r;
    asm("cvt.rna.tf32.f32 %0, %1;" : "=r"(r) : "f"(f));
    return r;
}

__device__ __forceinline__ uint32_t sptr(const void* p) {
    return (uint32_t)__cvta_generic_to_shared(p);
}

__device__ __forceinline__ void cpa16(uint32_t d, const float* s, bool pred) {
    int sz = pred ? 16 : 0;
    asm volatile("cp.async.cg.shared.global [%0], [%1], 16, %2;"
                 :: "r"(d), "l"(s), "r"(sz));
}

__device__ __forceinline__ float wsum(float v) {
#pragma unroll
    for (int o = 16; o; o >>= 1) v += __shfl_xor_sync(0xffffffffu, v, o);
    return v;
}
__device__ __forceinline__ float wmax(float v) {
#pragma unroll
    for (int o = 16; o; o >>= 1) v = fmaxf(v, __shfl_xor_sync(0xffffffffu, v, o));
    return v;
}

#define MMA_TF32(c, a0, a1, a2, a3, b0, b1)                                      \
    asm volatile("mma.sync.aligned.m16n8k8.row.col.f32.tf32.tf32.f32 "           \
                 "{%0,%1,%2,%3}, {%4,%5,%6,%7}, {%8,%9}, {%0,%1,%2,%3};"         \
                 : "+f"((c)[0]), "+f"((c)[1]), "+f"((c)[2]), "+f"((c)[3])        \
                 : "r"(a0), "r"(a1), "r"(a2), "r"(a3), "r"(b0), "r"(b1))

struct GArgs {
    const float* A; int lda;
    const float* B; long bStride; int ldb;
    const float* bias; int biasStride;
    float* C; int ldc;
    int M, N, K;
    const int* rows; const int* cnt;
    int gshift;
    int varN, varK;
    int act;            // 0 none, 1..4 fixed (act-1), 5 per-expert e&3
    long cStride;       // split-K partial-buffer stride (elements); 0 = no split
    int* zcnt;          // if non-null: block (0,0,0) zeroes 48 counters
};

// ---------------- tf32 grouped GEMM (experts), split-K capable ---------------
// BM=32, BN=64; 64 threads = 2 warps; warp tile 32x32; S-stage cp.async.
// SPLIT>1: each x-slice computes a K-range into C + slice*cStride (no bias/act).
template<int SPLIT, int S>
__global__ __launch_bounds__(64) void tgemm_k(GArgs g) {
    constexpr int BM  = 32;
    constexpr int BN  = 64;
    constexpr int MI  = 2;
    constexpr int NI  = 4;
    constexpr int BNP = BN + 8;

    const int e  = blockIdx.z;
    const int Me = g.cnt[e];
    if (Me == 0) return;
    const int he = 512 * (2 + (e >> 2));
    const int Ne = g.varN ? he : g.N;
    const int Ke = g.varK ? he : g.K;

    const int ntiles = gridDim.x / SPLIT;
    const int slice  = blockIdx.x / ntiles;
    const int n0     = (blockIdx.x % ntiles) * BN;
    if (n0 >= Ne) return;

    const int Ksl   = Ke / SPLIT;
    const int kbase = slice * Ksl;
    const int KT    = Ksl >> 4;

    float* Cp = g.C + (long)slice * g.cStride;

    const float* Bp = g.B + (long)e * g.bStride;
    const int*   rl = g.rows + e * NPAIR;

    __shared__ float As[S][BM][20];
    __shared__ float Bs[S][16][BNP];

    const int tid = threadIdx.x, lane = tid & 31;
    const int wn = tid >> 5;
    const int grp = lane >> 2, t4 = lane & 3;
    const int a_row = tid >> 1;
    const int aq    = (tid & 1) * 2;

    const int aAct = (g.act == 5) ? (e & 3) : (g.act - 1);

    for (int m0 = blockIdx.y * BM; m0 < Me; m0 += gridDim.y * BM) {
        const bool mv = (m0 + a_row) < Me;
        long arow = 0;
        if (mv) arow = (long)(rl[m0 + a_row] >> g.gshift);
        const float* Ap = g.A + arow * (long)g.lda + kbase;

        int crow[MI * 2];
#pragma unroll
        for (int mi = 0; mi < MI; mi++)
#pragma unroll
            for (int h = 0; h < 2; h++) {
                int m = m0 + mi * 16 + grp + h * 8;
                crow[mi * 2 + h] = (m < Me) ? rl[m] : -1;
            }

        float acc[MI][NI][4];
#pragma unroll
        for (int mi = 0; mi < MI; mi++)
#pragma unroll
            for (int ni = 0; ni < NI; ni++)
#pragma unroll
                for (int c = 0; c < 4; c++) acc[mi][ni][c] = 0.0f;

        auto loadStage = [&](int s, int kt) {
            int k0 = kt << 4;
#pragma unroll
            for (int i = 0; i < 2; i++)
                cpa16(sptr(&As[s][a_row][(aq + i) * 4]), Ap + k0 + (aq + i) * 4, mv);
#pragma unroll
            for (int i = 0; i < 4; i++) {
                int idx = tid + i * 64;
                int r = idx >> 4, col = (idx & 15) * 4;
                cpa16(sptr(&Bs[s][r][col]),
                      Bp + (long)(kbase + k0 + r) * g.ldb + n0 + col, true);
            }
            asm volatile("cp.async.commit_group;");
        };

#pragma unroll
        for (int s = 0; s < S - 1; s++) {
            if (s < KT) loadStage(s, s);
            else        asm volatile("cp.async.commit_group;");
        }

        for (int kt = 0; kt < KT; kt++) {
            asm volatile("cp.async.wait_group %0;" :: "n"(S - 2));
            __syncthreads();
            const int buf = kt % S;

            if (kt + S - 1 < KT) loadStage((kt + S - 1) % S, kt + S - 1);
            else                 asm volatile("cp.async.commit_group;");

#pragma unroll
            for (int ks = 0; ks < 2; ks++) {
                const int kk = ks * 8;
                unsigned a[MI][4], b[NI][2];
#pragma unroll
                for (int mi = 0; mi < MI; mi++) {
                    int mr = mi * 16 + grp;
                    a[mi][0] = f2tf32(As[buf][mr][kk + t4]);
                    a[mi][1] = f2tf32(As[buf][mr + 8][kk + t4]);
                    a[mi][2] = f2tf32(As[buf][mr][kk + t4 + 4]);
                    a[mi][3] = f2tf32(As[buf][mr + 8][kk + t4 + 4]);
                }
#pragma unroll
                for (int ni = 0; ni < NI; ni++) {
                    int nc = wn * 32 + ni * 8 + grp;
                    b[ni][0] = f2tf32(Bs[buf][kk + t4][nc]);
                    b[ni][1] = f2tf32(Bs[buf][kk + t4 + 4][nc]);
                }
#pragma unroll
                for (int mi = 0; mi < MI; mi++)
#pragma unroll
                    for (int ni = 0; ni < NI; ni++)
                        MMA_TF32(acc[mi][ni], a[mi][0], a[mi][1], a[mi][2], a[mi][3],
                                 b[ni][0], b[ni][1]);
            }
        }

#pragma unroll
        for (int ni = 0; ni < NI; ni++) {
            int c = n0 + wn * 32 + ni * 8 + t4 * 2;
            float b0 = 0.0f, b1 = 0.0f;
            if (SPLIT == 1) {
                const float* bias = g.bias + (long)e * g.biasStride;
                b0 = bias[c]; b1 = bias[c + 1];
            }
#pragma unroll
            for (int mi = 0; mi < MI; mi++)
#pragma unroll
                for (int h = 0; h < 2; h++) {
                    int cr = crow[mi * 2 + h];
                    if (cr >= 0) {
                        float v0 = acc[mi][ni][h * 2 + 0] + b0;
                        float v1 = acc[mi][ni][h * 2 + 1] + b1;
                        if (SPLIT == 1 && aAct >= 0) { v0 = actf(aAct, v0); v1 = actf(aAct, v1); }
                        *(float2*)(Cp + (long)cr * g.ldc + c) = make_float2(v0, v1);
                    }
                }
        }
        asm volatile("cp.async.wait_group 0;");
        __syncthreads();
    }
}

// ---------------- router GEMM: split-tf32 (hi/lo), optional split-K ----------
__global__ __launch_bounds__(256) void rgemm_k(GArgs g) {
    const int n0 = blockIdx.x * 64;
    const int m0 = blockIdx.y * 128;
    if (n0 >= g.N) return;
    const int slice = blockIdx.z;

    if (g.zcnt && blockIdx.x == 0 && blockIdx.y == 0 && slice == 0 && threadIdx.x < 48)
        g.zcnt[threadIdx.x] = 0;

    __shared__ unsigned AsH[128][20], AsL[128][20];
    __shared__ unsigned BsH[16][72], BsL[16][72];

    const int tid = threadIdx.x, warp = tid >> 5, lane = tid & 31;
    const int grp = lane >> 2, t4 = lane & 3;
    const int wm = warp >> 1, wn = warp & 1;
    const int a_row = tid >> 1;
    const int aq = (tid & 1) * 2;
    const int bk = tid >> 4, cb = (tid & 15) * 4;

    const bool mv = (m0 + a_row) < g.M;
    const float* Ap = g.A + (long)(m0 + a_row) * g.lda + (long)slice * g.K;
    const float* Bp = g.B + (long)slice * g.K * g.ldb;
    float* Cp = g.C + (long)slice * g.cStride;
    const bool full = (g.cStride == 0);

    float acc[2][4][4];
#pragma unroll
    for (int mi = 0; mi < 2; mi++)
#pragma unroll
        for (int ni = 0; ni < 4; ni++)
#pragma unroll
            for (int c = 0; c < 4; c++) acc[mi][ni][c] = 0.0f;

    float4 av[2], bv;
    auto ldreg = [&](int k0) {
#pragma unroll
        for (int i = 0; i < 2; i++)
            av[i] = mv ? *(const float4*)(Ap + k0 + (aq + i) * 4)
                       : make_float4(0.f, 0.f, 0.f, 0.f);
        bv = *(const float4*)(Bp + (long)(k0 + bk) * g.ldb + n0 + cb);
    };

    const int KT = g.K >> 4;
    ldreg(0);
    for (int kt = 0; kt < KT; kt++) {
        __syncthreads();
#pragma unroll
        for (int i = 0; i < 2; i++) {
            float vv[4] = {av[i].x, av[i].y, av[i].z, av[i].w};
            uint4 uh, ul;
            unsigned* ph = &uh.x; unsigned* pl = &ul.x;
#pragma unroll
            for (int c = 0; c < 4; c++) {
                unsigned hb = f2tf32(vv[c]);
                ph[c] = hb;
                pl[c] = f2tf32(vv[c] - __uint_as_float(hb));
            }
            *(uint4*)&AsH[a_row][(aq + i) * 4] = uh;
            *(uint4*)&AsL[a_row][(aq + i) * 4] = ul;
        }
        {
            float vv[4] = {bv.x, bv.y, bv.z, bv.w};
            uint4 uh, ul;
            unsigned* ph = &uh.x; unsigned* pl = &ul.x;
#pragma unroll
            for (int c = 0; c < 4; c++) {
                unsigned hb = f2tf32(vv[c]);
                ph[c] = hb;
                pl[c] = f2tf32(vv[c] - __uint_as_float(hb));
            }
            *(uint4*)&BsH[bk][cb] = uh;
            *(uint4*)&BsL[bk][cb] = ul;
        }
        __syncthreads();

        if (kt + 1 < KT) ldreg((kt + 1) << 4);

#pragma unroll
        for (int ks = 0; ks < 2; ks++) {
            const int kk = ks * 8;
            unsigned ah[2][4], al[2][4], bh[4][2], bl[4][2];
#pragma unroll
            for (int mi = 0; mi < 2; mi++) {
                int mr = wm * 32 + mi * 16 + grp;
                ah[mi][0] = AsH[mr][kk + t4];     al[mi][0] = AsL[mr][kk + t4];
                ah[mi][1] = AsH[mr + 8][kk + t4]; al[mi][1] = AsL[mr + 8][kk + t4];
                ah[mi][2] = AsH[mr][kk + t4 + 4]; al[mi][2] = AsL[mr][kk + t4 + 4];
                ah[mi][3] = AsH[mr + 8][kk + t4 + 4]; al[mi][3] = AsL[mr + 8][kk + t4 + 4];
            }
#pragma unroll
            for (int ni = 0; ni < 4; ni++) {
                int nc = wn * 32 + ni * 8 + grp;
                bh[ni][0] = BsH[kk + t4][nc];     bl[ni][0] = BsL[kk + t4][nc];
                bh[ni][1] = BsH[kk + t4 + 4][nc]; bl[ni][1] = BsL[kk + t4 + 4][nc];
            }
#pragma unroll
            for (int mi = 0; mi < 2; mi++)
#pragma unroll
                for (int ni = 0; ni < 4; ni++) {
                    MMA_TF32(acc[mi][ni], ah[mi][0], ah[mi][1], ah[mi][2], ah[mi][3],
                             bh[ni][0], bh[ni][1]);
                    MMA_TF32(acc[mi][ni], ah[mi][0], ah[mi][1], ah[mi][2], ah[mi][3],
                             bl[ni][0], bl[ni][1]);
                    MMA_TF32(acc[mi][ni], al[mi][0], al[mi][1], al[mi][2], al[mi][3],
                             bh[ni][0], bh[ni][1]);
                }
        }
    }

    const int aAct = g.act - 1;
#pragma unroll
    for (int ni = 0; ni < 4; ni++) {
        int c = n0 + wn * 32 + ni * 8 + t4 * 2;
        float b0 = 0.0f, b1 = 0.0f;
        if (full) { b0 = g.bias[c]; b1 = g.bias[c + 1]; }
#pragma unroll
        for (int mi = 0; mi < 2; mi++)
#pragma unroll
            for (int h = 0; h < 2; h++) {
                int m = m0 + wm * 32 + mi * 16 + grp + h * 8;
                if (m < g.M) {
                    float v0 = acc[mi][ni][h * 2 + 0] + b0;
                    float v1 = acc[mi][ni][h * 2 + 1] + b1;
                    if (full && aAct >= 0) { v0 = actf(aAct, v0); v1 = actf(aAct, v1); }
                    *(float2*)(Cp + (long)m * g.ldc + c) = make_float2(v0, v1);
                }
            }
    }
}

// ---------------- softmax + top-k + routing (sums 2 fc3 partials + bias) -----
__global__ __launch_bounds__(256) void route_k(const float* scores, const float* sbias,
                                               const float* temp,
                                               float* w, int* prei, int* mlpi, int* posti,
                                               int* cnt, int* rows) {
    const int t = blockIdx.x, tid = threadIdx.x;
    const int wid = tid >> 5, lane = tid & 31;
    __shared__ float sm[NSCORE];
    __shared__ float ws1[8], ws2[8];
    __shared__ float wv[8];
    __shared__ int   wi[8];

    const float invT = 1.0f / temp[0];
    const long TN = (long)T * NSCORE;
    for (int j = tid; j < NSCORE; j += 256) {
        long off = (long)t * NSCORE + j;
        sm[j] = (scores[off] + scores[TN + off] + sbias[j]) * invT;
    }
    __syncthreads();

    float mx = -3.4e38f;
    for (int j = tid; j < NSCORE; j += 256) mx = fmaxf(mx, sm[j]);
    mx = wmax(mx);
    if (lane == 0) ws1[wid] = mx;
    __syncthreads();
    float gmax = ws1[0];
#pragma unroll
    for (int i = 1; i < 8; i++) gmax = fmaxf(gmax, ws1[i]);

    float sum = 0.0f;
    for (int j = tid; j < NSCORE; j += 256) sum += expf(sm[j] - gmax);
    sum = wsum(sum);
    if (lane == 0) ws2[wid] = sum;
    __syncthreads();
    float gsum = 0.0f;
#pragma unroll
    for (int i = 0; i < 8; i++) gsum += ws2[i];

    for (int k = 0; k < TOPK; k++) {
        float bv = -3.4e38f; int bi = NSCORE;
        for (int j = tid; j < NSCORE; j += 256) {
            float v = sm[j];
            if (v > bv || (v == bv && j < bi)) { bv = v; bi = j; }
        }
#pragma unroll
        for (int o = 16; o; o >>= 1) {
            float ov = __shfl_xor_sync(0xffffffffu, bv, o);
            int oi = __shfl_xor_sync(0xffffffffu, bi, o);
            if (ov > bv || (ov == bv && oi < bi)) { bv = ov; bi = oi; }
        }
        if (lane == 0) { wv[wid] = bv; wi[wid] = bi; }
        __syncthreads();
        if (tid == 0) {
            float fv = wv[0]; int fi = wi[0];
#pragma unroll
            for (int i = 1; i < 8; i++) {
                if (wv[i] > fv || (wv[i] == fv && wi[i] < fi)) { fv = wv[i]; fi = wi[i]; }
            }
            float prob = expf(fv - gmax) / gsum;
            float ww = (prob >= 1e-6f) ? prob : 0.0f;
            int pair = t * TOPK + k;
            int pe = fi >> 8, rem = fi & 255, me = rem >> 4, oe = rem & 15;
            prei[pair] = pe; mlpi[pair] = me; posti[pair] = oe; w[pair] = ww;
            int s0 = atomicAdd(&cnt[pe], 1);       rows[pe * NPAIR + s0] = pair;
            int s1 = atomicAdd(&cnt[16 + me], 1);  rows[(16 + me) * NPAIR + s1] = pair;
            int s2 = atomicAdd(&cnt[32 + oe], 1);  rows[(32 + oe) * NPAIR + s2] = pair;
            sm[fi] = -3.4e38f;
        }
        __syncthreads();
    }
}

// ---------------- pre: sum 2 partials + bias + LN + act ----------------------
__global__ __launch_bounds__(256) void prelnact_k(const float* U, const int* prei,
                                                  const float* pbias,
                                                  const float* g, const float* b, float* X) {
    const int warp = threadIdx.x >> 5, lane = threadIdx.x & 31;
    const int p = blockIdx.x * 8 + warp;
    const int e = prei[p];
    float u[16];
#pragma unroll
    for (int j = 0; j < 16; j++) {
        int idx = lane + 32 * j;
        u[j] = U[p * D + idx] + U[(long)NPAIR * D + p * D + idx] + pbias[e * D + idx];
    }

    float s = 0.0f;
#pragma unroll
    for (int j = 0; j < 16; j++) s += u[j];
    const float mean = wsum(s) * (1.0f / D);

    float v = 0.0f;
#pragma unroll
    for (int j = 0; j < 16; j++) { float d = u[j] - mean; v += d * d; }
    const float rstd = rsqrtf(wsum(v) * (1.0f / D) + 1e-5f);

    const int a = e & 3;
#pragma unroll
    for (int j = 0; j < 16; j++) {
        int idx = lane + 32 * j;
        float val = (u[j] - mean) * rstd * g[e * D + idx] + b[e * D + idx];
        X[p * D + idx] = actf(a, val);
    }
}

// ---------------- mlp2: sum 4 partials + bias --------------------------------
__global__ __launch_bounds__(256) void addy_k(const float* Y4, const int* mlpi,
                                              const float* b2, float* y) {
    const int warp = threadIdx.x >> 5, lane = threadIdx.x & 31;
    const int p = blockIdx.x * 8 + warp;
    const int e = mlpi[p];
#pragma unroll
    for (int j = 0; j < 16; j++) {
        int idx = lane + 32 * j;
        long off = (long)p * D + idx;
        float s = Y4[off] + Y4[(long)NPAIR * D + off]
                + Y4[2L * NPAIR * D + off] + Y4[3L * NPAIR * D + off]
                + b2[e * D + idx];
        y[off] = s;
    }
}

// ---------------- post: sum 2 partials + bias + LN + weighted reduce ---------
__global__ __launch_bounds__(256) void final_k(const float* Z, const int* posti, const float* w,
                                               const float* pbias,
                                               const float* g, const float* b, float* out) {
    const int t = blockIdx.x, tid = threadIdx.x;
    const int warp = tid >> 5, lane = tid & 31;
    __shared__ float sacc[8][D];

    const int pair = t * TOPK + warp;
    const int e = posti[pair];
    const float ww = w[pair];
    float z[16];
#pragma unroll
    for (int j = 0; j < 16; j++) {
        int idx = lane + 32 * j;
        z[j] = Z[(long)pair * D + idx] + Z[(long)NPAIR * D + (long)pair * D + idx]
             + pbias[e * D + idx];
    }

    if ((e & 1) == 0) {
        float s = 0.0f;
#pragma unroll
        for (int j = 0; j < 16; j++) s += z[j];
        const float mean = wsum(s) * (1.0f / D);
        float v = 0.0f;
#pragma unroll
        for (int j = 0; j < 16; j++) { float d = z[j] - mean; v += d * d; }
        const float rstd = rsqrtf(wsum(v) * (1.0f / D) + 1e-5f);
#pragma unroll
        for (int j = 0; j < 16; j++) {
            int idx = lane + 32 * j;
            z[j] = (z[j] - mean) * rstd * g[e * D + idx] + b[e * D + idx];
        }
    }
#pragma unroll
    for (int j = 0; j < 16; j++) sacc[warp][lane + 32 * j] = ww * z[j];
    __syncthreads();

    for (int i = tid; i < D; i += 256) {
        float s = 0.0f;
#pragma unroll
        for (int k = 0; k < 8; k++) s += sacc[k][i];
        out[t * D + i] = s;
    }
}

// ---------------- launch -----------------------------------------------------
extern "C" void kernel_launch(void* const* d_in, const int* in_sizes, int n_in,
                              void* d_out, int out_size) {
    const float* x       = (const float*)d_in[0];
    const float* r_w1    = (const float*)d_in[1];
    const float* r_b1    = (const float*)d_in[2];
    const float* r_w2    = (const float*)d_in[3];
    const float* r_b2    = (const float*)d_in[4];
    const float* r_w3    = (const float*)d_in[5];
    const float* r_b3    = (const float*)d_in[6];
    const float* temp    = (const float*)d_in[7];
    const float* pre_w   = (const float*)d_in[8];
    const float* pre_b   = (const float*)d_in[9];
    const float* pre_g   = (const float*)d_in[10];
    const float* pre_be  = (const float*)d_in[11];
    const float* mlp_w1  = (const float*)d_in[12];
    const float* mlp_b1  = (const float*)d_in[13];
    const float* mlp_w2  = (const float*)d_in[14];
    const float* mlp_b2  = (const float*)d_in[15];
    const float* post_w  = (const float*)d_in[16];
    const float* post_b  = (const float*)d_in[17];
    const float* post_g  = (const float*)d_in[18];
    const float* post_be = (const float*)d_in[19];
    float* out = (float*)d_out;

    float *h1, *h2, *sc, *preu, *xin, *hmid, *y4, *y, *z, *w;
    int *prei, *mlpi, *posti, *cnt, *rows;
    cudaGetSymbolAddress((void**)&h1, g_h1);
    cudaGetSymbolAddress((void**)&h2, g_h2);
    cudaGetSymbolAddress((void**)&sc, g_scores);
    cudaGetSymbolAddress((void**)&preu, g_preu);
    cudaGetSymbolAddress((void**)&xin, g_xin);
    cudaGetSymbolAddress((void**)&hmid, g_hmid);
    cudaGetSymbolAddress((void**)&y4, g_y4);
    cudaGetSymbolAddress((void**)&y, g_y);
    cudaGetSymbolAddress((void**)&z, g_z);
    cudaGetSymbolAddress((void**)&w, g_w);
    cudaGetSymbolAddress((void**)&prei, g_prei);
    cudaGetSymbolAddress((void**)&mlpi, g_mlpi);
    cudaGetSymbolAddress((void**)&posti, g_posti);
    cudaGetSymbolAddress((void**)&cnt, g_cnt);
    cudaGetSymbolAddress((void**)&rows, g_rows);

    // router fc1 (also zeroes routing counters in block 0)
    {
        GArgs a = {x, D, r_w1, 0, 512, r_b1, 0, h1, 512,
                   T, 512, 512, nullptr, nullptr, 0, 0, 0, 1, 0, cnt};
        rgemm_k<<<dim3(8, 2, 1), 256>>>(a);
    }
    {
        GArgs a = {h1, 512, r_w2, 0, 256, r_b2, 0, h2, 256,
                   T, 256, 512, nullptr, nullptr, 0, 0, 0, 1, 0, nullptr};
        rgemm_k<<<dim3(4, 2, 1), 256>>>(a);
    }
    // fc3: split-K=2 (grid z), partials summed (with bias) inside route_k
    {
        GArgs a = {h2, 256, r_w3, 0, NSCORE, r_b3, 0, sc, NSCORE,
                   T, NSCORE, 128, nullptr, nullptr, 0, 0, 0, 0,
                   (long)T * NSCORE, nullptr};
        rgemm_k<<<dim3(64, 2, 2), 256>>>(a);
    }

    route_k<<<T, 256>>>(sc, r_b3, temp, w, prei, mlpi, posti, cnt, rows);

    // pre: split-K=2, S=4
    {
        GArgs a = {x, D, pre_w, (long)D * D, D, pre_b, D, preu, D,
                   NPAIR, D, D, rows, cnt, 3, 0, 0, 0, (long)NPAIR * D, nullptr};
        tgemm_k<2, 4><<<dim3(16, 6, NEXP), 64>>>(a);
    }
    prelnact_k<<<NPAIR / 8, 256>>>(preu, prei, pre_b, pre_g, pre_be, xin);

    // mlp1: fused bias+act, S=3 (lower smem -> more blocks/SM)
    {
        GArgs a = {xin, D, mlp_w1, (long)D * MAXH, MAXH, mlp_b1, MAXH, hmid, MAXH,
                   NPAIR, MAXH, D, rows + 16 * NPAIR, cnt + 16, 0, 1, 0, 5, 0, nullptr};
        tgemm_k<1, 3><<<dim3(40, 6, NEXP), 64>>>(a);
    }
    // mlp2: split-K=4, S=3
    {
        GArgs a = {hmid, MAXH, mlp_w2, (long)MAXH * D, D, mlp_b2, D, y4, D,
                   NPAIR, D, MAXH, rows + 16 * NPAIR, cnt + 16, 0, 0, 1, 0,
                   (long)NPAIR * D, nullptr};
        tgemm_k<4, 3><<<dim3(32, 6, NEXP), 64>>>(a);
    }
    addy_k<<<NPAIR / 8, 256>>>(y4, mlpi, mlp_b2, y);

    // post: split-K=2, S=4
    {
        GArgs a = {y, D, post_w, (long)D * D, D, post_b, D, z, D,
                   NPAIR, D, D, rows + 32 * NPAIR, cnt + 32, 0, 0, 0, 0,
                   (long)NPAIR * D, nullptr};
        tgemm_k<2, 4><<<dim3(16, 6, NEXP), 64>>>(a);
    }

    final_k<<<T, 256>>>(z, posti, w, post_b, post_g, post_be, out);
}

// round 11
// speedup vs baseline: 1.8052x; 1.0548x over previous
#include <cuda_runtime.h>
#include <math.h>
#include <stdint.h>

#define D      512
#define T      256
#define TOPK   8
#define NPAIR  2048
#define NEXP   16
#define MAXH   2560
#define NSCORE 4096

// ---------------- scratch ----------------------------------------------------
__device__ float g_h1[T * D];
__device__ float g_h2[T * 256];
__device__ float g_scores[2 * T * NSCORE];   // 2 split-K partials (fc3)
__device__ float g_preu[2 * NPAIR * D];      // 2 split-K partials
__device__ float g_xin[NPAIR * D];
__device__ float g_hmid[NPAIR * MAXH];
__device__ float g_y4[4 * NPAIR * D];        // 4 split-K partials (mlp2)
__device__ float g_y[NPAIR * D];
__device__ float g_z[2 * NPAIR * D];         // 2 split-K partials (post)
__device__ float g_w[NPAIR];
__device__ int   g_prei[NPAIR];
__device__ int   g_mlpi[NPAIR];
__device__ int   g_posti[NPAIR];
__device__ int   g_cnt[48];
__device__ int   g_rows[48 * NPAIR];

// ---------------- helpers ----------------------------------------------------
__device__ __forceinline__ float actf(int a, float v) {
    switch (a) {
        case 0: return 0.5f * v * (1.0f + erff(v * 0.7071067811865476f));
        case 1: return fmaxf(v, 0.0f);
        case 2: return tanhf(v);
        default: return v / (1.0f + expf(-v));
    }
}

__device__ __forceinline__ unsigned f2tf32(float f) {
    unsigned r;
    asm("cvt.rna.tf32.f32 %0, %1;" : "=r"(r) : "f"(f));
    return r;
}

__device__ __forceinline__ uint32_t sptr(const void* p) {
    return (uint32_t)__cvta_generic_to_shared(p);
}

__device__ __forceinline__ void cpa16(uint32_t d, const float* s, bool pred) {
    int sz = pred ? 16 : 0;
    asm volatile("cp.async.cg.shared.global [%0], [%1], 16, %2;"
                 :: "r"(d), "l"(s), "r"(sz));
}

__device__ __forceinline__ float wsum(float v) {
#pragma unroll
    for (int o = 16; o; o >>= 1) v += __shfl_xor_sync(0xffffffffu, v, o);
    return v;
}
__device__ __forceinline__ float wmax(float v) {
#pragma unroll
    for (int o = 16; o; o >>= 1) v = fmaxf(v, __shfl_xor_sync(0xffffffffu, v, o));
    return v;
}

#define MMA_TF32(c, a0, a1, a2, a3, b0, b1)                                      \
    asm volatile("mma.sync.aligned.m16n8k8.row.col.f32.tf32.tf32.f32 "           \
                 "{%0,%1,%2,%3}, {%4,%5,%6,%7}, {%8,%9}, {%0,%1,%2,%3};"         \
                 : "+f"((c)[0]), "+f"((c)[1]), "+f"((c)[2]), "+f"((c)[3])        \
                 : "r"(a0), "r"(a1), "r"(a2), "r"(a3), "r"(b0), "r"(b1))

struct GArgs {
    const float* A; int lda;
    const float* B; long bStride; int ldb;
    const float* bias; int biasStride;
    float* C; int ldc;
    int M, N, K;
    const int* rows; const int* cnt;
    int gshift;
    int varN, varK;
    int act;            // 0 none, 1..4 fixed (act-1), 5 per-expert e&3
    long cStride;       // split-K partial-buffer stride (elements); 0 = no split
    int* zcnt;          // if non-null: block (0,0,0) zeroes 48 counters
};

// ---------------- tf32 grouped GEMM (experts), split-K capable ---------------
template<int SPLIT, int S>
__global__ __launch_bounds__(64) void tgemm_k(GArgs g) {
    constexpr int BM  = 32;
    constexpr int BN  = 64;
    constexpr int MI  = 2;
    constexpr int NI  = 4;
    constexpr int BNP = BN + 8;

    const int e  = blockIdx.z;
    const int Me = g.cnt[e];
    if (Me == 0) return;
    const int he = 512 * (2 + (e >> 2));
    const int Ne = g.varN ? he : g.N;
    const int Ke = g.varK ? he : g.K;

    const int ntiles = gridDim.x / SPLIT;
    const int slice  = blockIdx.x / ntiles;
    const int n0     = (blockIdx.x % ntiles) * BN;
    if (n0 >= Ne) return;

    const int Ksl   = Ke / SPLIT;
    const int kbase = slice * Ksl;
    const int KT    = Ksl >> 4;

    float* Cp = g.C + (long)slice * g.cStride;

    const float* Bp = g.B + (long)e * g.bStride;
    const int*   rl = g.rows + e * NPAIR;

    __shared__ float As[S][BM][20];
    __shared__ float Bs[S][16][BNP];

    const int tid = threadIdx.x, lane = tid & 31;
    const int wn = tid >> 5;
    const int grp = lane >> 2, t4 = lane & 3;
    const int a_row = tid >> 1;
    const int aq    = (tid & 1) * 2;

    const int aAct = (g.act == 5) ? (e & 3) : (g.act - 1);

    for (int m0 = blockIdx.y * BM; m0 < Me; m0 += gridDim.y * BM) {
        const bool mv = (m0 + a_row) < Me;
        long arow = 0;
        if (mv) arow = (long)(rl[m0 + a_row] >> g.gshift);
        const float* Ap = g.A + arow * (long)g.lda + kbase;

        int crow[MI * 2];
#pragma unroll
        for (int mi = 0; mi < MI; mi++)
#pragma unroll
            for (int h = 0; h < 2; h++) {
                int m = m0 + mi * 16 + grp + h * 8;
                crow[mi * 2 + h] = (m < Me) ? rl[m] : -1;
            }

        float acc[MI][NI][4];
#pragma unroll
        for (int mi = 0; mi < MI; mi++)
#pragma unroll
            for (int ni = 0; ni < NI; ni++)
#pragma unroll
                for (int c = 0; c < 4; c++) acc[mi][ni][c] = 0.0f;

        auto loadStage = [&](int s, int kt) {
            int k0 = kt << 4;
#pragma unroll
            for (int i = 0; i < 2; i++)
                cpa16(sptr(&As[s][a_row][(aq + i) * 4]), Ap + k0 + (aq + i) * 4, mv);
#pragma unroll
            for (int i = 0; i < 4; i++) {
                int idx = tid + i * 64;
                int r = idx >> 4, col = (idx & 15) * 4;
                cpa16(sptr(&Bs[s][r][col]),
                      Bp + (long)(kbase + k0 + r) * g.ldb + n0 + col, true);
            }
            asm volatile("cp.async.commit_group;");
        };

#pragma unroll
        for (int s = 0; s < S - 1; s++) {
            if (s < KT) loadStage(s, s);
            else        asm volatile("cp.async.commit_group;");
        }

        for (int kt = 0; kt < KT; kt++) {
            asm volatile("cp.async.wait_group %0;" :: "n"(S - 2));
            __syncthreads();
            const int buf = kt % S;

            if (kt + S - 1 < KT) loadStage((kt + S - 1) % S, kt + S - 1);
            else                 asm volatile("cp.async.commit_group;");

#pragma unroll
            for (int ks = 0; ks < 2; ks++) {
                const int kk = ks * 8;
                unsigned a[MI][4], b[NI][2];
#pragma unroll
                for (int mi = 0; mi < MI; mi++) {
                    int mr = mi * 16 + grp;
                    a[mi][0] = f2tf32(As[buf][mr][kk + t4]);
                    a[mi][1] = f2tf32(As[buf][mr + 8][kk + t4]);
                    a[mi][2] = f2tf32(As[buf][mr][kk + t4 + 4]);
                    a[mi][3] = f2tf32(As[buf][mr + 8][kk + t4 + 4]);
                }
#pragma unroll
                for (int ni = 0; ni < NI; ni++) {
                    int nc = wn * 32 + ni * 8 + grp;
                    b[ni][0] = f2tf32(Bs[buf][kk + t4][nc]);
                    b[ni][1] = f2tf32(Bs[buf][kk + t4 + 4][nc]);
                }
#pragma unroll
                for (int mi = 0; mi < MI; mi++)
#pragma unroll
                    for (int ni = 0; ni < NI; ni++)
                        MMA_TF32(acc[mi][ni], a[mi][0], a[mi][1], a[mi][2], a[mi][3],
                                 b[ni][0], b[ni][1]);
            }
        }

#pragma unroll
        for (int ni = 0; ni < NI; ni++) {
            int c = n0 + wn * 32 + ni * 8 + t4 * 2;
            float b0 = 0.0f, b1 = 0.0f;
            if (SPLIT == 1) {
                const float* bias = g.bias + (long)e * g.biasStride;
                b0 = bias[c]; b1 = bias[c + 1];
            }
#pragma unroll
            for (int mi = 0; mi < MI; mi++)
#pragma unroll
                for (int h = 0; h < 2; h++) {
                    int cr = crow[mi * 2 + h];
                    if (cr >= 0) {
                        float v0 = acc[mi][ni][h * 2 + 0] + b0;
                        float v1 = acc[mi][ni][h * 2 + 1] + b1;
                        if (SPLIT == 1 && aAct >= 0) { v0 = actf(aAct, v0); v1 = actf(aAct, v1); }
                        *(float2*)(Cp + (long)cr * g.ldc + c) = make_float2(v0, v1);
                    }
                }
        }
        asm volatile("cp.async.wait_group 0;");
        __syncthreads();
    }
}

// ---------------- router GEMM: split-tf32 (hi/lo), optional split-K ----------
__global__ __launch_bounds__(256) void rgemm_k(GArgs g) {
    const int n0 = blockIdx.x * 64;
    const int m0 = blockIdx.y * 128;
    if (n0 >= g.N) return;
    const int slice = blockIdx.z;

    if (g.zcnt && blockIdx.x == 0 && blockIdx.y == 0 && slice == 0 && threadIdx.x < 48)
        g.zcnt[threadIdx.x] = 0;

    __shared__ unsigned AsH[128][20], AsL[128][20];
    __shared__ unsigned BsH[16][72], BsL[16][72];

    const int tid = threadIdx.x, warp = tid >> 5, lane = tid & 31;
    const int grp = lane >> 2, t4 = lane & 3;
    const int wm = warp >> 1, wn = warp & 1;
    const int a_row = tid >> 1;
    const int aq = (tid & 1) * 2;
    const int bk = tid >> 4, cb = (tid & 15) * 4;

    const bool mv = (m0 + a_row) < g.M;
    const float* Ap = g.A + (long)(m0 + a_row) * g.lda + (long)slice * g.K;
    const float* Bp = g.B + (long)slice * g.K * g.ldb;
    float* Cp = g.C + (long)slice * g.cStride;
    const bool full = (g.cStride == 0);

    float acc[2][4][4];
#pragma unroll
    for (int mi = 0; mi < 2; mi++)
#pragma unroll
        for (int ni = 0; ni < 4; ni++)
#pragma unroll
            for (int c = 0; c < 4; c++) acc[mi][ni][c] = 0.0f;

    float4 av[2], bv;
    auto ldreg = [&](int k0) {
#pragma unroll
        for (int i = 0; i < 2; i++)
            av[i] = mv ? *(const float4*)(Ap + k0 + (aq + i) * 4)
                       : make_float4(0.f, 0.f, 0.f, 0.f);
        bv = *(const float4*)(Bp + (long)(k0 + bk) * g.ldb + n0 + cb);
    };

    const int KT = g.K >> 4;
    ldreg(0);
    for (int kt = 0; kt < KT; kt++) {
        __syncthreads();
#pragma unroll
        for (int i = 0; i < 2; i++) {
            float vv[4] = {av[i].x, av[i].y, av[i].z, av[i].w};
            uint4 uh, ul;
            unsigned* ph = &uh.x; unsigned* pl = &ul.x;
#pragma unroll
            for (int c = 0; c < 4; c++) {
                unsigned hb = f2tf32(vv[c]);
                ph[c] = hb;
                pl[c] = f2tf32(vv[c] - __uint_as_float(hb));
            }
            *(uint4*)&AsH[a_row][(aq + i) * 4] = uh;
            *(uint4*)&AsL[a_row][(aq + i) * 4] = ul;
        }
        {
            float vv[4] = {bv.x, bv.y, bv.z, bv.w};
            uint4 uh, ul;
            unsigned* ph = &uh.x; unsigned* pl = &ul.x;
#pragma unroll
            for (int c = 0; c < 4; c++) {
                unsigned hb = f2tf32(vv[c]);
                ph[c] = hb;
                pl[c] = f2tf32(vv[c] - __uint_as_float(hb));
            }
            *(uint4*)&BsH[bk][cb] = uh;
            *(uint4*)&BsL[bk][cb] = ul;
        }
        __syncthreads();

        if (kt + 1 < KT) ldreg((kt + 1) << 4);

#pragma unroll
        for (int ks = 0; ks < 2; ks++) {
            const int kk = ks * 8;
            unsigned ah[2][4], al[2][4], bh[4][2], bl[4][2];
#pragma unroll
            for (int mi = 0; mi < 2; mi++) {
                int mr = wm * 32 + mi * 16 + grp;
                ah[mi][0] = AsH[mr][kk + t4];     al[mi][0] = AsL[mr][kk + t4];
                ah[mi][1] = AsH[mr + 8][kk + t4]; al[mi][1] = AsL[mr + 8][kk + t4];
                ah[mi][2] = AsH[mr][kk + t4 + 4]; al[mi][2] = AsL[mr][kk + t4 + 4];
                ah[mi][3] = AsH[mr + 8][kk + t4 + 4]; al[mi][3] = AsL[mr + 8][kk + t4 + 4];
            }
#pragma unroll
            for (int ni = 0; ni < 4; ni++) {
                int nc = wn * 32 + ni * 8 + grp;
                bh[ni][0] = BsH[kk + t4][nc];     bl[ni][0] = BsL[kk + t4][nc];
                bh[ni][1] = BsH[kk + t4 + 4][nc]; bl[ni][1] = BsL[kk + t4 + 4][nc];
            }
#pragma unroll
            for (int mi = 0; mi < 2; mi++)
#pragma unroll
                for (int ni = 0; ni < 4; ni++) {
                    MMA_TF32(acc[mi][ni], ah[mi][0], ah[mi][1], ah[mi][2], ah[mi][3],
                             bh[ni][0], bh[ni][1]);
                    MMA_TF32(acc[mi][ni], ah[mi][0], ah[mi][1], ah[mi][2], ah[mi][3],
                             bl[ni][0], bl[ni][1]);
                    MMA_TF32(acc[mi][ni], al[mi][0], al[mi][1], al[mi][2], al[mi][3],
                             bh[ni][0], bh[ni][1]);
                }
        }
    }

    const int aAct = g.act - 1;
#pragma unroll
    for (int ni = 0; ni < 4; ni++) {
        int c = n0 + wn * 32 + ni * 8 + t4 * 2;
        float b0 = 0.0f, b1 = 0.0f;
        if (full) { b0 = g.bias[c]; b1 = g.bias[c + 1]; }
#pragma unroll
        for (int mi = 0; mi < 2; mi++)
#pragma unroll
            for (int h = 0; h < 2; h++) {
                int m = m0 + wm * 32 + mi * 16 + grp + h * 8;
                if (m < g.M) {
                    float v0 = acc[mi][ni][h * 2 + 0] + b0;
                    float v1 = acc[mi][ni][h * 2 + 1] + b1;
                    if (full && aAct >= 0) { v0 = actf(aAct, v0); v1 = actf(aAct, v1); }
                    *(float2*)(Cp + (long)m * g.ldc + c) = make_float2(v0, v1);
                }
            }
    }
}

// ---------------- softmax + top-k + routing (register-resident, 2 syncs) -----
__global__ __launch_bounds__(256) void route_k(const float* scores, const float* sbias,
                                               const float* temp,
                                               float* w, int* prei, int* mlpi, int* posti,
                                               int* cnt, int* rows) {
    const int t = blockIdx.x, tid = threadIdx.x;
    const int wid = tid >> 5, lane = tid & 31;
    __shared__ float ws1[8], ws2[8];
    __shared__ float cval[64];
    __shared__ int   cidx[64];

    const float invT = 1.0f / temp[0];
    const long TN = (long)T * NSCORE;

    // load 16 values per thread into registers (sum fc3 partials + bias)
    float v[16];
    const int baseIdx = wid * 512 + lane;
#pragma unroll
    for (int j = 0; j < 16; j++) {
        int idx = baseIdx + 32 * j;
        long off = (long)t * NSCORE + idx;
        v[j] = (scores[off] + scores[TN + off] + sbias[idx]) * invT;
    }

    // global max
    float mx = v[0];
#pragma unroll
    for (int j = 1; j < 16; j++) mx = fmaxf(mx, v[j]);
    mx = wmax(mx);
    if (lane == 0) ws1[wid] = mx;
    __syncthreads();
    float gmax = ws1[0];
#pragma unroll
    for (int i = 1; i < 8; i++) gmax = fmaxf(gmax, ws1[i]);

    // global exp-sum
    float sum = 0.0f;
#pragma unroll
    for (int j = 0; j < 16; j++) sum += expf(v[j] - gmax);
    sum = wsum(sum);
    if (lane == 0) ws2[wid] = sum;

    // phase 1: per-warp top-8 (register scans + warp shuffles, no block syncs)
#pragma unroll
    for (int k = 0; k < TOPK; k++) {
        float bv = -3.4e38f; int bi = NSCORE;
#pragma unroll
        for (int j = 0; j < 16; j++) {
            if (v[j] > bv) { bv = v[j]; bi = baseIdx + 32 * j; }   // ascending idx: strict > keeps smallest
        }
#pragma unroll
        for (int o = 16; o; o >>= 1) {
            float ov = __shfl_xor_sync(0xffffffffu, bv, o);
            int   oi = __shfl_xor_sync(0xffffffffu, bi, o);
            if (ov > bv || (ov == bv && oi < bi)) { bv = ov; bi = oi; }
        }
        if (lane == 0) { cval[wid * 8 + k] = bv; cidx[wid * 8 + k] = bi; }
        if ((bi & 31) == lane) v[(bi >> 5) & 15] = -3.4e38f;       // owner poisons
    }
    __syncthreads();

    float gsum = ws2[0];
#pragma unroll
    for (int i = 1; i < 8; i++) gsum += ws2[i];

    // phase 2: warp 0 merges 64 candidates -> global top-8
    if (wid == 0) {
        float cv0 = cval[lane], cv1 = cval[lane + 32];
        int   ci0 = cidx[lane], ci1 = cidx[lane + 32];
        float myv = 0.0f; int myi = 0;
#pragma unroll
        for (int k = 0; k < TOPK; k++) {
            float bv; int bi;
            if (cv0 > cv1 || (cv0 == cv1 && ci0 < ci1)) { bv = cv0; bi = ci0; }
            else                                        { bv = cv1; bi = ci1; }
#pragma unroll
            for (int o = 16; o; o >>= 1) {
                float ov = __shfl_xor_sync(0xffffffffu, bv, o);
                int   oi = __shfl_xor_sync(0xffffffffu, bi, o);
                if (ov > bv || (ov == bv && oi < bi)) { bv = ov; bi = oi; }
            }
            if (lane == k) { myv = bv; myi = bi; }
            if (ci0 == bi) cv0 = -3.4e38f;
            if (ci1 == bi) cv1 = -3.4e38f;
        }
        if (lane < TOPK) {
            float prob = expf(myv - gmax) / gsum;
            float ww = (prob >= 1e-6f) ? prob : 0.0f;
            int pair = t * TOPK + lane;
            int pe = myi >> 8, rem = myi & 255, me = rem >> 4, oe = rem & 15;
            prei[pair] = pe; mlpi[pair] = me; posti[pair] = oe; w[pair] = ww;
            int s0 = atomicAdd(&cnt[pe], 1);       rows[pe * NPAIR + s0] = pair;
            int s1 = atomicAdd(&cnt[16 + me], 1);  rows[(16 + me) * NPAIR + s1] = pair;
            int s2 = atomicAdd(&cnt[32 + oe], 1);  rows[(32 + oe) * NPAIR + s2] = pair;
        }
    }
}

// ---------------- pre: sum 2 partials + bias + LN + act ----------------------
__global__ __launch_bounds__(256) void prelnact_k(const float* U, const int* prei,
                                                  const float* pbias,
                                                  const float* g, const float* b, float* X) {
    const int warp = threadIdx.x >> 5, lane = threadIdx.x & 31;
    const int p = blockIdx.x * 8 + warp;
    const int e = prei[p];
    float u[16];
#pragma unroll
    for (int j = 0; j < 16; j++) {
        int idx = lane + 32 * j;
        u[j] = U[p * D + idx] + U[(long)NPAIR * D + p * D + idx] + pbias[e * D + idx];
    }

    float s = 0.0f;
#pragma unroll
    for (int j = 0; j < 16; j++) s += u[j];
    const float mean = wsum(s) * (1.0f / D);

    float v = 0.0f;
#pragma unroll
    for (int j = 0; j < 16; j++) { float d = u[j] - mean; v += d * d; }
    const float rstd = rsqrtf(wsum(v) * (1.0f / D) + 1e-5f);

    const int a = e & 3;
#pragma unroll
    for (int j = 0; j < 16; j++) {
        int idx = lane + 32 * j;
        float val = (u[j] - mean) * rstd * g[e * D + idx] + b[e * D + idx];
        X[p * D + idx] = actf(a, val);
    }
}

// ---------------- mlp2: sum 4 partials + bias --------------------------------
__global__ __launch_bounds__(256) void addy_k(const float* Y4, const int* mlpi,
                                              const float* b2, float* y) {
    const int warp = threadIdx.x >> 5, lane = threadIdx.x & 31;
    const int p = blockIdx.x * 8 + warp;
    const int e = mlpi[p];
#pragma unroll
    for (int j = 0; j < 16; j++) {
        int idx = lane + 32 * j;
        long off = (long)p * D + idx;
        float s = Y4[off] + Y4[(long)NPAIR * D + off]
                + Y4[2L * NPAIR * D + off] + Y4[3L * NPAIR * D + off]
                + b2[e * D + idx];
        y[off] = s;
    }
}

// ---------------- post: sum 2 partials + bias + LN + weighted reduce ---------
__global__ __launch_bounds__(256) void final_k(const float* Z, const int* posti, const float* w,
                                               const float* pbias,
                                               const float* g, const float* b, float* out) {
    const int t = blockIdx.x, tid = threadIdx.x;
    const int warp = tid >> 5, lane = tid & 31;
    __shared__ float sacc[8][D];

    const int pair = t * TOPK + warp;
    const int e = posti[pair];
    const float ww = w[pair];
    float z[16];
#pragma unroll
    for (int j = 0; j < 16; j++) {
        int idx = lane + 32 * j;
        z[j] = Z[(long)pair * D + idx] + Z[(long)NPAIR * D + (long)pair * D + idx]
             + pbias[e * D + idx];
    }

    if ((e & 1) == 0) {
        float s = 0.0f;
#pragma unroll
        for (int j = 0; j < 16; j++) s += z[j];
        const float mean = wsum(s) * (1.0f / D);
        float v = 0.0f;
#pragma unroll
        for (int j = 0; j < 16; j++) { float d = z[j] - mean; v += d * d; }
        const float rstd = rsqrtf(wsum(v) * (1.0f / D) + 1e-5f);
#pragma unroll
        for (int j = 0; j < 16; j++) {
            int idx = lane + 32 * j;
            z[j] = (z[j] - mean) * rstd * g[e * D + idx] + b[e * D + idx];
        }
    }
#pragma unroll
    for (int j = 0; j < 16; j++) sacc[warp][lane + 32 * j] = ww * z[j];
    __syncthreads();

    for (int i = tid; i < D; i += 256) {
        float s = 0.0f;
#pragma unroll
        for (int k = 0; k < 8; k++) s += sacc[k][i];
        out[t * D + i] = s;
    }
}

// ---------------- launch -----------------------------------------------------
extern "C" void kernel_launch(void* const* d_in, const int* in_sizes, int n_in,
                              void* d_out, int out_size) {
    const float* x       = (const float*)d_in[0];
    const float* r_w1    = (const float*)d_in[1];
    const float* r_b1    = (const float*)d_in[2];
    const float* r_w2    = (const float*)d_in[3];
    const float* r_b2    = (const float*)d_in[4];
    const float* r_w3    = (const float*)d_in[5];
    const float* r_b3    = (const float*)d_in[6];
    const float* temp    = (const float*)d_in[7];
    const float* pre_w   = (const float*)d_in[8];
    const float* pre_b   = (const float*)d_in[9];
    const float* pre_g   = (const float*)d_in[10];
    const float* pre_be  = (const float*)d_in[11];
    const float* mlp_w1  = (const float*)d_in[12];
    const float* mlp_b1  = (const float*)d_in[13];
    const float* mlp_w2  = (const float*)d_in[14];
    const float* mlp_b2  = (const float*)d_in[15];
    const float* post_w  = (const float*)d_in[16];
    const float* post_b  = (const float*)d_in[17];
    const float* post_g  = (const float*)d_in[18];
    const float* post_be = (const float*)d_in[19];
    float* out = (float*)d_out;

    float *h1, *h2, *sc, *preu, *xin, *hmid, *y4, *y, *z, *w;
    int *prei, *mlpi, *posti, *cnt, *rows;
    cudaGetSymbolAddress((void**)&h1, g_h1);
    cudaGetSymbolAddress((void**)&h2, g_h2);
    cudaGetSymbolAddress((void**)&sc, g_scores);
    cudaGetSymbolAddress((void**)&preu, g_preu);
    cudaGetSymbolAddress((void**)&xin, g_xin);
    cudaGetSymbolAddress((void**)&hmid, g_hmid);
    cudaGetSymbolAddress((void**)&y4, g_y4);
    cudaGetSymbolAddress((void**)&y, g_y);
    cudaGetSymbolAddress((void**)&z, g_z);
    cudaGetSymbolAddress((void**)&w, g_w);
    cudaGetSymbolAddress((void**)&prei, g_prei);
    cudaGetSymbolAddress((void**)&mlpi, g_mlpi);
    cudaGetSymbolAddress((void**)&posti, g_posti);
    cudaGetSymbolAddress((void**)&cnt, g_cnt);
    cudaGetSymbolAddress((void**)&rows, g_rows);

    // router fc1 (also zeroes routing counters in block 0)
    {
        GArgs a = {x, D, r_w1, 0, 512, r_b1, 0, h1, 512,
                   T, 512, 512, nullptr, nullptr, 0, 0, 0, 1, 0, cnt};
        rgemm_k<<<dim3(8, 2, 1), 256>>>(a);
    }
    {
        GArgs a = {h1, 512, r_w2, 0, 256, r_b2, 0, h2, 256,
                   T, 256, 512, nullptr, nullptr, 0, 0, 0, 1, 0, nullptr};
        rgemm_k<<<dim3(4, 2, 1), 256>>>(a);
    }
    // fc3: split-K=2 (grid z), partials summed (with bias) inside route_k
    {
        GArgs a = {h2, 256, r_w3, 0, NSCORE, r_b3, 0, sc, NSCORE,
                   T, NSCORE, 128, nullptr, nullptr, 0, 0, 0, 0,
                   (long)T * NSCORE, nullptr};
        rgemm_k<<<dim3(64, 2, 2), 256>>>(a);
    }

    route_k<<<T, 256>>>(sc, r_b3, temp, w, prei, mlpi, posti, cnt, rows);

    // pre: split-K=2, S=4
    {
        GArgs a = {x, D, pre_w, (long)D * D, D, pre_b, D, preu, D,
                   NPAIR, D, D, rows, cnt, 3, 0, 0, 0, (long)NPAIR * D, nullptr};
        tgemm_k<2, 4><<<dim3(16, 6, NEXP), 64>>>(a);
    }
    prelnact_k<<<NPAIR / 8, 256>>>(preu, prei, pre_b, pre_g, pre_be, xin);

    // mlp1: fused bias+act, S=3
    {
        GArgs a = {xin, D, mlp_w1, (long)D * MAXH, MAXH, mlp_b1, MAXH, hmid, MAXH,
                   NPAIR, MAXH, D, rows + 16 * NPAIR, cnt + 16, 0, 1, 0, 5, 0, nullptr};
        tgemm_k<1, 3><<<dim3(40, 6, NEXP), 64>>>(a);
    }
    // mlp2: split-K=4, S=3
    {
        GArgs a = {hmid, MAXH, mlp_w2, (long)MAXH * D, D, mlp_b2, D, y4, D,
                   NPAIR, D, MAXH, rows + 16 * NPAIR, cnt + 16, 0, 0, 1, 0,
                   (long)NPAIR * D, nullptr};
        tgemm_k<4, 3><<<dim3(32, 6, NEXP), 64>>>(a);
    }
    addy_k<<<NPAIR / 8, 256>>>(y4, mlpi, mlp_b2, y);

    // post: split-K=2, S=4
    {
        GArgs a = {y, D, post_w, (long)D * D, D, post_b, D, z, D,
                   NPAIR, D, D, rows + 32 * NPAIR, cnt + 32, 0, 0, 0, 0,
                   (long)NPAIR * D, nullptr};
        tgemm_k<2, 4><<<dim3(16, 6, NEXP), 64>>>(a);
    }

    final_k<<<T, 256>>>(z, posti, w, post_b, post_g, post_be, out);
}